// round 7
// baseline (speedup 1.0000x reference)
#include <cuda_runtime.h>
#include <math.h>
#include <stdint.h>

// Problem constants
constexpr int B   = 8;
constexpr int S   = 1024;
constexpr int D   = 1024;
constexpr int H   = 16;
constexpr int DK  = 64;
constexpr int DFF = 4096;
constexpr int NT  = B * S;          // 8192 rows
constexpr float EPS = 1e-5f;

// ---------------------------------------------------------------------------
// Scratch (static __device__ arrays — no runtime allocation)
// ---------------------------------------------------------------------------
__device__ float g_q  [NT * D];
__device__ float g_k  [NT * D];
__device__ float g_v  [NT * D];
__device__ float g_ctx[NT * D];
__device__ float g_h  [NT * D];
__device__ float g_ff [(size_t)NT * DFF];
__device__ float g_part[2 * B * 256];
__device__ float g_stats[2 * B];
// tf32-pre-rounded operand copies
__device__ float g_xr [NT * D];
__device__ float g_hr [NT * D];
__device__ float g_wqr[D * D];
__device__ float g_wkr[D * D];
__device__ float g_wvr[D * D];
__device__ float g_w1r[D * DFF];
__device__ float g_w2r[DFF * D];

// ---------------------------------------------------------------------------
// tf32 / async helpers
// ---------------------------------------------------------------------------
__device__ __forceinline__ uint32_t f2tf32(float x) {
    uint32_t r;
    asm("cvt.rna.tf32.f32 %0, %1;" : "=r"(r) : "f"(x));
    return r;
}

__device__ __forceinline__ void mma_tf32(float c[4], const uint32_t a[4], const uint32_t b[2]) {
    asm volatile(
        "mma.sync.aligned.m16n8k8.row.col.f32.tf32.tf32.f32 "
        "{%0,%1,%2,%3}, {%4,%5,%6,%7}, {%8,%9}, {%0,%1,%2,%3};\n"
        : "+f"(c[0]), "+f"(c[1]), "+f"(c[2]), "+f"(c[3])
        : "r"(a[0]), "r"(a[1]), "r"(a[2]), "r"(a[3]), "r"(b[0]), "r"(b[1]));
}

__device__ __forceinline__ void cp_async16(void* smem_ptr, const void* gptr) {
    uint32_t sa = (uint32_t)__cvta_generic_to_shared(smem_ptr);
    asm volatile("cp.async.cg.shared.global [%0], [%1], 16;\n" :: "r"(sa), "l"(gptr));
}
__device__ __forceinline__ void cp_commit() {
    asm volatile("cp.async.commit_group;\n");
}
template <int N>
__device__ __forceinline__ void cp_wait() {
    asm volatile("cp.async.wait_group %0;\n" :: "n"(N));
}

// ---------------------------------------------------------------------------
// Elementwise tf32 rounding pre-pass (float4)
// ---------------------------------------------------------------------------
__global__ void __launch_bounds__(256)
round_tf32(const float* __restrict__ in, float* __restrict__ out, int n4)
{
    const int i = blockIdx.x * 256 + threadIdx.x;
    if (i < n4) {
        float4 v = ((const float4*)in)[i];
        v.x = __uint_as_float(f2tf32(v.x));
        v.y = __uint_as_float(f2tf32(v.y));
        v.z = __uint_as_float(f2tf32(v.z));
        v.w = __uint_as_float(f2tf32(v.w));
        ((float4*)out)[i] = v;
    }
}

// ---------------------------------------------------------------------------
// Pipelined TF32 GEMM. Pre-rounded operands. 128 threads = 4 warps,
// warp tile 64x64 (4 m-frags x 8 n-frags), CTA tile 128x128, BK=32,
// 3-stage cp.async pipeline, no cvt in mainloop.
// EPI: 0 = bias, 1 = bias+GeLU (+tf32-rounded out), 2 = bias+residual
// ---------------------------------------------------------------------------
constexpr int ASZ = 128 * 36;    // [128][36]: frag banks 4g+t (conflict-free)
constexpr int BSZ = 32 * 136;    // [32][136]: frag banks 8t+g (conflict-free)
constexpr int GEMM_SMEM = 3 * (ASZ + BSZ) * 4;   // 107,520 B

template <int EPI>
__device__ __forceinline__ void gemm_body(
    const float* __restrict__ A, const float* __restrict__ W,
    const float* __restrict__ bias, const float* __restrict__ res,
    float* __restrict__ C, int K, int N, int bx, int by, float* sm)
{
    float* AsB = sm;
    float* BsB = sm + 3 * ASZ;

    const int tid  = threadIdx.x;
    const int lane = tid & 31;
    const int warp = tid >> 5;         // 0..3
    const int g    = lane >> 2;
    const int t    = lane & 3;
    const int wm   = (warp & 1) * 64;
    const int wn   = (warp >> 1) * 64;

    const float* Ab = A + (size_t)(by * 128) * K;
    const float* Wb = W + bx * 128;

    float acc[4][8][4];
#pragma unroll
    for (int mi = 0; mi < 4; mi++)
#pragma unroll
        for (int nj = 0; nj < 8; nj++)
#pragma unroll
            for (int c = 0; c < 4; c++) acc[mi][nj][c] = 0.f;

    auto stage = [&](int buf, int kk) {
        float* Ad = AsB + buf * ASZ;
        float* Bd = BsB + buf * BSZ;
#pragma unroll
        for (int u = 0; u < 8; u++) {
            const int i   = tid + u * 128;
            const int row = i >> 3;
            const int c4  = (i & 7) * 4;
            cp_async16(Ad + row * 36 + c4, Ab + (size_t)row * K + kk + c4);
        }
#pragma unroll
        for (int u = 0; u < 8; u++) {
            const int i   = tid + u * 128;
            const int row = i >> 5;
            const int c4  = (i & 31) * 4;
            cp_async16(Bd + row * 136 + c4, Wb + (size_t)(kk + row) * N + c4);
        }
        cp_commit();
    };

    const int nT = K >> 5;
    stage(0, 0);
    if (nT > 1) stage(1, 32);

    for (int tt = 0; tt < nT; tt++) {
        if (tt + 1 < nT) cp_wait<1>(); else cp_wait<0>();
        __syncthreads();
        if (tt + 2 < nT) stage((tt + 2) % 3, (tt + 2) * 32);

        const uint32_t* Ac = (const uint32_t*)(AsB + (tt % 3) * ASZ);
        const uint32_t* Bc = (const uint32_t*)(BsB + (tt % 3) * BSZ);
#pragma unroll
        for (int ks = 0; ks < 4; ks++) {
            const int kb = ks * 8;
            uint32_t a[4][4], b[8][2];
#pragma unroll
            for (int mi = 0; mi < 4; mi++) {
                const int m0 = wm + mi * 16;
                a[mi][0] = Ac[(m0 + g)     * 36 + kb + t];
                a[mi][1] = Ac[(m0 + 8 + g) * 36 + kb + t];
                a[mi][2] = Ac[(m0 + g)     * 36 + kb + 4 + t];
                a[mi][3] = Ac[(m0 + 8 + g) * 36 + kb + 4 + t];
            }
#pragma unroll
            for (int nj = 0; nj < 8; nj++) {
                const int n0 = wn + nj * 8;
                b[nj][0] = Bc[(kb + t)     * 136 + n0 + g];
                b[nj][1] = Bc[(kb + 4 + t) * 136 + n0 + g];
            }
#pragma unroll
            for (int mi = 0; mi < 4; mi++)
#pragma unroll
                for (int nj = 0; nj < 8; nj++)
                    mma_tf32(acc[mi][nj], a[mi], b[nj]);
        }
    }

    // epilogue
#pragma unroll
    for (int mi = 0; mi < 4; mi++) {
#pragma unroll
        for (int nj = 0; nj < 8; nj++) {
            const int row = by * 128 + wm + mi * 16 + g;
            const int col = bx * 128 + wn + nj * 8 + t * 2;
#pragma unroll
            for (int half = 0; half < 2; half++) {
                const int r = row + half * 8;
                float v0 = acc[mi][nj][half * 2 + 0] + bias[col];
                float v1 = acc[mi][nj][half * 2 + 1] + bias[col + 1];
                if (EPI == 1) {
                    v0 = 0.5f * v0 * (1.0f + erff(v0 * 0.70710678118654752f));
                    v1 = 0.5f * v1 * (1.0f + erff(v1 * 0.70710678118654752f));
                    v0 = __uint_as_float(f2tf32(v0));
                    v1 = __uint_as_float(f2tf32(v1));
                } else if (EPI == 2) {
                    v0 += res[(size_t)r * N + col];
                    v1 += res[(size_t)r * N + col + 1];
                }
                float2 out = make_float2(v0, v1);
                *(float2*)(C + (size_t)r * N + col) = out;
            }
        }
    }
}

// Fused QKV: blockIdx.z selects {q,k,v}
__global__ void __launch_bounds__(128, 2)
gemm_qkv(const float* __restrict__ x,
         const float* __restrict__ wq, const float* __restrict__ bq,
         const float* __restrict__ wk, const float* __restrict__ bk,
         const float* __restrict__ wv, const float* __restrict__ bv,
         float* __restrict__ q, float* __restrict__ k, float* __restrict__ v)
{
    extern __shared__ float sm[];
    const float* W; const float* bias; float* C;
    if (blockIdx.z == 0)      { W = wq; bias = bq; C = q; }
    else if (blockIdx.z == 1) { W = wk; bias = bk; C = k; }
    else                      { W = wv; bias = bv; C = v; }
    gemm_body<0>(x, W, bias, nullptr, C, D, D, blockIdx.x, blockIdx.y, sm);
}

template <int EPI>
__global__ void __launch_bounds__(128, 2)
gemm_pipe(const float* __restrict__ A, const float* __restrict__ W,
          const float* __restrict__ bias, const float* __restrict__ res,
          float* __restrict__ C, int K, int N)
{
    extern __shared__ float sm[];
    gemm_body<EPI>(A, W, bias, res, C, K, N, blockIdx.x, blockIdx.y, sm);
}

// ---------------------------------------------------------------------------
// Flash attention (verified in rounds 4-6, unchanged)
// ---------------------------------------------------------------------------
constexpr int PS_STRIDE = 132;
constexpr int KS_STRIDE = 68;
constexpr int VS_STRIDE = 72;
constexpr int ATTN_SMEM = (128 * PS_STRIDE + 128 * KS_STRIDE + 128 * VS_STRIDE) * 4;

__global__ void __launch_bounds__(256)
flash_attn(const float* __restrict__ Q, const float* __restrict__ Kg,
           const float* __restrict__ Vg, float* __restrict__ O)
{
    extern __shared__ uint32_t smem[];
    uint32_t* Ps = smem;
    uint32_t* Ks = Ps + 128 * PS_STRIDE;
    uint32_t* Vs = Ks + 128 * KS_STRIDE;

    const int tid  = threadIdx.x;
    const int lane = tid & 31;
    const int warp = tid >> 5;
    const int g    = lane >> 2;
    const int t    = lane & 3;
    const int m0   = warp * 16;

    const int q0 = blockIdx.x * 128;
    const int h  = blockIdx.y;
    const int b  = blockIdx.z;

    const float* Qb = Q  + (size_t)b * S * D + h * DK;
    const float* Kb = Kg + (size_t)b * S * D + h * DK;
    const float* Vb = Vg + (size_t)b * S * D + h * DK;

#pragma unroll
    for (int u = 0; u < 8; u++) {
        const int idx = u * 256 + tid;
        const int row = idx >> 4;
        const int c4  = (idx & 15) * 4;
        float4 v = *(const float4*)(Qb + (size_t)(q0 + row) * D + c4);
        Ps[row * PS_STRIDE + c4 + 0] = f2tf32(v.x * 0.125f);
        Ps[row * PS_STRIDE + c4 + 1] = f2tf32(v.y * 0.125f);
        Ps[row * PS_STRIDE + c4 + 2] = f2tf32(v.z * 0.125f);
        Ps[row * PS_STRIDE + c4 + 3] = f2tf32(v.w * 0.125f);
    }
    __syncthreads();

    uint32_t qf[8][4];
#pragma unroll
    for (int kc = 0; kc < 8; kc++) {
        const int kb = kc * 8;
        qf[kc][0] = Ps[(m0 + g)     * PS_STRIDE + kb + t];
        qf[kc][1] = Ps[(m0 + 8 + g) * PS_STRIDE + kb + t];
        qf[kc][2] = Ps[(m0 + g)     * PS_STRIDE + kb + 4 + t];
        qf[kc][3] = Ps[(m0 + 8 + g) * PS_STRIDE + kb + 4 + t];
    }

    float o[8][4];
#pragma unroll
    for (int j = 0; j < 8; j++)
#pragma unroll
        for (int c = 0; c < 4; c++) o[j][c] = 0.f;
    float mrun0 = -1e30f, mrun1 = -1e30f, lrun0 = 0.f, lrun1 = 0.f;

    for (int k0 = 0; k0 < S; k0 += 128) {
        __syncthreads();
#pragma unroll
        for (int u = 0; u < 8; u++) {
            const int idx = u * 256 + tid;
            const int row = idx >> 4;
            const int c4  = (idx & 15) * 4;
            float4 kv = *(const float4*)(Kb + (size_t)(k0 + row) * D + c4);
            Ks[row * KS_STRIDE + c4 + 0] = f2tf32(kv.x);
            Ks[row * KS_STRIDE + c4 + 1] = f2tf32(kv.y);
            Ks[row * KS_STRIDE + c4 + 2] = f2tf32(kv.z);
            Ks[row * KS_STRIDE + c4 + 3] = f2tf32(kv.w);
            float4 vv = *(const float4*)(Vb + (size_t)(k0 + row) * D + c4);
            Vs[row * VS_STRIDE + c4 + 0] = f2tf32(vv.x);
            Vs[row * VS_STRIDE + c4 + 1] = f2tf32(vv.y);
            Vs[row * VS_STRIDE + c4 + 2] = f2tf32(vv.z);
            Vs[row * VS_STRIDE + c4 + 3] = f2tf32(vv.w);
        }
        __syncthreads();

        float sc[16][4];
#pragma unroll
        for (int j = 0; j < 16; j++) {
            sc[j][0] = 0.f; sc[j][1] = 0.f; sc[j][2] = 0.f; sc[j][3] = 0.f;
            const int n0 = j * 8;
#pragma unroll
            for (int kc = 0; kc < 8; kc++) {
                const int kb = kc * 8;
                uint32_t bf[2];
                bf[0] = Ks[(n0 + g) * KS_STRIDE + kb + t];
                bf[1] = Ks[(n0 + g) * KS_STRIDE + kb + 4 + t];
                mma_tf32(sc[j], qf[kc], bf);
            }
        }

        float nm0 = -1e30f, nm1 = -1e30f;
#pragma unroll
        for (int j = 0; j < 16; j++) {
            nm0 = fmaxf(nm0, fmaxf(sc[j][0], sc[j][1]));
            nm1 = fmaxf(nm1, fmaxf(sc[j][2], sc[j][3]));
        }
        nm0 = fmaxf(nm0, __shfl_xor_sync(0xffffffffu, nm0, 1));
        nm0 = fmaxf(nm0, __shfl_xor_sync(0xffffffffu, nm0, 2));
        nm1 = fmaxf(nm1, __shfl_xor_sync(0xffffffffu, nm1, 1));
        nm1 = fmaxf(nm1, __shfl_xor_sync(0xffffffffu, nm1, 2));
        const float newm0 = fmaxf(mrun0, nm0);
        const float newm1 = fmaxf(mrun1, nm1);
        const float f0 = __expf(mrun0 - newm0);
        const float f1 = __expf(mrun1 - newm1);

        float s0 = 0.f, s1 = 0.f;
#pragma unroll
        for (int j = 0; j < 16; j++) {
            const float p00 = __expf(sc[j][0] - newm0);
            const float p01 = __expf(sc[j][1] - newm0);
            const float p10 = __expf(sc[j][2] - newm1);
            const float p11 = __expf(sc[j][3] - newm1);
            s0 += p00 + p01;
            s1 += p10 + p11;
            uint2 w0 = make_uint2(f2tf32(p00), f2tf32(p01));
            uint2 w1 = make_uint2(f2tf32(p10), f2tf32(p11));
            *(uint2*)&Ps[(m0 + g)     * PS_STRIDE + j * 8 + 2 * t] = w0;
            *(uint2*)&Ps[(m0 + 8 + g) * PS_STRIDE + j * 8 + 2 * t] = w1;
        }
        s0 += __shfl_xor_sync(0xffffffffu, s0, 1);
        s0 += __shfl_xor_sync(0xffffffffu, s0, 2);
        s1 += __shfl_xor_sync(0xffffffffu, s1, 1);
        s1 += __shfl_xor_sync(0xffffffffu, s1, 2);
        lrun0 = lrun0 * f0 + s0;
        lrun1 = lrun1 * f1 + s1;
        mrun0 = newm0;
        mrun1 = newm1;
#pragma unroll
        for (int j = 0; j < 8; j++) {
            o[j][0] *= f0; o[j][1] *= f0;
            o[j][2] *= f1; o[j][3] *= f1;
        }
        __syncwarp();

#pragma unroll
        for (int kc = 0; kc < 16; kc++) {
            const int kb = kc * 8;
            uint32_t a[4];
            a[0] = Ps[(m0 + g)     * PS_STRIDE + kb + t];
            a[1] = Ps[(m0 + 8 + g) * PS_STRIDE + kb + t];
            a[2] = Ps[(m0 + g)     * PS_STRIDE + kb + 4 + t];
            a[3] = Ps[(m0 + 8 + g) * PS_STRIDE + kb + 4 + t];
#pragma unroll
            for (int j = 0; j < 8; j++) {
                uint32_t bf[2];
                bf[0] = Vs[(kb + t)     * VS_STRIDE + j * 8 + g];
                bf[1] = Vs[(kb + 4 + t) * VS_STRIDE + j * 8 + g];
                mma_tf32(o[j], a, bf);
            }
        }
    }

    const float inv0 = 1.0f / lrun0;
    const float inv1 = 1.0f / lrun1;
    const int row0 = q0 + m0 + g;
    const int row1 = row0 + 8;
#pragma unroll
    for (int j = 0; j < 8; j++) {
        const int col = h * DK + j * 8 + 2 * t;
        float2 r0 = make_float2(o[j][0] * inv0, o[j][1] * inv0);
        float2 r1 = make_float2(o[j][2] * inv1, o[j][3] * inv1);
        *(float2*)(O + (size_t)(b * S + row0) * D + col) = r0;
        *(float2*)(O + (size_t)(b * S + row1) * D + col) = r1;
    }
}

// ---------------------------------------------------------------------------
// LayerNorm over (S,D) per batch
// ---------------------------------------------------------------------------
__global__ void __launch_bounds__(256)
ln_partial(const float* __restrict__ a, const float* __restrict__ c,
           float* __restrict__ y, float* __restrict__ part)
{
    const int b = blockIdx.y, chunk = blockIdx.x, tid = threadIdx.x;
    const size_t base = (size_t)b * S * D + (size_t)chunk * 4096 + tid * 16;
    float s = 0.f, s2 = 0.f;
#pragma unroll
    for (int i = 0; i < 16; i += 4) {
        float4 va = *(const float4*)(a + base + i);
        if (c) {
            float4 vc = *(const float4*)(c + base + i);
            va.x += vc.x; va.y += vc.y; va.z += vc.z; va.w += vc.w;
        }
        if (y) *(float4*)(y + base + i) = va;
        s  += va.x + va.y + va.z + va.w;
        s2 += va.x * va.x + va.y * va.y + va.z * va.z + va.w * va.w;
    }
    __shared__ float r1[256], r2[256];
    r1[tid] = s; r2[tid] = s2; __syncthreads();
    for (int st = 128; st > 0; st >>= 1) {
        if (tid < st) { r1[tid] += r1[tid + st]; r2[tid] += r2[tid + st]; }
        __syncthreads();
    }
    if (tid == 0) {
        part[b * 256 + chunk]            = r1[0];
        part[B * 256 + b * 256 + chunk]  = r2[0];
    }
}

__global__ void __launch_bounds__(256)
ln_finalize(const float* __restrict__ part, float* __restrict__ stats)
{
    const int b = blockIdx.x, tid = threadIdx.x;
    __shared__ float r1[256], r2[256];
    r1[tid] = part[b * 256 + tid];
    r2[tid] = part[B * 256 + b * 256 + tid];
    __syncthreads();
    for (int st = 128; st > 0; st >>= 1) {
        if (tid < st) { r1[tid] += r1[tid + st]; r2[tid] += r2[tid + st]; }
        __syncthreads();
    }
    if (tid == 0) {
        const float n = (float)S * (float)D;
        float mean = r1[0] / n;
        float var  = r2[0] / n - mean * mean;
        stats[2 * b]     = mean;
        stats[2 * b + 1] = rsqrtf(var + EPS);
    }
}

__global__ void __launch_bounds__(256)
ln_apply(const float* __restrict__ y, const float* __restrict__ g,
         const float* __restrict__ beta, const float* __restrict__ stats,
         float* __restrict__ out, float* __restrict__ out_r)
{
    const int b = blockIdx.y;
    const int idx = (blockIdx.x * 256 + threadIdx.x) * 4;
    const float mean = stats[2 * b];
    const float rstd = stats[2 * b + 1];
    const size_t off = (size_t)b * S * D + idx;
    float4 v  = *(const float4*)(y + off);
    float4 gg = *(const float4*)(g + idx);
    float4 bb = *(const float4*)(beta + idx);
    v.x = (v.x - mean) * rstd * gg.x + bb.x;
    v.y = (v.y - mean) * rstd * gg.y + bb.y;
    v.z = (v.z - mean) * rstd * gg.z + bb.z;
    v.w = (v.w - mean) * rstd * gg.w + bb.w;
    *(float4*)(out + off) = v;
    if (out_r) {
        float4 r;
        r.x = __uint_as_float(f2tf32(v.x));
        r.y = __uint_as_float(f2tf32(v.y));
        r.z = __uint_as_float(f2tf32(v.z));
        r.w = __uint_as_float(f2tf32(v.w));
        *(float4*)(out_r + off) = r;
    }
}

// ---------------------------------------------------------------------------
// kernel_launch
// ---------------------------------------------------------------------------
extern "C" void kernel_launch(void* const* d_in, const int* in_sizes, int n_in,
                              void* d_out, int out_size)
{
    const float* x    = (const float*)d_in[0];
    const float* wq   = (const float*)d_in[1];
    const float* bq   = (const float*)d_in[2];
    const float* wk   = (const float*)d_in[3];
    const float* bk   = (const float*)d_in[4];
    const float* wv   = (const float*)d_in[5];
    const float* bv   = (const float*)d_in[6];
    const float* ln1g = (const float*)d_in[7];
    const float* ln1b = (const float*)d_in[8];
    const float* w1   = (const float*)d_in[9];
    const float* b1   = (const float*)d_in[10];
    const float* w2   = (const float*)d_in[11];
    const float* b2   = (const float*)d_in[12];
    const float* ln2g = (const float*)d_in[13];
    const float* ln2b = (const float*)d_in[14];
    float* out = (float*)d_out;

    float *q, *k, *v, *ctx, *h, *ff, *part, *stats;
    float *xr, *hr, *wqr, *wkr, *wvr, *w1r, *w2r;
    cudaGetSymbolAddress((void**)&q,     g_q);
    cudaGetSymbolAddress((void**)&k,     g_k);
    cudaGetSymbolAddress((void**)&v,     g_v);
    cudaGetSymbolAddress((void**)&ctx,   g_ctx);
    cudaGetSymbolAddress((void**)&h,     g_h);
    cudaGetSymbolAddress((void**)&ff,    g_ff);
    cudaGetSymbolAddress((void**)&part,  g_part);
    cudaGetSymbolAddress((void**)&stats, g_stats);
    cudaGetSymbolAddress((void**)&xr,    g_xr);
    cudaGetSymbolAddress((void**)&hr,    g_hr);
    cudaGetSymbolAddress((void**)&wqr,   g_wqr);
    cudaGetSymbolAddress((void**)&wkr,   g_wkr);
    cudaGetSymbolAddress((void**)&wvr,   g_wvr);
    cudaGetSymbolAddress((void**)&w1r,   g_w1r);
    cudaGetSymbolAddress((void**)&w2r,   g_w2r);

    static bool attr_done = false;
    if (!attr_done) {
        cudaFuncSetAttribute(flash_attn,
                             cudaFuncAttributeMaxDynamicSharedMemorySize, ATTN_SMEM);
        cudaFuncSetAttribute(gemm_qkv,
                             cudaFuncAttributeMaxDynamicSharedMemorySize, GEMM_SMEM);
        cudaFuncSetAttribute(gemm_pipe<1>,
                             cudaFuncAttributeMaxDynamicSharedMemorySize, GEMM_SMEM);
        cudaFuncSetAttribute(gemm_pipe<2>,
                             cudaFuncAttributeMaxDynamicSharedMemorySize, GEMM_SMEM);
        attr_done = true;
    }

    // tf32 pre-rounding of GEMM operands
    round_tf32<<<(NT * D / 4 + 255) / 256, 256>>>(x,  xr,  NT * D / 4);
    round_tf32<<<(D * D / 4 + 255) / 256, 256>>>(wq, wqr, D * D / 4);
    round_tf32<<<(D * D / 4 + 255) / 256, 256>>>(wk, wkr, D * D / 4);
    round_tf32<<<(D * D / 4 + 255) / 256, 256>>>(wv, wvr, D * D / 4);
    round_tf32<<<(D * DFF / 4 + 255) / 256, 256>>>(w1, w1r, D * DFF / 4);
    round_tf32<<<(D * DFF / 4 + 255) / 256, 256>>>(w2, w2r, D * DFF / 4);

    // QKV projections (fused launch, pre-rounded operands)
    gemm_qkv<<<dim3(D / 128, NT / 128, 3), 128, GEMM_SMEM>>>(
        xr, wqr, bq, wkr, bk, wvr, bv, q, k, v);

    // Flash attention
    flash_attn<<<dim3(S / 128, H, B), 256, ATTN_SMEM>>>(q, k, v, ctx);

    // LayerNorm 1: h = LN(x + ctx) (+ rounded copy hr)
    ln_partial<<<dim3(256, B), 256>>>(x, ctx, h, part);
    ln_finalize<<<B, 256>>>(part, stats);
    ln_apply<<<dim3(1024, B), 256>>>(h, ln1g, ln1b, stats, h, hr);

    // FFN: ff = round(gelu(hr @ w1r + b1)); ctx = ff @ w2r + b2 + h
    gemm_pipe<1><<<dim3(DFF / 128, NT / 128), 128, GEMM_SMEM>>>(hr, w1r, b1, nullptr, ff, D, DFF);
    gemm_pipe<2><<<dim3(D / 128, NT / 128), 128, GEMM_SMEM>>>(ff, w2r, b2, h, ctx, DFF, D);

    // LayerNorm 2 -> output
    ln_partial<<<dim3(256, B), 256>>>(ctx, nullptr, nullptr, part);
    ln_finalize<<<B, 256>>>(part, stats);
    ln_apply<<<dim3(1024, B), 256>>>(ctx, ln2g, ln2b, stats, out, nullptr);
}

// round 9
// speedup vs baseline: 1.5726x; 1.5726x over previous
#include <cuda_runtime.h>
#include <math.h>
#include <stdint.h>

// Problem constants
constexpr int B   = 8;
constexpr int S   = 1024;
constexpr int D   = 1024;
constexpr int H   = 16;
constexpr int DK  = 64;
constexpr int DFF = 4096;
constexpr int NT  = B * S;          // 8192 rows
constexpr float EPS = 1e-5f;

// ---------------------------------------------------------------------------
// Scratch (static __device__ arrays — no runtime allocation)
// ---------------------------------------------------------------------------
__device__ float g_q  [NT * D];
__device__ float g_k  [NT * D];
__device__ float g_v  [NT * D];
__device__ float g_ctx[NT * D];
__device__ float g_h  [NT * D];
__device__ float g_ff [(size_t)NT * DFF];
__device__ float g_part[2 * B * 256];
__device__ float g_stats[2 * B];
// tf32-pre-rounded A operands
__device__ float g_xr [NT * D];
__device__ float g_hr [NT * D];
// transposed + tf32-rounded weights: Wt[n][k] = rna(W[k][n])
__device__ float g_wqt[D * D];
__device__ float g_wkt[D * D];
__device__ float g_wvt[D * D];
__device__ float g_w1t[(size_t)DFF * D];
__device__ float g_w2t[(size_t)D * DFF];

// ---------------------------------------------------------------------------
// helpers
// ---------------------------------------------------------------------------
__device__ __forceinline__ uint32_t f2tf32(float x) {
    uint32_t r;
    asm("cvt.rna.tf32.f32 %0, %1;" : "=r"(r) : "f"(x));
    return r;
}
__device__ __forceinline__ void mma_tf32(float c[4], const uint32_t a[4], const uint32_t b[2]) {
    asm volatile(
        "mma.sync.aligned.m16n8k8.row.col.f32.tf32.tf32.f32 "
        "{%0,%1,%2,%3}, {%4,%5,%6,%7}, {%8,%9}, {%0,%1,%2,%3};\n"
        : "+f"(c[0]), "+f"(c[1]), "+f"(c[2]), "+f"(c[3])
        : "r"(a[0]), "r"(a[1]), "r"(a[2]), "r"(a[3]), "r"(b[0]), "r"(b[1]));
}
__device__ __forceinline__ void cp_async16(void* smem_ptr, const void* gptr) {
    uint32_t sa = (uint32_t)__cvta_generic_to_shared(smem_ptr);
    asm volatile("cp.async.cg.shared.global [%0], [%1], 16;\n" :: "r"(sa), "l"(gptr));
}
__device__ __forceinline__ void cp_commit() { asm volatile("cp.async.commit_group;\n"); }
__device__ __forceinline__ void ldsm_x4(uint32_t& r0, uint32_t& r1, uint32_t& r2, uint32_t& r3,
                                        uint32_t addr) {
    asm volatile("ldmatrix.sync.aligned.m8n8.x4.shared.b16 {%0,%1,%2,%3}, [%4];"
                 : "=r"(r0), "=r"(r1), "=r"(r2), "=r"(r3) : "r"(addr));
}
__device__ __forceinline__ uint32_t smem_u32(const void* p) {
    uint32_t a;
    asm("{ .reg .u64 t; cvta.to.shared.u64 t, %1; cvt.u32.u64 %0, t; }" : "=r"(a) : "l"(p));
    return a;
}

// ---------------------------------------------------------------------------
// Pre-pass kernels
// ---------------------------------------------------------------------------
__global__ void __launch_bounds__(256)
round_tf32(const float* __restrict__ in, float* __restrict__ out, int n4)
{
    const int i = blockIdx.x * 256 + threadIdx.x;
    if (i < n4) {
        float4 v = ((const float4*)in)[i];
        v.x = __uint_as_float(f2tf32(v.x));
        v.y = __uint_as_float(f2tf32(v.y));
        v.z = __uint_as_float(f2tf32(v.z));
        v.w = __uint_as_float(f2tf32(v.w));
        ((float4*)out)[i] = v;
    }
}

// out[c][r] = rna(in[r][c]);  in: [R][C]
__global__ void __launch_bounds__(256)
transpose_round(const float* __restrict__ in, float* __restrict__ out, int R, int C)
{
    __shared__ float tile[32][33];
    const int c0 = blockIdx.x * 32, r0 = blockIdx.y * 32;
    const int tx = threadIdx.x, ty = threadIdx.y;   // 32 x 8
#pragma unroll
    for (int i = 0; i < 32; i += 8)
        tile[ty + i][tx] = in[(size_t)(r0 + ty + i) * C + c0 + tx];
    __syncthreads();
#pragma unroll
    for (int i = 0; i < 32; i += 8)
        out[(size_t)(c0 + ty + i) * R + r0 + tx] =
            __uint_as_float(f2tf32(tile[tx][ty + i]));
}

// ---------------------------------------------------------------------------
// Pipelined TF32 GEMM with ldmatrix fragment loads.
// A[m][k] and Wt[n][k] both K-major, pre-rounded. 256 threads = 8 warps,
// warp tile 64x32, CTA tile 128x128, BK=32, 3-stage cp.async pipeline.
// Both smem tiles: [128 rows][36 floats] (stride 144B: LDSM phases cover
// banks 4r..4r+3 for r=0..7 => all 32 banks, conflict-free).
// EPI: 0 = bias, 1 = bias+GeLU+round, 2 = bias+residual
// ---------------------------------------------------------------------------
constexpr int TSZ = 128 * 36;                    // one tile (floats)
constexpr int GEMM_SMEM = 3 * 2 * TSZ * 4;       // 110,592 B

template <int EPI>
__device__ __forceinline__ void gemm_body(
    const float* __restrict__ A, const float* __restrict__ Wt,
    const float* __restrict__ bias, const float* __restrict__ res,
    float* __restrict__ C, int K, int N, int bx, int by, float* sm)
{
    float* AsB = sm;                 // 3 x [128][36]
    float* BsB = sm + 3 * TSZ;       // 3 x [128][36]

    const int tid  = threadIdx.x;
    const int lane = tid & 31;
    const int warp = tid >> 5;
    const int g    = lane >> 2;
    const int t    = lane & 3;
    const int wm   = (warp & 1) * 64;
    const int wn   = (warp >> 1) * 32;

    // ldmatrix per-lane row mapping: quad = lane>>3
    const int quad    = lane >> 3;
    const int row_off = (lane & 7) + (quad & 1) * 8;   // +8 rows for odd quads
    const int kh16    = (quad >> 1) * 16;              // k-half byte offset

    const uint32_t smem_base = smem_u32(sm);
    // byte offsets within a tile for this lane (row stride 144B)
    const uint32_t lane_off = (uint32_t)(row_off * 144 + kh16);

    const float* Ab = A  + (size_t)(by * 128) * K;
    const float* Bb = Wt + (size_t)(bx * 128) * K;

    float acc[4][4][4];
#pragma unroll
    for (int mi = 0; mi < 4; mi++)
#pragma unroll
        for (int nj = 0; nj < 4; nj++)
#pragma unroll
            for (int c = 0; c < 4; c++) acc[mi][nj][c] = 0.f;

    auto stage = [&](int buf, int kk) {
        float* Ad = AsB + buf * TSZ;
        float* Bd = BsB + buf * TSZ;
        // 128 rows x 32 floats = 8 chunks/row; 1024 chunks per tile
#pragma unroll
        for (int u = 0; u < 4; u++) {
            const int i   = tid + u * 256;
            const int row = i >> 3;
            const int c4  = (i & 7) * 4;
            cp_async16(Ad + row * 36 + c4, Ab + (size_t)row * K + kk + c4);
        }
#pragma unroll
        for (int u = 0; u < 4; u++) {
            const int i   = tid + u * 256;
            const int row = i >> 3;
            const int c4  = (i & 7) * 4;
            cp_async16(Bd + row * 36 + c4, Bb + (size_t)row * K + kk + c4);
        }
        cp_commit();
    };

    const int nT = K >> 5;
    stage(0, 0);
    if (nT > 1) stage(1, 32);

    for (int tt = 0; tt < nT; tt++) {
        if (tt + 1 < nT) asm volatile("cp.async.wait_group 1;\n" ::: "memory");
        else             asm volatile("cp.async.wait_group 0;\n" ::: "memory");
        __syncthreads();
        if (tt + 2 < nT) stage((tt + 2) % 3, (tt + 2) * 32);

        const int buf = tt % 3;
        const uint32_t Aaddr = smem_base + (uint32_t)(buf * TSZ * 4) + lane_off;
        const uint32_t Baddr = smem_base + (uint32_t)((3 * TSZ + buf * TSZ) * 4) + lane_off;

#pragma unroll
        for (int ks = 0; ks < 4; ks++) {
            const uint32_t kof = ks * 32;   // 8 floats = 32 bytes
            uint32_t a[4][4], b[4][2];
#pragma unroll
            for (int mi = 0; mi < 4; mi++) {
                ldsm_x4(a[mi][0], a[mi][1], a[mi][2], a[mi][3],
                        Aaddr + (uint32_t)((wm + mi * 16) * 144) + kof);
            }
#pragma unroll
            for (int np = 0; np < 2; np++) {
                uint32_t r0, r1, r2, r3;
                ldsm_x4(r0, r1, r2, r3,
                        Baddr + (uint32_t)((wn + np * 16) * 144) + kof);
                b[np * 2 + 0][0] = r0; b[np * 2 + 0][1] = r2;
                b[np * 2 + 1][0] = r1; b[np * 2 + 1][1] = r3;
            }
#pragma unroll
            for (int mi = 0; mi < 4; mi++)
#pragma unroll
                for (int nj = 0; nj < 4; nj++)
                    mma_tf32(acc[mi][nj], a[mi], b[nj]);
        }
        __syncthreads();
    }

    // epilogue
#pragma unroll
    for (int mi = 0; mi < 4; mi++) {
#pragma unroll
        for (int nj = 0; nj < 4; nj++) {
            const int row = by * 128 + wm + mi * 16 + g;
            const int col = bx * 128 + wn + nj * 8 + t * 2;
#pragma unroll
            for (int half = 0; half < 2; half++) {
                const int r = row + half * 8;
                float v0 = acc[mi][nj][half * 2 + 0] + bias[col];
                float v1 = acc[mi][nj][half * 2 + 1] + bias[col + 1];
                if (EPI == 1) {
                    v0 = 0.5f * v0 * (1.0f + erff(v0 * 0.70710678118654752f));
                    v1 = 0.5f * v1 * (1.0f + erff(v1 * 0.70710678118654752f));
                    v0 = __uint_as_float(f2tf32(v0));
                    v1 = __uint_as_float(f2tf32(v1));
                } else if (EPI == 2) {
                    v0 += res[(size_t)r * N + col];
                    v1 += res[(size_t)r * N + col + 1];
                }
                float2 out = make_float2(v0, v1);
                *(float2*)(C + (size_t)r * N + col) = out;
            }
        }
    }
}

// Fused QKV: blockIdx.z selects {q,k,v}
__global__ void __launch_bounds__(256, 2)
gemm_qkv(const float* __restrict__ x,
         const float* __restrict__ wqt, const float* __restrict__ bq,
         const float* __restrict__ wkt, const float* __restrict__ bk,
         const float* __restrict__ wvt, const float* __restrict__ bv,
         float* __restrict__ q, float* __restrict__ k, float* __restrict__ v)
{
    extern __shared__ float sm[];
    const float* Wt; const float* bias; float* C;
    if (blockIdx.z == 0)      { Wt = wqt; bias = bq; C = q; }
    else if (blockIdx.z == 1) { Wt = wkt; bias = bk; C = k; }
    else                      { Wt = wvt; bias = bv; C = v; }
    gemm_body<0>(x, Wt, bias, nullptr, C, D, D, blockIdx.x, blockIdx.y, sm);
}

template <int EPI>
__global__ void __launch_bounds__(256, 2)
gemm_pipe(const float* __restrict__ A, const float* __restrict__ Wt,
          const float* __restrict__ bias, const float* __restrict__ res,
          float* __restrict__ C, int K, int N)
{
    extern __shared__ float sm[];
    gemm_body<EPI>(A, Wt, bias, res, C, K, N, blockIdx.x, blockIdx.y, sm);
}

// ---------------------------------------------------------------------------
// Flash attention (verified rounds 4-6, unchanged)
// ---------------------------------------------------------------------------
constexpr int PS_STRIDE = 132;
constexpr int KS_STRIDE = 68;
constexpr int VS_STRIDE = 72;
constexpr int ATTN_SMEM = (128 * PS_STRIDE + 128 * KS_STRIDE + 128 * VS_STRIDE) * 4;

__global__ void __launch_bounds__(256)
flash_attn(const float* __restrict__ Q, const float* __restrict__ Kg,
           const float* __restrict__ Vg, float* __restrict__ O)
{
    extern __shared__ uint32_t smem[];
    uint32_t* Ps = smem;
    uint32_t* Ks = Ps + 128 * PS_STRIDE;
    uint32_t* Vs = Ks + 128 * KS_STRIDE;

    const int tid  = threadIdx.x;
    const int lane = tid & 31;
    const int warp = tid >> 5;
    const int g    = lane >> 2;
    const int t    = lane & 3;
    const int m0   = warp * 16;

    const int q0 = blockIdx.x * 128;
    const int h  = blockIdx.y;
    const int b  = blockIdx.z;

    const float* Qb = Q  + (size_t)b * S * D + h * DK;
    const float* Kb = Kg + (size_t)b * S * D + h * DK;
    const float* Vb = Vg + (size_t)b * S * D + h * DK;

#pragma unroll
    for (int u = 0; u < 8; u++) {
        const int idx = u * 256 + tid;
        const int row = idx >> 4;
        const int c4  = (idx & 15) * 4;
        float4 v = *(const float4*)(Qb + (size_t)(q0 + row) * D + c4);
        Ps[row * PS_STRIDE + c4 + 0] = f2tf32(v.x * 0.125f);
        Ps[row * PS_STRIDE + c4 + 1] = f2tf32(v.y * 0.125f);
        Ps[row * PS_STRIDE + c4 + 2] = f2tf32(v.z * 0.125f);
        Ps[row * PS_STRIDE + c4 + 3] = f2tf32(v.w * 0.125f);
    }
    __syncthreads();

    uint32_t qf[8][4];
#pragma unroll
    for (int kc = 0; kc < 8; kc++) {
        const int kb = kc * 8;
        qf[kc][0] = Ps[(m0 + g)     * PS_STRIDE + kb + t];
        qf[kc][1] = Ps[(m0 + 8 + g) * PS_STRIDE + kb + t];
        qf[kc][2] = Ps[(m0 + g)     * PS_STRIDE + kb + 4 + t];
        qf[kc][3] = Ps[(m0 + 8 + g) * PS_STRIDE + kb + 4 + t];
    }

    float o[8][4];
#pragma unroll
    for (int j = 0; j < 8; j++)
#pragma unroll
        for (int c = 0; c < 4; c++) o[j][c] = 0.f;
    float mrun0 = -1e30f, mrun1 = -1e30f, lrun0 = 0.f, lrun1 = 0.f;

    for (int k0 = 0; k0 < S; k0 += 128) {
        __syncthreads();
#pragma unroll
        for (int u = 0; u < 8; u++) {
            const int idx = u * 256 + tid;
            const int row = idx >> 4;
            const int c4  = (idx & 15) * 4;
            float4 kv = *(const float4*)(Kb + (size_t)(k0 + row) * D + c4);
            Ks[row * KS_STRIDE + c4 + 0] = f2tf32(kv.x);
            Ks[row * KS_STRIDE + c4 + 1] = f2tf32(kv.y);
            Ks[row * KS_STRIDE + c4 + 2] = f2tf32(kv.z);
            Ks[row * KS_STRIDE + c4 + 3] = f2tf32(kv.w);
            float4 vv = *(const float4*)(Vb + (size_t)(k0 + row) * D + c4);
            Vs[row * VS_STRIDE + c4 + 0] = f2tf32(vv.x);
            Vs[row * VS_STRIDE + c4 + 1] = f2tf32(vv.y);
            Vs[row * VS_STRIDE + c4 + 2] = f2tf32(vv.z);
            Vs[row * VS_STRIDE + c4 + 3] = f2tf32(vv.w);
        }
        __syncthreads();

        float sc[16][4];
#pragma unroll
        for (int j = 0; j < 16; j++) {
            sc[j][0] = 0.f; sc[j][1] = 0.f; sc[j][2] = 0.f; sc[j][3] = 0.f;
            const int n0 = j * 8;
#pragma unroll
            for (int kc = 0; kc < 8; kc++) {
                const int kb = kc * 8;
                uint32_t bf[2];
                bf[0] = Ks[(n0 + g) * KS_STRIDE + kb + t];
                bf[1] = Ks[(n0 + g) * KS_STRIDE + kb + 4 + t];
                mma_tf32(sc[j], qf[kc], bf);
            }
        }

        float nm0 = -1e30f, nm1 = -1e30f;
#pragma unroll
        for (int j = 0; j < 16; j++) {
            nm0 = fmaxf(nm0, fmaxf(sc[j][0], sc[j][1]));
            nm1 = fmaxf(nm1, fmaxf(sc[j][2], sc[j][3]));
        }
        nm0 = fmaxf(nm0, __shfl_xor_sync(0xffffffffu, nm0, 1));
        nm0 = fmaxf(nm0, __shfl_xor_sync(0xffffffffu, nm0, 2));
        nm1 = fmaxf(nm1, __shfl_xor_sync(0xffffffffu, nm1, 1));
        nm1 = fmaxf(nm1, __shfl_xor_sync(0xffffffffu, nm1, 2));
        const float newm0 = fmaxf(mrun0, nm0);
        const float newm1 = fmaxf(mrun1, nm1);
        const float f0 = __expf(mrun0 - newm0);
        const float f1 = __expf(mrun1 - newm1);

        float s0 = 0.f, s1 = 0.f;
#pragma unroll
        for (int j = 0; j < 16; j++) {
            const float p00 = __expf(sc[j][0] - newm0);
            const float p01 = __expf(sc[j][1] - newm0);
            const float p10 = __expf(sc[j][2] - newm1);
            const float p11 = __expf(sc[j][3] - newm1);
            s0 += p00 + p01;
            s1 += p10 + p11;
            uint2 w0 = make_uint2(f2tf32(p00), f2tf32(p01));
            uint2 w1 = make_uint2(f2tf32(p10), f2tf32(p11));
            *(uint2*)&Ps[(m0 + g)     * PS_STRIDE + j * 8 + 2 * t] = w0;
            *(uint2*)&Ps[(m0 + 8 + g) * PS_STRIDE + j * 8 + 2 * t] = w1;
        }
        s0 += __shfl_xor_sync(0xffffffffu, s0, 1);
        s0 += __shfl_xor_sync(0xffffffffu, s0, 2);
        s1 += __shfl_xor_sync(0xffffffffu, s1, 1);
        s1 += __shfl_xor_sync(0xffffffffu, s1, 2);
        lrun0 = lrun0 * f0 + s0;
        lrun1 = lrun1 * f1 + s1;
        mrun0 = newm0;
        mrun1 = newm1;
#pragma unroll
        for (int j = 0; j < 8; j++) {
            o[j][0] *= f0; o[j][1] *= f0;
            o[j][2] *= f1; o[j][3] *= f1;
        }
        __syncwarp();

#pragma unroll
        for (int kc = 0; kc < 16; kc++) {
            const int kb = kc * 8;
            uint32_t a[4];
            a[0] = Ps[(m0 + g)     * PS_STRIDE + kb + t];
            a[1] = Ps[(m0 + 8 + g) * PS_STRIDE + kb + t];
            a[2] = Ps[(m0 + g)     * PS_STRIDE + kb + 4 + t];
            a[3] = Ps[(m0 + 8 + g) * PS_STRIDE + kb + 4 + t];
#pragma unroll
            for (int j = 0; j < 8; j++) {
                uint32_t bf[2];
                bf[0] = Vs[(kb + t)     * VS_STRIDE + j * 8 + g];
                bf[1] = Vs[(kb + 4 + t) * VS_STRIDE + j * 8 + g];
                mma_tf32(o[j], a, bf);
            }
        }
    }

    const float inv0 = 1.0f / lrun0;
    const float inv1 = 1.0f / lrun1;
    const int row0 = q0 + m0 + g;
    const int row1 = row0 + 8;
#pragma unroll
    for (int j = 0; j < 8; j++) {
        const int col = h * DK + j * 8 + 2 * t;
        float2 r0 = make_float2(o[j][0] * inv0, o[j][1] * inv0);
        float2 r1 = make_float2(o[j][2] * inv1, o[j][3] * inv1);
        *(float2*)(O + (size_t)(b * S + row0) * D + col) = r0;
        *(float2*)(O + (size_t)(b * S + row1) * D + col) = r1;
    }
}

// ---------------------------------------------------------------------------
// LayerNorm over (S,D) per batch
// ---------------------------------------------------------------------------
__global__ void __launch_bounds__(256)
ln_partial(const float* __restrict__ a, const float* __restrict__ c,
           float* __restrict__ y, float* __restrict__ part)
{
    const int b = blockIdx.y, chunk = blockIdx.x, tid = threadIdx.x;
    const size_t base = (size_t)b * S * D + (size_t)chunk * 4096 + tid * 16;
    float s = 0.f, s2 = 0.f;
#pragma unroll
    for (int i = 0; i < 16; i += 4) {
        float4 va = *(const float4*)(a + base + i);
        if (c) {
            float4 vc = *(const float4*)(c + base + i);
            va.x += vc.x; va.y += vc.y; va.z += vc.z; va.w += vc.w;
        }
        if (y) *(float4*)(y + base + i) = va;
        s  += va.x + va.y + va.z + va.w;
        s2 += va.x * va.x + va.y * va.y + va.z * va.z + va.w * va.w;
    }
    __shared__ float r1[256], r2[256];
    r1[tid] = s; r2[tid] = s2; __syncthreads();
    for (int st = 128; st > 0; st >>= 1) {
        if (tid < st) { r1[tid] += r1[tid + st]; r2[tid] += r2[tid + st]; }
        __syncthreads();
    }
    if (tid == 0) {
        part[b * 256 + chunk]            = r1[0];
        part[B * 256 + b * 256 + chunk]  = r2[0];
    }
}

__global__ void __launch_bounds__(256)
ln_finalize(const float* __restrict__ part, float* __restrict__ stats)
{
    const int b = blockIdx.x, tid = threadIdx.x;
    __shared__ float r1[256], r2[256];
    r1[tid] = part[b * 256 + tid];
    r2[tid] = part[B * 256 + b * 256 + tid];
    __syncthreads();
    for (int st = 128; st > 0; st >>= 1) {
        if (tid < st) { r1[tid] += r1[tid + st]; r2[tid] += r2[tid + st]; }
        __syncthreads();
    }
    if (tid == 0) {
        const float n = (float)S * (float)D;
        float mean = r1[0] / n;
        float var  = r2[0] / n - mean * mean;
        stats[2 * b]     = mean;
        stats[2 * b + 1] = rsqrtf(var + EPS);
    }
}

__global__ void __launch_bounds__(256)
ln_apply(const float* __restrict__ y, const float* __restrict__ g,
         const float* __restrict__ beta, const float* __restrict__ stats,
         float* __restrict__ out, float* __restrict__ out_r)
{
    const int b = blockIdx.y;
    const int idx = (blockIdx.x * 256 + threadIdx.x) * 4;
    const float mean = stats[2 * b];
    const float rstd = stats[2 * b + 1];
    const size_t off = (size_t)b * S * D + idx;
    float4 v  = *(const float4*)(y + off);
    float4 gg = *(const float4*)(g + idx);
    float4 bb = *(const float4*)(beta + idx);
    v.x = (v.x - mean) * rstd * gg.x + bb.x;
    v.y = (v.y - mean) * rstd * gg.y + bb.y;
    v.z = (v.z - mean) * rstd * gg.z + bb.z;
    v.w = (v.w - mean) * rstd * gg.w + bb.w;
    *(float4*)(out + off) = v;
    if (out_r) {
        float4 r;
        r.x = __uint_as_float(f2tf32(v.x));
        r.y = __uint_as_float(f2tf32(v.y));
        r.z = __uint_as_float(f2tf32(v.z));
        r.w = __uint_as_float(f2tf32(v.w));
        *(float4*)(out_r + off) = r;
    }
}

// ---------------------------------------------------------------------------
// kernel_launch
// ---------------------------------------------------------------------------
extern "C" void kernel_launch(void* const* d_in, const int* in_sizes, int n_in,
                              void* d_out, int out_size)
{
    const float* x    = (const float*)d_in[0];
    const float* wq   = (const float*)d_in[1];
    const float* bq   = (const float*)d_in[2];
    const float* wk   = (const float*)d_in[3];
    const float* bk   = (const float*)d_in[4];
    const float* wv   = (const float*)d_in[5];
    const float* bv   = (const float*)d_in[6];
    const float* ln1g = (const float*)d_in[7];
    const float* ln1b = (const float*)d_in[8];
    const float* w1   = (const float*)d_in[9];
    const float* b1   = (const float*)d_in[10];
    const float* w2   = (const float*)d_in[11];
    const float* b2   = (const float*)d_in[12];
    const float* ln2g = (const float*)d_in[13];
    const float* ln2b = (const float*)d_in[14];
    float* out = (float*)d_out;

    float *q, *k, *v, *ctx, *h, *ff, *part, *stats;
    float *xr, *hr, *wqt, *wkt, *wvt, *w1t, *w2t;
    cudaGetSymbolAddress((void**)&q,     g_q);
    cudaGetSymbolAddress((void**)&k,     g_k);
    cudaGetSymbolAddress((void**)&v,     g_v);
    cudaGetSymbolAddress((void**)&ctx,   g_ctx);
    cudaGetSymbolAddress((void**)&h,     g_h);
    cudaGetSymbolAddress((void**)&ff,    g_ff);
    cudaGetSymbolAddress((void**)&part,  g_part);
    cudaGetSymbolAddress((void**)&stats, g_stats);
    cudaGetSymbolAddress((void**)&xr,    g_xr);
    cudaGetSymbolAddress((void**)&hr,    g_hr);
    cudaGetSymbolAddress((void**)&wqt,   g_wqt);
    cudaGetSymbolAddress((void**)&wkt,   g_wkt);
    cudaGetSymbolAddress((void**)&wvt,   g_wvt);
    cudaGetSymbolAddress((void**)&w1t,   g_w1t);
    cudaGetSymbolAddress((void**)&w2t,   g_w2t);

    static bool attr_done = false;
    if (!attr_done) {
        cudaFuncSetAttribute(flash_attn,
                             cudaFuncAttributeMaxDynamicSharedMemorySize, ATTN_SMEM);
        cudaFuncSetAttribute(gemm_qkv,
                             cudaFuncAttributeMaxDynamicSharedMemorySize, GEMM_SMEM);
        cudaFuncSetAttribute(gemm_pipe<1>,
                             cudaFuncAttributeMaxDynamicSharedMemorySize, GEMM_SMEM);
        cudaFuncSetAttribute(gemm_pipe<2>,
                             cudaFuncAttributeMaxDynamicSharedMemorySize, GEMM_SMEM);
        attr_done = true;
    }

    // Pre-pass: round x; transpose+round weights (Wt[n][k] = rna(W[k][n]))
    round_tf32<<<(NT * D / 4 + 255) / 256, 256>>>(x, xr, NT * D / 4);
    transpose_round<<<dim3(D / 32, D / 32),   dim3(32, 8)>>>(wq, wqt, D, D);
    transpose_round<<<dim3(D / 32, D / 32),   dim3(32, 8)>>>(wk, wkt, D, D);
    transpose_round<<<dim3(D / 32, D / 32),   dim3(32, 8)>>>(wv, wvt, D, D);
    transpose_round<<<dim3(DFF / 32, D / 32), dim3(32, 8)>>>(w1, w1t, D, DFF);
    transpose_round<<<dim3(D / 32, DFF / 32), dim3(32, 8)>>>(w2, w2t, DFF, D);

    // QKV projections (fused launch, ldmatrix GEMM)
    gemm_qkv<<<dim3(D / 128, NT / 128, 3), 256, GEMM_SMEM>>>(
        xr, wqt, bq, wkt, bk, wvt, bv, q, k, v);

    // Flash attention
    flash_attn<<<dim3(S / 128, H, B), 256, ATTN_SMEM>>>(q, k, v, ctx);

    // LayerNorm 1: h = LN(x + ctx) (+ rounded copy hr)
    ln_partial<<<dim3(256, B), 256>>>(x, ctx, h, part);
    ln_finalize<<<B, 256>>>(part, stats);
    ln_apply<<<dim3(1024, B), 256>>>(h, ln1g, ln1b, stats, h, hr);

    // FFN: ff = round(gelu(hr @ w1 + b1));  ctx = ff @ w2 + b2 + h
    gemm_pipe<1><<<dim3(DFF / 128, NT / 128), 256, GEMM_SMEM>>>(hr, w1t, b1, nullptr, ff, D, DFF);
    gemm_pipe<2><<<dim3(D / 128, NT / 128),   256, GEMM_SMEM>>>(ff, w2t, b2, h, ctx, DFF, D);

    // LayerNorm 2 -> output
    ln_partial<<<dim3(256, B), 256>>>(ctx, nullptr, nullptr, part);
    ln_finalize<<<B, 256>>>(part, stats);
    ln_apply<<<dim3(1024, B), 256>>>(ctx, ln2g, ln2b, stats, out, nullptr);
}

// round 10
// speedup vs baseline: 1.6849x; 1.0715x over previous
#include <cuda_runtime.h>
#include <math.h>
#include <stdint.h>

// Problem constants
constexpr int B   = 8;
constexpr int S   = 1024;
constexpr int D   = 1024;
constexpr int H   = 16;
constexpr int DK  = 64;
constexpr int DFF = 4096;
constexpr int NT  = B * S;          // 8192 rows
constexpr float EPS = 1e-5f;

// ---------------------------------------------------------------------------
// Scratch (static __device__ arrays — no runtime allocation)
// ---------------------------------------------------------------------------
__device__ float g_q  [NT * D];
__device__ float g_k  [NT * D];
__device__ float g_v  [NT * D];
__device__ float g_ctx[NT * D];
__device__ float g_h  [NT * D];
__device__ float g_ff [(size_t)NT * DFF];
__device__ float g_part[2 * B * 256];
__device__ float g_stats[2 * B];
// tf32-pre-rounded operand copies
__device__ float g_xr [NT * D];
__device__ float g_hr [NT * D];
__device__ float g_wqr[D * D];
__device__ float g_wkr[D * D];
__device__ float g_wvr[D * D];
__device__ float g_w1r[D * DFF];
__device__ float g_w2r[DFF * D];

// ---------------------------------------------------------------------------
// tf32 / async helpers
// ---------------------------------------------------------------------------
__device__ __forceinline__ uint32_t f2tf32(float x) {
    uint32_t r;
    asm("cvt.rna.tf32.f32 %0, %1;" : "=r"(r) : "f"(x));
    return r;
}

__device__ __forceinline__ void mma_tf32(float c[4], const uint32_t a[4], const uint32_t b[2]) {
    asm volatile(
        "mma.sync.aligned.m16n8k8.row.col.f32.tf32.tf32.f32 "
        "{%0,%1,%2,%3}, {%4,%5,%6,%7}, {%8,%9}, {%0,%1,%2,%3};\n"
        : "+f"(c[0]), "+f"(c[1]), "+f"(c[2]), "+f"(c[3])
        : "r"(a[0]), "r"(a[1]), "r"(a[2]), "r"(a[3]), "r"(b[0]), "r"(b[1]));
}

__device__ __forceinline__ void cp_async16(void* smem_ptr, const void* gptr) {
    uint32_t sa = (uint32_t)__cvta_generic_to_shared(smem_ptr);
    asm volatile("cp.async.cg.shared.global [%0], [%1], 16;\n" :: "r"(sa), "l"(gptr));
}
__device__ __forceinline__ void cp_commit() {
    asm volatile("cp.async.commit_group;\n");
}

// ---------------------------------------------------------------------------
// Pre-pass kernels: tf32 rounding (single and dual-tensor variants)
// ---------------------------------------------------------------------------
__global__ void __launch_bounds__(256)
round_tf32(const float* __restrict__ in, float* __restrict__ out, int n4)
{
    const int i = blockIdx.x * 256 + threadIdx.x;
    if (i < n4) {
        float4 v = ((const float4*)in)[i];
        v.x = __uint_as_float(f2tf32(v.x));
        v.y = __uint_as_float(f2tf32(v.y));
        v.z = __uint_as_float(f2tf32(v.z));
        v.w = __uint_as_float(f2tf32(v.w));
        ((float4*)out)[i] = v;
    }
}

// rounds two equal-size tensors in one launch (grid.z selects)
__global__ void __launch_bounds__(256)
round2_tf32(const float* __restrict__ inA, float* __restrict__ outA,
            const float* __restrict__ inB, float* __restrict__ outB, int n4)
{
    const int i = blockIdx.x * 256 + threadIdx.x;
    const float* in  = blockIdx.z == 0 ? inA  : inB;
    float*       out = blockIdx.z == 0 ? outA : outB;
    if (i < n4) {
        float4 v = ((const float4*)in)[i];
        v.x = __uint_as_float(f2tf32(v.x));
        v.y = __uint_as_float(f2tf32(v.y));
        v.z = __uint_as_float(f2tf32(v.z));
        v.w = __uint_as_float(f2tf32(v.w));
        ((float4*)out)[i] = v;
    }
}

// ---------------------------------------------------------------------------
// Pipelined TF32 GEMM (round-6 layout). Pre-rounded operands, no cvt in loop.
// 256 threads = 8 warps, warp tile 64x32, CTA tile 128x128, BK=32,
// 3-stage cp.async pipeline with REGISTER-ROTATED buffer pointers.
// EPI: 0 = bias, 1 = bias+GeLU+round, 2 = bias+residual
// ---------------------------------------------------------------------------
constexpr int ASZ = 128 * 36;    // A stage: [128][36] (frag banks 4g+t, conflict-free)
constexpr int BSZ = 32 * 136;    // B stage: [32][136] (frag banks 8t+g, conflict-free)
constexpr int GEMM_SMEM = 3 * (ASZ + BSZ) * 4;   // 107,520 B

template <int EPI>
__device__ __forceinline__ void gemm_body(
    const float* __restrict__ A, const float* __restrict__ W,
    const float* __restrict__ bias, const float* __restrict__ res,
    float* __restrict__ C, int K, int N, int bx, int by, float* sm)
{
    float* AsB = sm;
    float* BsB = sm + 3 * ASZ;

    const int tid  = threadIdx.x;
    const int lane = tid & 31;
    const int warp = tid >> 5;
    const int g    = lane >> 2;
    const int t    = lane & 3;
    const int wm   = (warp & 1) * 64;
    const int wn   = (warp >> 1) * 32;

    const float* Ab = A + (size_t)(by * 128) * K;
    const float* Wb = W + bx * 128;

    float acc[4][4][4];
#pragma unroll
    for (int mi = 0; mi < 4; mi++)
#pragma unroll
        for (int nj = 0; nj < 4; nj++)
#pragma unroll
            for (int c = 0; c < 4; c++) acc[mi][nj][c] = 0.f;

    // rotated buffer pointers: slot0 = compute, slot2 = stage target
    const uint32_t* Ac0 = (const uint32_t*)(AsB);
    const uint32_t* Ac1 = (const uint32_t*)(AsB + ASZ);
    const uint32_t* Ac2 = (const uint32_t*)(AsB + 2 * ASZ);
    const uint32_t* Bc0 = (const uint32_t*)(BsB);
    const uint32_t* Bc1 = (const uint32_t*)(BsB + BSZ);
    const uint32_t* Bc2 = (const uint32_t*)(BsB + 2 * BSZ);

    auto stage_to = [&](float* Ad, float* Bd, int kk) {
#pragma unroll
        for (int u = 0; u < 4; u++) {
            const int i   = tid + u * 256;
            const int row = i >> 3;
            const int c4  = (i & 7) * 4;
            cp_async16(Ad + row * 36 + c4, Ab + (size_t)row * K + kk + c4);
        }
#pragma unroll
        for (int u = 0; u < 4; u++) {
            const int i   = tid + u * 256;
            const int row = i >> 5;
            const int c4  = (i & 31) * 4;
            cp_async16(Bd + row * 136 + c4, Wb + (size_t)(kk + row) * N + c4);
        }
        cp_commit();
    };

    const int nT = K >> 5;
    stage_to((float*)Ac0, (float*)Bc0, 0);
    if (nT > 1) stage_to((float*)Ac1, (float*)Bc1, 32);

    for (int tt = 0; tt < nT; tt++) {
        if (tt + 1 < nT) asm volatile("cp.async.wait_group 1;\n" ::: "memory");
        else             asm volatile("cp.async.wait_group 0;\n" ::: "memory");
        __syncthreads();
        if (tt + 2 < nT) stage_to((float*)Ac2, (float*)Bc2, (tt + 2) * 32);

#pragma unroll
        for (int ks = 0; ks < 4; ks++) {
            const int kb = ks * 8;
            uint32_t a[4][4], b[4][2];
#pragma unroll
            for (int mi = 0; mi < 4; mi++) {
                const int m0 = wm + mi * 16;
                a[mi][0] = Ac0[(m0 + g)     * 36 + kb + t];
                a[mi][1] = Ac0[(m0 + 8 + g) * 36 + kb + t];
                a[mi][2] = Ac0[(m0 + g)     * 36 + kb + 4 + t];
                a[mi][3] = Ac0[(m0 + 8 + g) * 36 + kb + 4 + t];
            }
#pragma unroll
            for (int nj = 0; nj < 4; nj++) {
                const int n0 = wn + nj * 8;
                b[nj][0] = Bc0[(kb + t)     * 136 + n0 + g];
                b[nj][1] = Bc0[(kb + 4 + t) * 136 + n0 + g];
            }
#pragma unroll
            for (int mi = 0; mi < 4; mi++)
#pragma unroll
                for (int nj = 0; nj < 4; nj++)
                    mma_tf32(acc[mi][nj], a[mi], b[nj]);
        }

        // rotate buffers left: 0<-1, 1<-2, 2<-old0
        const uint32_t* ta = Ac0; Ac0 = Ac1; Ac1 = Ac2; Ac2 = ta;
        const uint32_t* tb = Bc0; Bc0 = Bc1; Bc1 = Bc2; Bc2 = tb;
    }

    // epilogue
#pragma unroll
    for (int mi = 0; mi < 4; mi++) {
#pragma unroll
        for (int nj = 0; nj < 4; nj++) {
            const int row = by * 128 + wm + mi * 16 + g;
            const int col = bx * 128 + wn + nj * 8 + t * 2;
#pragma unroll
            for (int half = 0; half < 2; half++) {
                const int r = row + half * 8;
                float v0 = acc[mi][nj][half * 2 + 0] + bias[col];
                float v1 = acc[mi][nj][half * 2 + 1] + bias[col + 1];
                if (EPI == 1) {
                    v0 = 0.5f * v0 * (1.0f + erff(v0 * 0.70710678118654752f));
                    v1 = 0.5f * v1 * (1.0f + erff(v1 * 0.70710678118654752f));
                    v0 = __uint_as_float(f2tf32(v0));
                    v1 = __uint_as_float(f2tf32(v1));
                } else if (EPI == 2) {
                    v0 += res[(size_t)r * N + col];
                    v1 += res[(size_t)r * N + col + 1];
                }
                float2 out = make_float2(v0, v1);
                *(float2*)(C + (size_t)r * N + col) = out;
            }
        }
    }
}

// Fused QKV: blockIdx.z selects {q,k,v}
__global__ void __launch_bounds__(256, 2)
gemm_qkv(const float* __restrict__ x,
         const float* __restrict__ wq, const float* __restrict__ bq,
         const float* __restrict__ wk, const float* __restrict__ bk,
         const float* __restrict__ wv, const float* __restrict__ bv,
         float* __restrict__ q, float* __restrict__ k, float* __restrict__ v)
{
    extern __shared__ float sm[];
    const float* W; const float* bias; float* C;
    if (blockIdx.z == 0)      { W = wq; bias = bq; C = q; }
    else if (blockIdx.z == 1) { W = wk; bias = bk; C = k; }
    else                      { W = wv; bias = bv; C = v; }
    gemm_body<0>(x, W, bias, nullptr, C, D, D, blockIdx.x, blockIdx.y, sm);
}

template <int EPI>
__global__ void __launch_bounds__(256, 2)
gemm_pipe(const float* __restrict__ A, const float* __restrict__ W,
          const float* __restrict__ bias, const float* __restrict__ res,
          float* __restrict__ C, int K, int N)
{
    extern __shared__ float sm[];
    gemm_body<EPI>(A, W, bias, res, C, K, N, blockIdx.x, blockIdx.y, sm);
}

// ---------------------------------------------------------------------------
// Flash attention (verified rounds 4-9, unchanged)
// ---------------------------------------------------------------------------
constexpr int PS_STRIDE = 132;
constexpr int KS_STRIDE = 68;
constexpr int VS_STRIDE = 72;
constexpr int ATTN_SMEM = (128 * PS_STRIDE + 128 * KS_STRIDE + 128 * VS_STRIDE) * 4;

__global__ void __launch_bounds__(256)
flash_attn(const float* __restrict__ Q, const float* __restrict__ Kg,
           const float* __restrict__ Vg, float* __restrict__ O)
{
    extern __shared__ uint32_t smem[];
    uint32_t* Ps = smem;
    uint32_t* Ks = Ps + 128 * PS_STRIDE;
    uint32_t* Vs = Ks + 128 * KS_STRIDE;

    const int tid  = threadIdx.x;
    const int lane = tid & 31;
    const int warp = tid >> 5;
    const int g    = lane >> 2;
    const int t    = lane & 3;
    const int m0   = warp * 16;

    const int q0 = blockIdx.x * 128;
    const int h  = blockIdx.y;
    const int b  = blockIdx.z;

    const float* Qb = Q  + (size_t)b * S * D + h * DK;
    const float* Kb = Kg + (size_t)b * S * D + h * DK;
    const float* Vb = Vg + (size_t)b * S * D + h * DK;

#pragma unroll
    for (int u = 0; u < 8; u++) {
        const int idx = u * 256 + tid;
        const int row = idx >> 4;
        const int c4  = (idx & 15) * 4;
        float4 v = *(const float4*)(Qb + (size_t)(q0 + row) * D + c4);
        Ps[row * PS_STRIDE + c4 + 0] = f2tf32(v.x * 0.125f);
        Ps[row * PS_STRIDE + c4 + 1] = f2tf32(v.y * 0.125f);
        Ps[row * PS_STRIDE + c4 + 2] = f2tf32(v.z * 0.125f);
        Ps[row * PS_STRIDE + c4 + 3] = f2tf32(v.w * 0.125f);
    }
    __syncthreads();

    uint32_t qf[8][4];
#pragma unroll
    for (int kc = 0; kc < 8; kc++) {
        const int kb = kc * 8;
        qf[kc][0] = Ps[(m0 + g)     * PS_STRIDE + kb + t];
        qf[kc][1] = Ps[(m0 + 8 + g) * PS_STRIDE + kb + t];
        qf[kc][2] = Ps[(m0 + g)     * PS_STRIDE + kb + 4 + t];
        qf[kc][3] = Ps[(m0 + 8 + g) * PS_STRIDE + kb + 4 + t];
    }

    float o[8][4];
#pragma unroll
    for (int j = 0; j < 8; j++)
#pragma unroll
        for (int c = 0; c < 4; c++) o[j][c] = 0.f;
    float mrun0 = -1e30f, mrun1 = -1e30f, lrun0 = 0.f, lrun1 = 0.f;

    for (int k0 = 0; k0 < S; k0 += 128) {
        __syncthreads();
#pragma unroll
        for (int u = 0; u < 8; u++) {
            const int idx = u * 256 + tid;
            const int row = idx >> 4;
            const int c4  = (idx & 15) * 4;
            float4 kv = *(const float4*)(Kb + (size_t)(k0 + row) * D + c4);
            Ks[row * KS_STRIDE + c4 + 0] = f2tf32(kv.x);
            Ks[row * KS_STRIDE + c4 + 1] = f2tf32(kv.y);
            Ks[row * KS_STRIDE + c4 + 2] = f2tf32(kv.z);
            Ks[row * KS_STRIDE + c4 + 3] = f2tf32(kv.w);
            float4 vv = *(const float4*)(Vb + (size_t)(k0 + row) * D + c4);
            Vs[row * VS_STRIDE + c4 + 0] = f2tf32(vv.x);
            Vs[row * VS_STRIDE + c4 + 1] = f2tf32(vv.y);
            Vs[row * VS_STRIDE + c4 + 2] = f2tf32(vv.z);
            Vs[row * VS_STRIDE + c4 + 3] = f2tf32(vv.w);
        }
        __syncthreads();

        float sc[16][4];
#pragma unroll
        for (int j = 0; j < 16; j++) {
            sc[j][0] = 0.f; sc[j][1] = 0.f; sc[j][2] = 0.f; sc[j][3] = 0.f;
            const int n0 = j * 8;
#pragma unroll
            for (int kc = 0; kc < 8; kc++) {
                const int kb = kc * 8;
                uint32_t bf[2];
                bf[0] = Ks[(n0 + g) * KS_STRIDE + kb + t];
                bf[1] = Ks[(n0 + g) * KS_STRIDE + kb + 4 + t];
                mma_tf32(sc[j], qf[kc], bf);
            }
        }

        float nm0 = -1e30f, nm1 = -1e30f;
#pragma unroll
        for (int j = 0; j < 16; j++) {
            nm0 = fmaxf(nm0, fmaxf(sc[j][0], sc[j][1]));
            nm1 = fmaxf(nm1, fmaxf(sc[j][2], sc[j][3]));
        }
        nm0 = fmaxf(nm0, __shfl_xor_sync(0xffffffffu, nm0, 1));
        nm0 = fmaxf(nm0, __shfl_xor_sync(0xffffffffu, nm0, 2));
        nm1 = fmaxf(nm1, __shfl_xor_sync(0xffffffffu, nm1, 1));
        nm1 = fmaxf(nm1, __shfl_xor_sync(0xffffffffu, nm1, 2));
        const float newm0 = fmaxf(mrun0, nm0);
        const float newm1 = fmaxf(mrun1, nm1);
        const float f0 = __expf(mrun0 - newm0);
        const float f1 = __expf(mrun1 - newm1);

        float s0 = 0.f, s1 = 0.f;
#pragma unroll
        for (int j = 0; j < 16; j++) {
            const float p00 = __expf(sc[j][0] - newm0);
            const float p01 = __expf(sc[j][1] - newm0);
            const float p10 = __expf(sc[j][2] - newm1);
            const float p11 = __expf(sc[j][3] - newm1);
            s0 += p00 + p01;
            s1 += p10 + p11;
            uint2 w0 = make_uint2(f2tf32(p00), f2tf32(p01));
            uint2 w1 = make_uint2(f2tf32(p10), f2tf32(p11));
            *(uint2*)&Ps[(m0 + g)     * PS_STRIDE + j * 8 + 2 * t] = w0;
            *(uint2*)&Ps[(m0 + 8 + g) * PS_STRIDE + j * 8 + 2 * t] = w1;
        }
        s0 += __shfl_xor_sync(0xffffffffu, s0, 1);
        s0 += __shfl_xor_sync(0xffffffffu, s0, 2);
        s1 += __shfl_xor_sync(0xffffffffu, s1, 1);
        s1 += __shfl_xor_sync(0xffffffffu, s1, 2);
        lrun0 = lrun0 * f0 + s0;
        lrun1 = lrun1 * f1 + s1;
        mrun0 = newm0;
        mrun1 = newm1;
#pragma unroll
        for (int j = 0; j < 8; j++) {
            o[j][0] *= f0; o[j][1] *= f0;
            o[j][2] *= f1; o[j][3] *= f1;
        }
        __syncwarp();

#pragma unroll
        for (int kc = 0; kc < 16; kc++) {
            const int kb = kc * 8;
            uint32_t a[4];
            a[0] = Ps[(m0 + g)     * PS_STRIDE + kb + t];
            a[1] = Ps[(m0 + 8 + g) * PS_STRIDE + kb + t];
            a[2] = Ps[(m0 + g)     * PS_STRIDE + kb + 4 + t];
            a[3] = Ps[(m0 + 8 + g) * PS_STRIDE + kb + 4 + t];
#pragma unroll
            for (int j = 0; j < 8; j++) {
                uint32_t bf[2];
                bf[0] = Vs[(kb + t)     * VS_STRIDE + j * 8 + g];
                bf[1] = Vs[(kb + 4 + t) * VS_STRIDE + j * 8 + g];
                mma_tf32(o[j], a, bf);
            }
        }
    }

    const float inv0 = 1.0f / lrun0;
    const float inv1 = 1.0f / lrun1;
    const int row0 = q0 + m0 + g;
    const int row1 = row0 + 8;
#pragma unroll
    for (int j = 0; j < 8; j++) {
        const int col = h * DK + j * 8 + 2 * t;
        float2 r0 = make_float2(o[j][0] * inv0, o[j][1] * inv0);
        float2 r1 = make_float2(o[j][2] * inv1, o[j][3] * inv1);
        *(float2*)(O + (size_t)(b * S + row0) * D + col) = r0;
        *(float2*)(O + (size_t)(b * S + row1) * D + col) = r1;
    }
}

// ---------------------------------------------------------------------------
// LayerNorm over (S,D) per batch
// ---------------------------------------------------------------------------
__global__ void __launch_bounds__(256)
ln_partial(const float* __restrict__ a, const float* __restrict__ c,
           float* __restrict__ y, float* __restrict__ part)
{
    const int b = blockIdx.y, chunk = blockIdx.x, tid = threadIdx.x;
    const size_t base = (size_t)b * S * D + (size_t)chunk * 4096 + tid * 16;
    float s = 0.f, s2 = 0.f;
#pragma unroll
    for (int i = 0; i < 16; i += 4) {
        float4 va = *(const float4*)(a + base + i);
        if (c) {
            float4 vc = *(const float4*)(c + base + i);
            va.x += vc.x; va.y += vc.y; va.z += vc.z; va.w += vc.w;
        }
        if (y) *(float4*)(y + base + i) = va;
        s  += va.x + va.y + va.z + va.w;
        s2 += va.x * va.x + va.y * va.y + va.z * va.z + va.w * va.w;
    }
    __shared__ float r1[256], r2[256];
    r1[tid] = s; r2[tid] = s2; __syncthreads();
    for (int st = 128; st > 0; st >>= 1) {
        if (tid < st) { r1[tid] += r1[tid + st]; r2[tid] += r2[tid + st]; }
        __syncthreads();
    }
    if (tid == 0) {
        part[b * 256 + chunk]            = r1[0];
        part[B * 256 + b * 256 + chunk]  = r2[0];
    }
}

__global__ void __launch_bounds__(256)
ln_finalize(const float* __restrict__ part, float* __restrict__ stats)
{
    const int b = blockIdx.x, tid = threadIdx.x;
    __shared__ float r1[256], r2[256];
    r1[tid] = part[b * 256 + tid];
    r2[tid] = part[B * 256 + b * 256 + tid];
    __syncthreads();
    for (int st = 128; st > 0; st >>= 1) {
        if (tid < st) { r1[tid] += r1[tid + st]; r2[tid] += r2[tid + st]; }
        __syncthreads();
    }
    if (tid == 0) {
        const float n = (float)S * (float)D;
        float mean = r1[0] / n;
        float var  = r2[0] / n - mean * mean;
        stats[2 * b]     = mean;
        stats[2 * b + 1] = rsqrtf(var + EPS);
    }
}

__global__ void __launch_bounds__(256)
ln_apply(const float* __restrict__ y, const float* __restrict__ g,
         const float* __restrict__ beta, const float* __restrict__ stats,
         float* __restrict__ out, float* __restrict__ out_r)
{
    const int b = blockIdx.y;
    const int idx = (blockIdx.x * 256 + threadIdx.x) * 4;
    const float mean = stats[2 * b];
    const float rstd = stats[2 * b + 1];
    const size_t off = (size_t)b * S * D + idx;
    float4 v  = *(const float4*)(y + off);
    float4 gg = *(const float4*)(g + idx);
    float4 bb = *(const float4*)(beta + idx);
    v.x = (v.x - mean) * rstd * gg.x + bb.x;
    v.y = (v.y - mean) * rstd * gg.y + bb.y;
    v.z = (v.z - mean) * rstd * gg.z + bb.z;
    v.w = (v.w - mean) * rstd * gg.w + bb.w;
    *(float4*)(out + off) = v;
    if (out_r) {
        float4 r;
        r.x = __uint_as_float(f2tf32(v.x));
        r.y = __uint_as_float(f2tf32(v.y));
        r.z = __uint_as_float(f2tf32(v.z));
        r.w = __uint_as_float(f2tf32(v.w));
        *(float4*)(out_r + off) = r;
    }
}

// ---------------------------------------------------------------------------
// kernel_launch
// ---------------------------------------------------------------------------
extern "C" void kernel_launch(void* const* d_in, const int* in_sizes, int n_in,
                              void* d_out, int out_size)
{
    const float* x    = (const float*)d_in[0];
    const float* wq   = (const float*)d_in[1];
    const float* bq   = (const float*)d_in[2];
    const float* wk   = (const float*)d_in[3];
    const float* bk   = (const float*)d_in[4];
    const float* wv   = (const float*)d_in[5];
    const float* bv   = (const float*)d_in[6];
    const float* ln1g = (const float*)d_in[7];
    const float* ln1b = (const float*)d_in[8];
    const float* w1   = (const float*)d_in[9];
    const float* b1   = (const float*)d_in[10];
    const float* w2   = (const float*)d_in[11];
    const float* b2   = (const float*)d_in[12];
    const float* ln2g = (const float*)d_in[13];
    const float* ln2b = (const float*)d_in[14];
    float* out = (float*)d_out;

    float *q, *k, *v, *ctx, *h, *ff, *part, *stats;
    float *xr, *hr, *wqr, *wkr, *wvr, *w1r, *w2r;
    cudaGetSymbolAddress((void**)&q,     g_q);
    cudaGetSymbolAddress((void**)&k,     g_k);
    cudaGetSymbolAddress((void**)&v,     g_v);
    cudaGetSymbolAddress((void**)&ctx,   g_ctx);
    cudaGetSymbolAddress((void**)&h,     g_h);
    cudaGetSymbolAddress((void**)&ff,    g_ff);
    cudaGetSymbolAddress((void**)&part,  g_part);
    cudaGetSymbolAddress((void**)&stats, g_stats);
    cudaGetSymbolAddress((void**)&xr,    g_xr);
    cudaGetSymbolAddress((void**)&hr,    g_hr);
    cudaGetSymbolAddress((void**)&wqr,   g_wqr);
    cudaGetSymbolAddress((void**)&wkr,   g_wkr);
    cudaGetSymbolAddress((void**)&wvr,   g_wvr);
    cudaGetSymbolAddress((void**)&w1r,   g_w1r);
    cudaGetSymbolAddress((void**)&w2r,   g_w2r);

    static bool attr_done = false;
    if (!attr_done) {
        cudaFuncSetAttribute(flash_attn,
                             cudaFuncAttributeMaxDynamicSharedMemorySize, ATTN_SMEM);
        cudaFuncSetAttribute(gemm_qkv,
                             cudaFuncAttributeMaxDynamicSharedMemorySize, GEMM_SMEM);
        cudaFuncSetAttribute(gemm_pipe<1>,
                             cudaFuncAttributeMaxDynamicSharedMemorySize, GEMM_SMEM);
        cudaFuncSetAttribute(gemm_pipe<2>,
                             cudaFuncAttributeMaxDynamicSharedMemorySize, GEMM_SMEM);
        attr_done = true;
    }

    // tf32 pre-rounding: exactly 5 launches so gemm_qkv is launch #6 (ncu -s 5)
    round_tf32<<<(NT * D / 4 + 255) / 256, 256>>>(x,  xr,  NT * D / 4);
    round_tf32<<<(D * D / 4 + 255) / 256, 256>>>(wq, wqr, D * D / 4);
    round_tf32<<<(D * D / 4 + 255) / 256, 256>>>(wk, wkr, D * D / 4);
    round_tf32<<<(D * D / 4 + 255) / 256, 256>>>(wv, wvr, D * D / 4);
    round2_tf32<<<dim3((D * DFF / 4 + 255) / 256, 1, 2), 256>>>(
        w1, w1r, w2, w2r, D * DFF / 4);

    // QKV projections (fused launch, pre-rounded operands)  — launch #6
    gemm_qkv<<<dim3(D / 128, NT / 128, 3), 256, GEMM_SMEM>>>(
        xr, wqr, bq, wkr, bk, wvr, bv, q, k, v);

    // Flash attention
    flash_attn<<<dim3(S / 128, H, B), 256, ATTN_SMEM>>>(q, k, v, ctx);

    // LayerNorm 1: h = LN(x + ctx) (+ rounded copy hr)
    ln_partial<<<dim3(256, B), 256>>>(x, ctx, h, part);
    ln_finalize<<<B, 256>>>(part, stats);
    ln_apply<<<dim3(1024, B), 256>>>(h, ln1g, ln1b, stats, h, hr);

    // FFN: ff = round(gelu(hr @ w1r + b1));  ctx = ff @ w2r + b2 + h
    gemm_pipe<1><<<dim3(DFF / 128, NT / 128), 256, GEMM_SMEM>>>(hr, w1r, b1, nullptr, ff, D, DFF);
    gemm_pipe<2><<<dim3(D / 128, NT / 128),   256, GEMM_SMEM>>>(ff, w2r, b2, h, ctx, DFF, D);

    // LayerNorm 2 -> output
    ln_partial<<<dim3(256, B), 256>>>(ctx, nullptr, nullptr, part);
    ln_finalize<<<B, 256>>>(part, stats);
    ln_apply<<<dim3(1024, B), 256>>>(ctx, ln2g, ln2b, stats, out, nullptr);
}

// round 12
// speedup vs baseline: 1.7434x; 1.0347x over previous
#include <cuda_runtime.h>
#include <math.h>
#include <stdint.h>

// Problem constants
constexpr int B   = 8;
constexpr int S   = 1024;
constexpr int D   = 1024;
constexpr int H   = 16;
constexpr int DK  = 64;
constexpr int DFF = 4096;
constexpr int NT  = B * S;          // 8192 rows
constexpr float EPS = 1e-5f;

// ---------------------------------------------------------------------------
// Scratch (static __device__ arrays — no runtime allocation)
// ---------------------------------------------------------------------------
__device__ float g_q  [NT * D];
__device__ float g_k  [NT * D];
__device__ float g_v  [NT * D];
__device__ float g_ctx[NT * D];
__device__ float g_h  [NT * D];
__device__ float g_ff [(size_t)NT * DFF];
__device__ float g_part[2 * B * 256];
__device__ float g_stats[2 * B];
// tf32-pre-rounded operand copies
__device__ float g_xr [NT * D];
__device__ float g_hr [NT * D];
__device__ float g_wqr[D * D];
__device__ float g_wkr[D * D];
__device__ float g_wvr[D * D];
__device__ float g_w1r[D * DFF];
__device__ float g_w2r[DFF * D];

// ---------------------------------------------------------------------------
// tf32 / async helpers
// ---------------------------------------------------------------------------
__device__ __forceinline__ uint32_t f2tf32(float x) {
    uint32_t r;
    asm("cvt.rna.tf32.f32 %0, %1;" : "=r"(r) : "f"(x));
    return r;
}

__device__ __forceinline__ void mma_tf32(float c[4], const uint32_t a[4], const uint32_t b[2]) {
    asm volatile(
        "mma.sync.aligned.m16n8k8.row.col.f32.tf32.tf32.f32 "
        "{%0,%1,%2,%3}, {%4,%5,%6,%7}, {%8,%9}, {%0,%1,%2,%3};\n"
        : "+f"(c[0]), "+f"(c[1]), "+f"(c[2]), "+f"(c[3])
        : "r"(a[0]), "r"(a[1]), "r"(a[2]), "r"(a[3]), "r"(b[0]), "r"(b[1]));
}

__device__ __forceinline__ void cp_async16(void* smem_ptr, const void* gptr) {
    uint32_t sa = (uint32_t)__cvta_generic_to_shared(smem_ptr);
    asm volatile("cp.async.cg.shared.global [%0], [%1], 16;\n" :: "r"(sa), "l"(gptr));
}
__device__ __forceinline__ void cp_commit() {
    asm volatile("cp.async.commit_group;\n");
}

// ---------------------------------------------------------------------------
// Pre-pass kernels: tf32 rounding
// ---------------------------------------------------------------------------
__global__ void __launch_bounds__(256)
round_tf32(const float* __restrict__ in, float* __restrict__ out, int n4)
{
    const int i = blockIdx.x * 256 + threadIdx.x;
    if (i < n4) {
        float4 v = ((const float4*)in)[i];
        v.x = __uint_as_float(f2tf32(v.x));
        v.y = __uint_as_float(f2tf32(v.y));
        v.z = __uint_as_float(f2tf32(v.z));
        v.w = __uint_as_float(f2tf32(v.w));
        ((float4*)out)[i] = v;
    }
}

__global__ void __launch_bounds__(256)
round2_tf32(const float* __restrict__ inA, float* __restrict__ outA,
            const float* __restrict__ inB, float* __restrict__ outB, int n4)
{
    const int i = blockIdx.x * 256 + threadIdx.x;
    const float* in  = blockIdx.z == 0 ? inA  : inB;
    float*       out = blockIdx.z == 0 ? outA : outB;
    if (i < n4) {
        float4 v = ((const float4*)in)[i];
        v.x = __uint_as_float(f2tf32(v.x));
        v.y = __uint_as_float(f2tf32(v.y));
        v.z = __uint_as_float(f2tf32(v.z));
        v.w = __uint_as_float(f2tf32(v.w));
        ((float4*)out)[i] = v;
    }
}

// ---------------------------------------------------------------------------
// Pipelined TF32 GEMM (round-10 layout, unchanged — best known config)
// ---------------------------------------------------------------------------
constexpr int ASZ = 128 * 36;
constexpr int BSZ = 32 * 136;
constexpr int GEMM_SMEM = 3 * (ASZ + BSZ) * 4;   // 107,520 B

template <int EPI>
__device__ __forceinline__ void gemm_body(
    const float* __restrict__ A, const float* __restrict__ W,
    const float* __restrict__ bias, const float* __restrict__ res,
    float* __restrict__ C, int K, int N, int bx, int by, float* sm)
{
    float* AsB = sm;
    float* BsB = sm + 3 * ASZ;

    const int tid  = threadIdx.x;
    const int lane = tid & 31;
    const int warp = tid >> 5;
    const int g    = lane >> 2;
    const int t    = lane & 3;
    const int wm   = (warp & 1) * 64;
    const int wn   = (warp >> 1) * 32;

    const float* Ab = A + (size_t)(by * 128) * K;
    const float* Wb = W + bx * 128;

    float acc[4][4][4];
#pragma unroll
    for (int mi = 0; mi < 4; mi++)
#pragma unroll
        for (int nj = 0; nj < 4; nj++)
#pragma unroll
            for (int c = 0; c < 4; c++) acc[mi][nj][c] = 0.f;

    const uint32_t* Ac0 = (const uint32_t*)(AsB);
    const uint32_t* Ac1 = (const uint32_t*)(AsB + ASZ);
    const uint32_t* Ac2 = (const uint32_t*)(AsB + 2 * ASZ);
    const uint32_t* Bc0 = (const uint32_t*)(BsB);
    const uint32_t* Bc1 = (const uint32_t*)(BsB + BSZ);
    const uint32_t* Bc2 = (const uint32_t*)(BsB + 2 * BSZ);

    auto stage_to = [&](float* Ad, float* Bd, int kk) {
#pragma unroll
        for (int u = 0; u < 4; u++) {
            const int i   = tid + u * 256;
            const int row = i >> 3;
            const int c4  = (i & 7) * 4;
            cp_async16(Ad + row * 36 + c4, Ab + (size_t)row * K + kk + c4);
        }
#pragma unroll
        for (int u = 0; u < 4; u++) {
            const int i   = tid + u * 256;
            const int row = i >> 5;
            const int c4  = (i & 31) * 4;
            cp_async16(Bd + row * 136 + c4, Wb + (size_t)(kk + row) * N + c4);
        }
        cp_commit();
    };

    const int nT = K >> 5;
    stage_to((float*)Ac0, (float*)Bc0, 0);
    if (nT > 1) stage_to((float*)Ac1, (float*)Bc1, 32);

    for (int tt = 0; tt < nT; tt++) {
        if (tt + 1 < nT) asm volatile("cp.async.wait_group 1;\n" ::: "memory");
        else             asm volatile("cp.async.wait_group 0;\n" ::: "memory");
        __syncthreads();
        if (tt + 2 < nT) stage_to((float*)Ac2, (float*)Bc2, (tt + 2) * 32);

#pragma unroll
        for (int ks = 0; ks < 4; ks++) {
            const int kb = ks * 8;
            uint32_t a[4][4], b[4][2];
#pragma unroll
            for (int mi = 0; mi < 4; mi++) {
                const int m0 = wm + mi * 16;
                a[mi][0] = Ac0[(m0 + g)     * 36 + kb + t];
                a[mi][1] = Ac0[(m0 + 8 + g) * 36 + kb + t];
                a[mi][2] = Ac0[(m0 + g)     * 36 + kb + 4 + t];
                a[mi][3] = Ac0[(m0 + 8 + g) * 36 + kb + 4 + t];
            }
#pragma unroll
            for (int nj = 0; nj < 4; nj++) {
                const int n0 = wn + nj * 8;
                b[nj][0] = Bc0[(kb + t)     * 136 + n0 + g];
                b[nj][1] = Bc0[(kb + 4 + t) * 136 + n0 + g];
            }
#pragma unroll
            for (int mi = 0; mi < 4; mi++)
#pragma unroll
                for (int nj = 0; nj < 4; nj++)
                    mma_tf32(acc[mi][nj], a[mi], b[nj]);
        }

        const uint32_t* ta = Ac0; Ac0 = Ac1; Ac1 = Ac2; Ac2 = ta;
        const uint32_t* tb = Bc0; Bc0 = Bc1; Bc1 = Bc2; Bc2 = tb;
    }

#pragma unroll
    for (int mi = 0; mi < 4; mi++) {
#pragma unroll
        for (int nj = 0; nj < 4; nj++) {
            const int row = by * 128 + wm + mi * 16 + g;
            const int col = bx * 128 + wn + nj * 8 + t * 2;
#pragma unroll
            for (int half = 0; half < 2; half++) {
                const int r = row + half * 8;
                float v0 = acc[mi][nj][half * 2 + 0] + bias[col];
                float v1 = acc[mi][nj][half * 2 + 1] + bias[col + 1];
                if (EPI == 1) {
                    v0 = 0.5f * v0 * (1.0f + erff(v0 * 0.70710678118654752f));
                    v1 = 0.5f * v1 * (1.0f + erff(v1 * 0.70710678118654752f));
                    v0 = __uint_as_float(f2tf32(v0));
                    v1 = __uint_as_float(f2tf32(v1));
                } else if (EPI == 2) {
                    v0 += res[(size_t)r * N + col];
                    v1 += res[(size_t)r * N + col + 1];
                }
                float2 out = make_float2(v0, v1);
                *(float2*)(C + (size_t)r * N + col) = out;
            }
        }
    }
}

__global__ void __launch_bounds__(256, 2)
gemm_qkv(const float* __restrict__ x,
         const float* __restrict__ wq, const float* __restrict__ bq,
         const float* __restrict__ wk, const float* __restrict__ bk,
         const float* __restrict__ wv, const float* __restrict__ bv,
         float* __restrict__ q, float* __restrict__ k, float* __restrict__ v)
{
    extern __shared__ float sm[];
    const float* W; const float* bias; float* C;
    if (blockIdx.z == 0)      { W = wq; bias = bq; C = q; }
    else if (blockIdx.z == 1) { W = wk; bias = bk; C = k; }
    else                      { W = wv; bias = bv; C = v; }
    gemm_body<0>(x, W, bias, nullptr, C, D, D, blockIdx.x, blockIdx.y, sm);
}

template <int EPI>
__global__ void __launch_bounds__(256, 2)
gemm_pipe(const float* __restrict__ A, const float* __restrict__ W,
          const float* __restrict__ bias, const float* __restrict__ res,
          float* __restrict__ C, int K, int N)
{
    extern __shared__ float sm[];
    gemm_body<EPI>(A, W, bias, res, C, K, N, blockIdx.x, blockIdx.y, sm);
}

// ---------------------------------------------------------------------------
// Flash attention, K-tile = 64 (smem 69 KB -> 2 CTAs/SM).
// One block per (b, h, 128-row q tile). 256 threads, 8 warps x 16 q rows.
// ---------------------------------------------------------------------------
constexpr int PS_STRIDE = 68;   // Q/P: 128 rows x 64 cols (+4 pad)
constexpr int KS_STRIDE = 68;   // K:    64 rows x 64 cols (+4 pad)
constexpr int VS_STRIDE = 72;   // V:    64 rows x 64 cols (+8 pad)
constexpr int ATTN_SMEM = (128 * PS_STRIDE + 64 * KS_STRIDE + 64 * VS_STRIDE) * 4; // 70,656 B

__global__ void __launch_bounds__(256, 2)
flash_attn(const float* __restrict__ Q, const float* __restrict__ Kg,
           const float* __restrict__ Vg, float* __restrict__ O)
{
    extern __shared__ uint32_t smem[];
    uint32_t* Ps = smem;                        // [128][68]
    uint32_t* Ks = Ps + 128 * PS_STRIDE;        // [64][68]
    uint32_t* Vs = Ks + 64 * KS_STRIDE;         // [64][72]

    const int tid  = threadIdx.x;
    const int lane = tid & 31;
    const int warp = tid >> 5;
    const int g    = lane >> 2;
    const int t    = lane & 3;
    const int m0   = warp * 16;

    const int q0 = blockIdx.x * 128;
    const int h  = blockIdx.y;
    const int b  = blockIdx.z;

    const float* Qb = Q  + (size_t)b * S * D + h * DK;
    const float* Kb = Kg + (size_t)b * S * D + h * DK;
    const float* Vb = Vg + (size_t)b * S * D + h * DK;

    // ---- stage Q tile (128 x 64, scaled)
#pragma unroll
    for (int u = 0; u < 8; u++) {
        const int idx = u * 256 + tid;
        const int row = idx >> 4;
        const int c4  = (idx & 15) * 4;
        float4 v = *(const float4*)(Qb + (size_t)(q0 + row) * D + c4);
        Ps[row * PS_STRIDE + c4 + 0] = f2tf32(v.x * 0.125f);
        Ps[row * PS_STRIDE + c4 + 1] = f2tf32(v.y * 0.125f);
        Ps[row * PS_STRIDE + c4 + 2] = f2tf32(v.z * 0.125f);
        Ps[row * PS_STRIDE + c4 + 3] = f2tf32(v.w * 0.125f);
    }
    __syncthreads();

    uint32_t qf[8][4];
#pragma unroll
    for (int kc = 0; kc < 8; kc++) {
        const int kb = kc * 8;
        qf[kc][0] = Ps[(m0 + g)     * PS_STRIDE + kb + t];
        qf[kc][1] = Ps[(m0 + 8 + g) * PS_STRIDE + kb + t];
        qf[kc][2] = Ps[(m0 + g)     * PS_STRIDE + kb + 4 + t];
        qf[kc][3] = Ps[(m0 + 8 + g) * PS_STRIDE + kb + 4 + t];
    }

    float o[8][4];
#pragma unroll
    for (int j = 0; j < 8; j++)
#pragma unroll
        for (int c = 0; c < 4; c++) o[j][c] = 0.f;
    float mrun0 = -1e30f, mrun1 = -1e30f, lrun0 = 0.f, lrun1 = 0.f;

    for (int k0 = 0; k0 < S; k0 += 64) {
        __syncthreads();
        // ---- stage K, V tiles (64 keys x 64 dk)
#pragma unroll
        for (int u = 0; u < 4; u++) {
            const int idx = u * 256 + tid;
            const int row = idx >> 4;
            const int c4  = (idx & 15) * 4;
            float4 kv = *(const float4*)(Kb + (size_t)(k0 + row) * D + c4);
            Ks[row * KS_STRIDE + c4 + 0] = f2tf32(kv.x);
            Ks[row * KS_STRIDE + c4 + 1] = f2tf32(kv.y);
            Ks[row * KS_STRIDE + c4 + 2] = f2tf32(kv.z);
            Ks[row * KS_STRIDE + c4 + 3] = f2tf32(kv.w);
            float4 vv = *(const float4*)(Vb + (size_t)(k0 + row) * D + c4);
            Vs[row * VS_STRIDE + c4 + 0] = f2tf32(vv.x);
            Vs[row * VS_STRIDE + c4 + 1] = f2tf32(vv.y);
            Vs[row * VS_STRIDE + c4 + 2] = f2tf32(vv.z);
            Vs[row * VS_STRIDE + c4 + 3] = f2tf32(vv.w);
        }
        __syncthreads();

        // ---- S = Q K^T : 8 n-frags (64 keys), 8 k-chunks
        float sc[8][4];
#pragma unroll
        for (int j = 0; j < 8; j++) {
            sc[j][0] = 0.f; sc[j][1] = 0.f; sc[j][2] = 0.f; sc[j][3] = 0.f;
            const int n0 = j * 8;
#pragma unroll
            for (int kc = 0; kc < 8; kc++) {
                const int kb = kc * 8;
                uint32_t bf[2];
                bf[0] = Ks[(n0 + g) * KS_STRIDE + kb + t];
                bf[1] = Ks[(n0 + g) * KS_STRIDE + kb + 4 + t];
                mma_tf32(sc[j], qf[kc], bf);
            }
        }

        // ---- online softmax
        float nm0 = -1e30f, nm1 = -1e30f;
#pragma unroll
        for (int j = 0; j < 8; j++) {
            nm0 = fmaxf(nm0, fmaxf(sc[j][0], sc[j][1]));
            nm1 = fmaxf(nm1, fmaxf(sc[j][2], sc[j][3]));
        }
        nm0 = fmaxf(nm0, __shfl_xor_sync(0xffffffffu, nm0, 1));
        nm0 = fmaxf(nm0, __shfl_xor_sync(0xffffffffu, nm0, 2));
        nm1 = fmaxf(nm1, __shfl_xor_sync(0xffffffffu, nm1, 1));
        nm1 = fmaxf(nm1, __shfl_xor_sync(0xffffffffu, nm1, 2));
        const float newm0 = fmaxf(mrun0, nm0);
        const float newm1 = fmaxf(mrun1, nm1);
        const float f0 = __expf(mrun0 - newm0);
        const float f1 = __expf(mrun1 - newm1);

        float s0 = 0.f, s1 = 0.f;
#pragma unroll
        for (int j = 0; j < 8; j++) {
            const float p00 = __expf(sc[j][0] - newm0);
            const float p01 = __expf(sc[j][1] - newm0);
            const float p10 = __expf(sc[j][2] - newm1);
            const float p11 = __expf(sc[j][3] - newm1);
            s0 += p00 + p01;
            s1 += p10 + p11;
            uint2 w0 = make_uint2(f2tf32(p00), f2tf32(p01));
            uint2 w1 = make_uint2(f2tf32(p10), f2tf32(p11));
            *(uint2*)&Ps[(m0 + g)     * PS_STRIDE + j * 8 + 2 * t] = w0;
            *(uint2*)&Ps[(m0 + 8 + g) * PS_STRIDE + j * 8 + 2 * t] = w1;
        }
        s0 += __shfl_xor_sync(0xffffffffu, s0, 1);
        s0 += __shfl_xor_sync(0xffffffffu, s0, 2);
        s1 += __shfl_xor_sync(0xffffffffu, s1, 1);
        s1 += __shfl_xor_sync(0xffffffffu, s1, 2);
        lrun0 = lrun0 * f0 + s0;
        lrun1 = lrun1 * f1 + s1;
        mrun0 = newm0;
        mrun1 = newm1;
#pragma unroll
        for (int j = 0; j < 8; j++) {
            o[j][0] *= f0; o[j][1] *= f0;
            o[j][2] *= f1; o[j][3] *= f1;
        }
        __syncwarp();   // P writes visible within warp before A-frag reads

        // ---- O += P V : 8 k-chunks (64 keys), 8 n-frags (64 dk)
#pragma unroll
        for (int kc = 0; kc < 8; kc++) {
            const int kb = kc * 8;
            uint32_t a[4];
            a[0] = Ps[(m0 + g)     * PS_STRIDE + kb + t];
            a[1] = Ps[(m0 + 8 + g) * PS_STRIDE + kb + t];
            a[2] = Ps[(m0 + g)     * PS_STRIDE + kb + 4 + t];
            a[3] = Ps[(m0 + 8 + g) * PS_STRIDE + kb + 4 + t];
#pragma unroll
            for (int j = 0; j < 8; j++) {
                uint32_t bf[2];
                bf[0] = Vs[(kb + t)     * VS_STRIDE + j * 8 + g];
                bf[1] = Vs[(kb + 4 + t) * VS_STRIDE + j * 8 + g];
                mma_tf32(o[j], a, bf);
            }
        }
    }

    const float inv0 = 1.0f / lrun0;
    const float inv1 = 1.0f / lrun1;
    const int row0 = q0 + m0 + g;
    const int row1 = row0 + 8;
#pragma unroll
    for (int j = 0; j < 8; j++) {
        const int col = h * DK + j * 8 + 2 * t;
        float2 r0 = make_float2(o[j][0] * inv0, o[j][1] * inv0);
        float2 r1 = make_float2(o[j][2] * inv1, o[j][3] * inv1);
        *(float2*)(O + (size_t)(b * S + row0) * D + col) = r0;
        *(float2*)(O + (size_t)(b * S + row1) * D + col) = r1;
    }
}

// ---------------------------------------------------------------------------
// LayerNorm over (S,D) per batch
// ---------------------------------------------------------------------------
__global__ void __launch_bounds__(256)
ln_partial(const float* __restrict__ a, const float* __restrict__ c,
           float* __restrict__ y, float* __restrict__ part)
{
    const int b = blockIdx.y, chunk = blockIdx.x, tid = threadIdx.x;
    const size_t base = (size_t)b * S * D + (size_t)chunk * 4096 + tid * 16;
    float s = 0.f, s2 = 0.f;
#pragma unroll
    for (int i = 0; i < 16; i += 4) {
        float4 va = *(const float4*)(a + base + i);
        if (c) {
            float4 vc = *(const float4*)(c + base + i);
            va.x += vc.x; va.y += vc.y; va.z += vc.z; va.w += vc.w;
        }
        if (y) *(float4*)(y + base + i) = va;
        s  += va.x + va.y + va.z + va.w;
        s2 += va.x * va.x + va.y * va.y + va.z * va.z + va.w * va.w;
    }
    __shared__ float r1[256], r2[256];
    r1[tid] = s; r2[tid] = s2; __syncthreads();
    for (int st = 128; st > 0; st >>= 1) {
        if (tid < st) { r1[tid] += r1[tid + st]; r2[tid] += r2[tid + st]; }
        __syncthreads();
    }
    if (tid == 0) {
        part[b * 256 + chunk]            = r1[0];
        part[B * 256 + b * 256 + chunk]  = r2[0];
    }
}

__global__ void __launch_bounds__(256)
ln_finalize(const float* __restrict__ part, float* __restrict__ stats)
{
    const int b = blockIdx.x, tid = threadIdx.x;
    __shared__ float r1[256], r2[256];
    r1[tid] = part[b * 256 + tid];
    r2[tid] = part[B * 256 + b * 256 + tid];
    __syncthreads();
    for (int st = 128; st > 0; st >>= 1) {
        if (tid < st) { r1[tid] += r1[tid + st]; r2[tid] += r2[tid + st]; }
        __syncthreads();
    }
    if (tid == 0) {
        const float n = (float)S * (float)D;
        float mean = r1[0] / n;
        float var  = r2[0] / n - mean * mean;
        stats[2 * b]     = mean;
        stats[2 * b + 1] = rsqrtf(var + EPS);
    }
}

__global__ void __launch_bounds__(256)
ln_apply(const float* __restrict__ y, const float* __restrict__ g,
         const float* __restrict__ beta, const float* __restrict__ stats,
         float* __restrict__ out, float* __restrict__ out_r)
{
    const int b = blockIdx.y;
    const int idx = (blockIdx.x * 256 + threadIdx.x) * 4;
    const float mean = stats[2 * b];
    const float rstd = stats[2 * b + 1];
    const size_t off = (size_t)b * S * D + idx;
    float4 v  = *(const float4*)(y + off);
    float4 gg = *(const float4*)(g + idx);
    float4 bb = *(const float4*)(beta + idx);
    v.x = (v.x - mean) * rstd * gg.x + bb.x;
    v.y = (v.y - mean) * rstd * gg.y + bb.y;
    v.z = (v.z - mean) * rstd * gg.z + bb.z;
    v.w = (v.w - mean) * rstd * gg.w + bb.w;
    *(float4*)(out + off) = v;
    if (out_r) {
        float4 r;
        r.x = __uint_as_float(f2tf32(v.x));
        r.y = __uint_as_float(f2tf32(v.y));
        r.z = __uint_as_float(f2tf32(v.z));
        r.w = __uint_as_float(f2tf32(v.w));
        *(float4*)(out_r + off) = r;
    }
}

// ---------------------------------------------------------------------------
// kernel_launch
// ---------------------------------------------------------------------------
extern "C" void kernel_launch(void* const* d_in, const int* in_sizes, int n_in,
                              void* d_out, int out_size)
{
    const float* x    = (const float*)d_in[0];
    const float* wq   = (const float*)d_in[1];
    const float* bq   = (const float*)d_in[2];
    const float* wk   = (const float*)d_in[3];
    const float* bk   = (const float*)d_in[4];
    const float* wv   = (const float*)d_in[5];
    const float* bv   = (const float*)d_in[6];
    const float* ln1g = (const float*)d_in[7];
    const float* ln1b = (const float*)d_in[8];
    const float* w1   = (const float*)d_in[9];
    const float* b1   = (const float*)d_in[10];
    const float* w2   = (const float*)d_in[11];
    const float* b2   = (const float*)d_in[12];
    const float* ln2g = (const float*)d_in[13];
    const float* ln2b = (const float*)d_in[14];
    float* out = (float*)d_out;

    float *q, *k, *v, *ctx, *h, *ff, *part, *stats;
    float *xr, *hr, *wqr, *wkr, *wvr, *w1r, *w2r;
    cudaGetSymbolAddress((void**)&q,     g_q);
    cudaGetSymbolAddress((void**)&k,     g_k);
    cudaGetSymbolAddress((void**)&v,     g_v);
    cudaGetSymbolAddress((void**)&ctx,   g_ctx);
    cudaGetSymbolAddress((void**)&h,     g_h);
    cudaGetSymbolAddress((void**)&ff,    g_ff);
    cudaGetSymbolAddress((void**)&part,  g_part);
    cudaGetSymbolAddress((void**)&stats, g_stats);
    cudaGetSymbolAddress((void**)&xr,    g_xr);
    cudaGetSymbolAddress((void**)&hr,    g_hr);
    cudaGetSymbolAddress((void**)&wqr,   g_wqr);
    cudaGetSymbolAddress((void**)&wkr,   g_wkr);
    cudaGetSymbolAddress((void**)&wvr,   g_wvr);
    cudaGetSymbolAddress((void**)&w1r,   g_w1r);
    cudaGetSymbolAddress((void**)&w2r,   g_w2r);

    static bool attr_done = false;
    if (!attr_done) {
        cudaFuncSetAttribute(flash_attn,
                             cudaFuncAttributeMaxDynamicSharedMemorySize, ATTN_SMEM);
        cudaFuncSetAttribute(gemm_qkv,
                             cudaFuncAttributeMaxDynamicSharedMemorySize, GEMM_SMEM);
        cudaFuncSetAttribute(gemm_pipe<1>,
                             cudaFuncAttributeMaxDynamicSharedMemorySize, GEMM_SMEM);
        cudaFuncSetAttribute(gemm_pipe<2>,
                             cudaFuncAttributeMaxDynamicSharedMemorySize, GEMM_SMEM);
        attr_done = true;
    }

    // tf32 pre-rounding (5 launches)
    round_tf32<<<(NT * D / 4 + 255) / 256, 256>>>(x,  xr,  NT * D / 4);
    round_tf32<<<(D * D / 4 + 255) / 256, 256>>>(wq, wqr, D * D / 4);
    round_tf32<<<(D * D / 4 + 255) / 256, 256>>>(wk, wkr, D * D / 4);
    round_tf32<<<(D * D / 4 + 255) / 256, 256>>>(wv, wvr, D * D / 4);
    round2_tf32<<<dim3((D * DFF / 4 + 255) / 256, 1, 2), 256>>>(
        w1, w1r, w2, w2r, D * DFF / 4);

    // QKV projections (fused launch, pre-rounded operands)
    gemm_qkv<<<dim3(D / 128, NT / 128, 3), 256, GEMM_SMEM>>>(
        xr, wqr, bq, wkr, bk, wvr, bv, q, k, v);

    // Flash attention (K-tile 64, 2 CTAs/SM)
    flash_attn<<<dim3(S / 128, H, B), 256, ATTN_SMEM>>>(q, k, v, ctx);

    // LayerNorm 1: h = LN(x + ctx) (+ rounded copy hr)
    ln_partial<<<dim3(256, B), 256>>>(x, ctx, h, part);
    ln_finalize<<<B, 256>>>(part, stats);
    ln_apply<<<dim3(1024, B), 256>>>(h, ln1g, ln1b, stats, h, hr);

    // FFN: ff = round(gelu(hr @ w1r + b1));  ctx = ff @ w2r + b2 + h
    gemm_pipe<1><<<dim3(DFF / 128, NT / 128), 256, GEMM_SMEM>>>(hr, w1r, b1, nullptr, ff, D, DFF);
    gemm_pipe<2><<<dim3(D / 128, NT / 128),   256, GEMM_SMEM>>>(ff, w2r, b2, h, ctx, DFF, D);

    // LayerNorm 2 -> output
    ln_partial<<<dim3(256, B), 256>>>(ctx, nullptr, nullptr, part);
    ln_finalize<<<B, 256>>>(part, stats);
    ln_apply<<<dim3(1024, B), 256>>>(ctx, ln2g, ln2b, stats, out, nullptr);
}

// round 13
// speedup vs baseline: 1.7480x; 1.0027x over previous
#include <cuda_runtime.h>
#include <math.h>
#include <stdint.h>

// Problem constants
constexpr int B   = 8;
constexpr int S   = 1024;
constexpr int D   = 1024;
constexpr int H   = 16;
constexpr int DK  = 64;
constexpr int DFF = 4096;
constexpr int NT  = B * S;          // 8192 rows
constexpr float EPS = 1e-5f;

// ---------------------------------------------------------------------------
// Scratch (static __device__ arrays — no runtime allocation)
// ---------------------------------------------------------------------------
__device__ float g_q  [NT * D];
__device__ float g_k  [NT * D];
__device__ float g_v  [NT * D];
__device__ float g_ctx[NT * D];
__device__ float g_h  [NT * D];
__device__ float g_ff [(size_t)NT * DFF];
__device__ float g_part[2 * B * 256];
__device__ float g_stats[2 * B];
// tf32-pre-rounded operand copies
__device__ float g_xr [NT * D];
__device__ float g_hr [NT * D];
__device__ float g_wqr[D * D];
__device__ float g_wkr[D * D];
__device__ float g_wvr[D * D];
__device__ float g_w1r[D * DFF];
__device__ float g_w2r[DFF * D];

// ---------------------------------------------------------------------------
// tf32 / async helpers
// ---------------------------------------------------------------------------
__device__ __forceinline__ uint32_t f2tf32(float x) {
    uint32_t r;
    asm("cvt.rna.tf32.f32 %0, %1;" : "=r"(r) : "f"(x));
    return r;
}

__device__ __forceinline__ void mma_tf32(float c[4], const uint32_t a[4], const uint32_t b[2]) {
    asm volatile(
        "mma.sync.aligned.m16n8k8.row.col.f32.tf32.tf32.f32 "
        "{%0,%1,%2,%3}, {%4,%5,%6,%7}, {%8,%9}, {%0,%1,%2,%3};\n"
        : "+f"(c[0]), "+f"(c[1]), "+f"(c[2]), "+f"(c[3])
        : "r"(a[0]), "r"(a[1]), "r"(a[2]), "r"(a[3]), "r"(b[0]), "r"(b[1]));
}

__device__ __forceinline__ void cp_async16(void* smem_ptr, const void* gptr) {
    uint32_t sa = (uint32_t)__cvta_generic_to_shared(smem_ptr);
    asm volatile("cp.async.cg.shared.global [%0], [%1], 16;\n" :: "r"(sa), "l"(gptr));
}
__device__ __forceinline__ void cp_commit() {
    asm volatile("cp.async.commit_group;\n");
}

// ---------------------------------------------------------------------------
// Prepass: all tf32 rounding in ONE kernel (flat segment dispatch)
// ---------------------------------------------------------------------------
constexpr int N_X = NT * D / 4;     // 2,097,152 float4
constexpr int N_W = D * D / 4;      //   262,144
constexpr int N_F = D * DFF / 4;    // 1,048,576
constexpr int N_ALL = N_X + 3 * N_W + 2 * N_F;

__global__ void __launch_bounds__(256)
round_all(const float* __restrict__ x,  float* __restrict__ xr,
          const float* __restrict__ wq, float* __restrict__ wqr,
          const float* __restrict__ wk, float* __restrict__ wkr,
          const float* __restrict__ wv, float* __restrict__ wvr,
          const float* __restrict__ w1, float* __restrict__ w1r,
          const float* __restrict__ w2, float* __restrict__ w2r)
{
    int i = blockIdx.x * 256 + threadIdx.x;
    if (i >= N_ALL) return;
    const float* in; float* out; int j;
    if (i < N_X)                    { in = x;  out = xr;  j = i; }
    else if (i < N_X + N_W)         { in = wq; out = wqr; j = i - N_X; }
    else if (i < N_X + 2 * N_W)     { in = wk; out = wkr; j = i - N_X - N_W; }
    else if (i < N_X + 3 * N_W)     { in = wv; out = wvr; j = i - N_X - 2 * N_W; }
    else if (i < N_X + 3 * N_W + N_F) { in = w1; out = w1r; j = i - N_X - 3 * N_W; }
    else                            { in = w2; out = w2r; j = i - N_X - 3 * N_W - N_F; }
    float4 v = ((const float4*)in)[j];
    v.x = __uint_as_float(f2tf32(v.x));
    v.y = __uint_as_float(f2tf32(v.y));
    v.z = __uint_as_float(f2tf32(v.z));
    v.w = __uint_as_float(f2tf32(v.w));
    ((float4*)out)[j] = v;
}

// ---------------------------------------------------------------------------
// Pipelined TF32 GEMM (round-10 best layout).
// EPI: 0 = bias, 1 = bias+GeLU+round, 2 = bias+residual (+LN partial sums),
//      3 = (bias + out)*oscale then tf32-round  (QKV outputs for attention)
// ---------------------------------------------------------------------------
constexpr int ASZ = 128 * 36;
constexpr int BSZ = 32 * 136;
constexpr int GEMM_SMEM = 3 * (ASZ + BSZ) * 4;   // 107,520 B

template <int EPI>
__device__ __forceinline__ void gemm_body(
    const float* __restrict__ A, const float* __restrict__ W,
    const float* __restrict__ bias, const float* __restrict__ res,
    float* __restrict__ C, int K, int N, int bx, int by, float* sm,
    float oscale, float* __restrict__ part2)
{
    float* AsB = sm;
    float* BsB = sm + 3 * ASZ;

    const int tid  = threadIdx.x;
    const int lane = tid & 31;
    const int warp = tid >> 5;
    const int g    = lane >> 2;
    const int t    = lane & 3;
    const int wm   = (warp & 1) * 64;
    const int wn   = (warp >> 1) * 32;

    const float* Ab = A + (size_t)(by * 128) * K;
    const float* Wb = W + bx * 128;

    float acc[4][4][4];
#pragma unroll
    for (int mi = 0; mi < 4; mi++)
#pragma unroll
        for (int nj = 0; nj < 4; nj++)
#pragma unroll
            for (int c = 0; c < 4; c++) acc[mi][nj][c] = 0.f;

    const uint32_t* Ac0 = (const uint32_t*)(AsB);
    const uint32_t* Ac1 = (const uint32_t*)(AsB + ASZ);
    const uint32_t* Ac2 = (const uint32_t*)(AsB + 2 * ASZ);
    const uint32_t* Bc0 = (const uint32_t*)(BsB);
    const uint32_t* Bc1 = (const uint32_t*)(BsB + BSZ);
    const uint32_t* Bc2 = (const uint32_t*)(BsB + 2 * BSZ);

    auto stage_to = [&](float* Ad, float* Bd, int kk) {
#pragma unroll
        for (int u = 0; u < 4; u++) {
            const int i   = tid + u * 256;
            const int row = i >> 3;
            const int c4  = (i & 7) * 4;
            cp_async16(Ad + row * 36 + c4, Ab + (size_t)row * K + kk + c4);
        }
#pragma unroll
        for (int u = 0; u < 4; u++) {
            const int i   = tid + u * 256;
            const int row = i >> 5;
            const int c4  = (i & 31) * 4;
            cp_async16(Bd + row * 136 + c4, Wb + (size_t)(kk + row) * N + c4);
        }
        cp_commit();
    };

    const int nT = K >> 5;
    stage_to((float*)Ac0, (float*)Bc0, 0);
    if (nT > 1) stage_to((float*)Ac1, (float*)Bc1, 32);

    for (int tt = 0; tt < nT; tt++) {
        if (tt + 1 < nT) asm volatile("cp.async.wait_group 1;\n" ::: "memory");
        else             asm volatile("cp.async.wait_group 0;\n" ::: "memory");
        __syncthreads();
        if (tt + 2 < nT) stage_to((float*)Ac2, (float*)Bc2, (tt + 2) * 32);

#pragma unroll
        for (int ks = 0; ks < 4; ks++) {
            const int kb = ks * 8;
            uint32_t a[4][4], b[4][2];
#pragma unroll
            for (int mi = 0; mi < 4; mi++) {
                const int m0 = wm + mi * 16;
                a[mi][0] = Ac0[(m0 + g)     * 36 + kb + t];
                a[mi][1] = Ac0[(m0 + 8 + g) * 36 + kb + t];
                a[mi][2] = Ac0[(m0 + g)     * 36 + kb + 4 + t];
                a[mi][3] = Ac0[(m0 + 8 + g) * 36 + kb + 4 + t];
            }
#pragma unroll
            for (int nj = 0; nj < 4; nj++) {
                const int n0 = wn + nj * 8;
                b[nj][0] = Bc0[(kb + t)     * 136 + n0 + g];
                b[nj][1] = Bc0[(kb + 4 + t) * 136 + n0 + g];
            }
#pragma unroll
            for (int mi = 0; mi < 4; mi++)
#pragma unroll
                for (int nj = 0; nj < 4; nj++)
                    mma_tf32(acc[mi][nj], a[mi], b[nj]);
        }

        const uint32_t* ta = Ac0; Ac0 = Ac1; Ac1 = Ac2; Ac2 = ta;
        const uint32_t* tb = Bc0; Bc0 = Bc1; Bc1 = Bc2; Bc2 = tb;
    }

    float lsum = 0.f, lsq = 0.f;
#pragma unroll
    for (int mi = 0; mi < 4; mi++) {
#pragma unroll
        for (int nj = 0; nj < 4; nj++) {
            const int row = by * 128 + wm + mi * 16 + g;
            const int col = bx * 128 + wn + nj * 8 + t * 2;
#pragma unroll
            for (int half = 0; half < 2; half++) {
                const int r = row + half * 8;
                float v0 = acc[mi][nj][half * 2 + 0] + bias[col];
                float v1 = acc[mi][nj][half * 2 + 1] + bias[col + 1];
                if (EPI == 1) {
                    v0 = 0.5f * v0 * (1.0f + erff(v0 * 0.70710678118654752f));
                    v1 = 0.5f * v1 * (1.0f + erff(v1 * 0.70710678118654752f));
                    v0 = __uint_as_float(f2tf32(v0));
                    v1 = __uint_as_float(f2tf32(v1));
                } else if (EPI == 2) {
                    v0 += res[(size_t)r * N + col];
                    v1 += res[(size_t)r * N + col + 1];
                    lsum += v0 + v1;
                    lsq  += v0 * v0 + v1 * v1;
                } else if (EPI == 3) {
                    v0 = __uint_as_float(f2tf32(v0 * oscale));
                    v1 = __uint_as_float(f2tf32(v1 * oscale));
                }
                float2 out = make_float2(v0, v1);
                *(float2*)(C + (size_t)r * N + col) = out;
            }
        }
    }

    if (EPI == 2) {
        // LN partial sums for this CTA's 128x128 tile (deterministic per-slot)
        __syncthreads();
        float* r1 = sm;
        float* r2 = sm + 256;
        r1[tid] = lsum; r2[tid] = lsq;
        __syncthreads();
        for (int st = 128; st > 0; st >>= 1) {
            if (tid < st) { r1[tid] += r1[tid + st]; r2[tid] += r2[tid + st]; }
            __syncthreads();
        }
        if (tid == 0) {
            const int b    = by >> 3;                 // 8 M-tiles per batch
            const int slot = (by & 7) * 8 + bx;       // 64 slots per batch
            part2[b * 64 + slot]          = r1[0];
            part2[B * 64 + b * 64 + slot] = r2[0];
        }
    }
}

// Fused QKV: blockIdx.z selects {q,k,v}; outputs tf32-rounded (q pre-scaled)
__global__ void __launch_bounds__(256, 2)
gemm_qkv(const float* __restrict__ x,
         const float* __restrict__ wq, const float* __restrict__ bq,
         const float* __restrict__ wk, const float* __restrict__ bk,
         const float* __restrict__ wv, const float* __restrict__ bv,
         float* __restrict__ q, float* __restrict__ k, float* __restrict__ v)
{
    extern __shared__ float sm[];
    const float* W; const float* bias; float* C; float osc;
    if (blockIdx.z == 0)      { W = wq; bias = bq; C = q; osc = 0.125f; }
    else if (blockIdx.z == 1) { W = wk; bias = bk; C = k; osc = 1.0f; }
    else                      { W = wv; bias = bv; C = v; osc = 1.0f; }
    gemm_body<3>(x, W, bias, nullptr, C, D, D, blockIdx.x, blockIdx.y, sm, osc, nullptr);
}

template <int EPI>
__global__ void __launch_bounds__(256, 2)
gemm_pipe(const float* __restrict__ A, const float* __restrict__ W,
          const float* __restrict__ bias, const float* __restrict__ res,
          float* __restrict__ C, int K, int N, float* __restrict__ part2)
{
    extern __shared__ float sm[];
    gemm_body<EPI>(A, W, bias, res, C, K, N, blockIdx.x, blockIdx.y, sm, 1.0f, part2);
}

// ---------------------------------------------------------------------------
// Flash attention: K-tile 64, cp.async double-buffered K/V, zero in-kernel cvt
// (q/k/v are pre-rounded; q pre-scaled by 1/8 in the QKV epilogue).
// One block per (b, h, 128-row q tile). 256 threads, 8 warps x 16 q rows.
// ---------------------------------------------------------------------------
constexpr int PS_STRIDE = 68;   // Q/P: 128 x 64 (+4 pad)
constexpr int KS_STRIDE = 68;   // K:    64 x 64 (+4 pad), x2 buffers
constexpr int VS_STRIDE = 72;   // V:    64 x 64 (+8 pad), x2 buffers
constexpr int ATTN_SMEM =
    (128 * PS_STRIDE + 2 * 64 * KS_STRIDE + 2 * 64 * VS_STRIDE) * 4;  // 106,496 B

__global__ void __launch_bounds__(256, 2)
flash_attn(const float* __restrict__ Q, const float* __restrict__ Kg,
           const float* __restrict__ Vg, float* __restrict__ O)
{
    extern __shared__ uint32_t smem[];
    uint32_t* Ps = smem;                              // [128][68]
    uint32_t* Kb = Ps + 128 * PS_STRIDE;              // 2 x [64][68]
    uint32_t* Vb = Kb + 2 * 64 * KS_STRIDE;           // 2 x [64][72]

    const int tid  = threadIdx.x;
    const int lane = tid & 31;
    const int warp = tid >> 5;
    const int g    = lane >> 2;
    const int t    = lane & 3;
    const int m0   = warp * 16;

    const int q0 = blockIdx.x * 128;
    const int h  = blockIdx.y;
    const int b  = blockIdx.z;

    const float* Qb  = Q  + (size_t)b * S * D + h * DK;
    const float* Kgb = Kg + (size_t)b * S * D + h * DK;
    const float* Vgb = Vg + (size_t)b * S * D + h * DK;

    // ---- stage Q tile via cp.async (group 1)
#pragma unroll
    for (int u = 0; u < 8; u++) {
        const int idx = u * 256 + tid;
        const int row = idx >> 4;
        const int c4  = (idx & 15) * 4;
        cp_async16(Ps + row * PS_STRIDE + c4, Qb + (size_t)(q0 + row) * D + c4);
    }
    cp_commit();

    auto stageKV = [&](int buf, int k0) {
        uint32_t* Kd = Kb + buf * 64 * KS_STRIDE;
        uint32_t* Vd = Vb + buf * 64 * VS_STRIDE;
#pragma unroll
        for (int u = 0; u < 4; u++) {
            const int idx = u * 256 + tid;
            const int row = idx >> 4;
            const int c4  = (idx & 15) * 4;
            cp_async16(Kd + row * KS_STRIDE + c4, Kgb + (size_t)(k0 + row) * D + c4);
            cp_async16(Vd + row * VS_STRIDE + c4, Vgb + (size_t)(k0 + row) * D + c4);
        }
        cp_commit();
    };

    stageKV(0, 0);                       // group 2

    // wait for Q (leave KV0 possibly pending), load Q fragments
    asm volatile("cp.async.wait_group 1;\n" ::: "memory");
    __syncthreads();
    uint32_t qf[8][4];
#pragma unroll
    for (int kc = 0; kc < 8; kc++) {
        const int kb = kc * 8;
        qf[kc][0] = Ps[(m0 + g)     * PS_STRIDE + kb + t];
        qf[kc][1] = Ps[(m0 + 8 + g) * PS_STRIDE + kb + t];
        qf[kc][2] = Ps[(m0 + g)     * PS_STRIDE + kb + 4 + t];
        qf[kc][3] = Ps[(m0 + 8 + g) * PS_STRIDE + kb + 4 + t];
    }

    float o[8][4];
#pragma unroll
    for (int j = 0; j < 8; j++)
#pragma unroll
        for (int c = 0; c < 4; c++) o[j][c] = 0.f;
    float mrun0 = -1e30f, mrun1 = -1e30f, lrun0 = 0.f, lrun1 = 0.f;

    constexpr int NIT = S / 64;          // 16
    for (int it = 0; it < NIT; it++) {
        const int buf = it & 1;
        __syncthreads();                 // prev iter done reading buf^1
        if (it + 1 < NIT) stageKV(buf ^ 1, (it + 1) * 64);
        if (it + 1 < NIT) asm volatile("cp.async.wait_group 1;\n" ::: "memory");
        else              asm volatile("cp.async.wait_group 0;\n" ::: "memory");
        __syncthreads();                 // buf data visible

        const uint32_t* Ks = Kb + buf * 64 * KS_STRIDE;
        const uint32_t* Vs = Vb + buf * 64 * VS_STRIDE;

        // ---- S = Q K^T
        float sc[8][4];
#pragma unroll
        for (int j = 0; j < 8; j++) {
            sc[j][0] = 0.f; sc[j][1] = 0.f; sc[j][2] = 0.f; sc[j][3] = 0.f;
            const int n0 = j * 8;
#pragma unroll
            for (int kc = 0; kc < 8; kc++) {
                const int kb = kc * 8;
                uint32_t bf[2];
                bf[0] = Ks[(n0 + g) * KS_STRIDE + kb + t];
                bf[1] = Ks[(n0 + g) * KS_STRIDE + kb + 4 + t];
                mma_tf32(sc[j], qf[kc], bf);
            }
        }

        // ---- online softmax
        float nm0 = -1e30f, nm1 = -1e30f;
#pragma unroll
        for (int j = 0; j < 8; j++) {
            nm0 = fmaxf(nm0, fmaxf(sc[j][0], sc[j][1]));
            nm1 = fmaxf(nm1, fmaxf(sc[j][2], sc[j][3]));
        }
        nm0 = fmaxf(nm0, __shfl_xor_sync(0xffffffffu, nm0, 1));
        nm0 = fmaxf(nm0, __shfl_xor_sync(0xffffffffu, nm0, 2));
        nm1 = fmaxf(nm1, __shfl_xor_sync(0xffffffffu, nm1, 1));
        nm1 = fmaxf(nm1, __shfl_xor_sync(0xffffffffu, nm1, 2));
        const float newm0 = fmaxf(mrun0, nm0);
        const float newm1 = fmaxf(mrun1, nm1);
        const float f0 = __expf(mrun0 - newm0);
        const float f1 = __expf(mrun1 - newm1);

        float s0 = 0.f, s1 = 0.f;
#pragma unroll
        for (int j = 0; j < 8; j++) {
            const float p00 = __expf(sc[j][0] - newm0);
            const float p01 = __expf(sc[j][1] - newm0);
            const float p10 = __expf(sc[j][2] - newm1);
            const float p11 = __expf(sc[j][3] - newm1);
            s0 += p00 + p01;
            s1 += p10 + p11;
            uint2 w0 = make_uint2(f2tf32(p00), f2tf32(p01));
            uint2 w1 = make_uint2(f2tf32(p10), f2tf32(p11));
            *(uint2*)&Ps[(m0 + g)     * PS_STRIDE + j * 8 + 2 * t] = w0;
            *(uint2*)&Ps[(m0 + 8 + g) * PS_STRIDE + j * 8 + 2 * t] = w1;
        }
        s0 += __shfl_xor_sync(0xffffffffu, s0, 1);
        s0 += __shfl_xor_sync(0xffffffffu, s0, 2);
        s1 += __shfl_xor_sync(0xffffffffu, s1, 1);
        s1 += __shfl_xor_sync(0xffffffffu, s1, 2);
        lrun0 = lrun0 * f0 + s0;
        lrun1 = lrun1 * f1 + s1;
        mrun0 = newm0;
        mrun1 = newm1;
#pragma unroll
        for (int j = 0; j < 8; j++) {
            o[j][0] *= f0; o[j][1] *= f0;
            o[j][2] *= f1; o[j][3] *= f1;
        }
        __syncwarp();   // P writes visible within warp

        // ---- O += P V
#pragma unroll
        for (int kc = 0; kc < 8; kc++) {
            const int kb = kc * 8;
            uint32_t a[4];
            a[0] = Ps[(m0 + g)     * PS_STRIDE + kb + t];
            a[1] = Ps[(m0 + 8 + g) * PS_STRIDE + kb + t];
            a[2] = Ps[(m0 + g)     * PS_STRIDE + kb + 4 + t];
            a[3] = Ps[(m0 + 8 + g) * PS_STRIDE + kb + 4 + t];
#pragma unroll
            for (int j = 0; j < 8; j++) {
                uint32_t bf[2];
                bf[0] = Vs[(kb + t)     * VS_STRIDE + j * 8 + g];
                bf[1] = Vs[(kb + 4 + t) * VS_STRIDE + j * 8 + g];
                mma_tf32(o[j], a, bf);
            }
        }
    }

    const float inv0 = 1.0f / lrun0;
    const float inv1 = 1.0f / lrun1;
    const int row0 = q0 + m0 + g;
    const int row1 = row0 + 8;
#pragma unroll
    for (int j = 0; j < 8; j++) {
        const int col = h * DK + j * 8 + 2 * t;
        float2 r0 = make_float2(o[j][0] * inv0, o[j][1] * inv0);
        float2 r1 = make_float2(o[j][2] * inv1, o[j][3] * inv1);
        *(float2*)(O + (size_t)(b * S + row0) * D + col) = r0;
        *(float2*)(O + (size_t)(b * S + row1) * D + col) = r1;
    }
}

// ---------------------------------------------------------------------------
// LayerNorm over (S,D) per batch
// ---------------------------------------------------------------------------
__global__ void __launch_bounds__(256)
ln_partial(const float* __restrict__ a, const float* __restrict__ c,
           float* __restrict__ y, float* __restrict__ part)
{
    const int b = blockIdx.y, chunk = blockIdx.x, tid = threadIdx.x;
    const size_t base = (size_t)b * S * D + (size_t)chunk * 4096 + tid * 16;
    float s = 0.f, s2 = 0.f;
#pragma unroll
    for (int i = 0; i < 16; i += 4) {
        float4 va = *(const float4*)(a + base + i);
        if (c) {
            float4 vc = *(const float4*)(c + base + i);
            va.x += vc.x; va.y += vc.y; va.z += vc.z; va.w += vc.w;
        }
        if (y) *(float4*)(y + base + i) = va;
        s  += va.x + va.y + va.z + va.w;
        s2 += va.x * va.x + va.y * va.y + va.z * va.z + va.w * va.w;
    }
    __shared__ float r1[256], r2[256];
    r1[tid] = s; r2[tid] = s2; __syncthreads();
    for (int st = 128; st > 0; st >>= 1) {
        if (tid < st) { r1[tid] += r1[tid + st]; r2[tid] += r2[tid + st]; }
        __syncthreads();
    }
    if (tid == 0) {
        part[b * 256 + chunk]            = r1[0];
        part[B * 256 + b * 256 + chunk]  = r2[0];
    }
}

// finalize from NCHUNK partials per batch
template <int NCHUNK>
__global__ void __launch_bounds__(256)
ln_finalize(const float* __restrict__ part, float* __restrict__ stats)
{
    const int b = blockIdx.x, tid = threadIdx.x;
    __shared__ float r1[256], r2[256];
    r1[tid] = tid < NCHUNK ? part[b * NCHUNK + tid] : 0.f;
    r2[tid] = tid < NCHUNK ? part[B * NCHUNK + b * NCHUNK + tid] : 0.f;
    __syncthreads();
    for (int st = 128; st > 0; st >>= 1) {
        if (tid < st) { r1[tid] += r1[tid + st]; r2[tid] += r2[tid + st]; }
        __syncthreads();
    }
    if (tid == 0) {
        const float n = (float)S * (float)D;
        float mean = r1[0] / n;
        float var  = r2[0] / n - mean * mean;
        stats[2 * b]     = mean;
        stats[2 * b + 1] = rsqrtf(var + EPS);
    }
}

__global__ void __launch_bounds__(256)
ln_apply(const float* __restrict__ y, const float* __restrict__ g,
         const float* __restrict__ beta, const float* __restrict__ stats,
         float* __restrict__ out, float* __restrict__ out_r)
{
    const int b = blockIdx.y;
    const int idx = (blockIdx.x * 256 + threadIdx.x) * 4;
    const float mean = stats[2 * b];
    const float rstd = stats[2 * b + 1];
    const size_t off = (size_t)b * S * D + idx;
    float4 v  = *(const float4*)(y + off);
    float4 gg = *(const float4*)(g + idx);
    float4 bb = *(const float4*)(beta + idx);
    v.x = (v.x - mean) * rstd * gg.x + bb.x;
    v.y = (v.y - mean) * rstd * gg.y + bb.y;
    v.z = (v.z - mean) * rstd * gg.z + bb.z;
    v.w = (v.w - mean) * rstd * gg.w + bb.w;
    *(float4*)(out + off) = v;
    if (out_r) {
        float4 r;
        r.x = __uint_as_float(f2tf32(v.x));
        r.y = __uint_as_float(f2tf32(v.y));
        r.z = __uint_as_float(f2tf32(v.z));
        r.w = __uint_as_float(f2tf32(v.w));
        *(float4*)(out_r + off) = r;
    }
}

// ---------------------------------------------------------------------------
// kernel_launch
// ---------------------------------------------------------------------------
extern "C" void kernel_launch(void* const* d_in, const int* in_sizes, int n_in,
                              void* d_out, int out_size)
{
    const float* x    = (const float*)d_in[0];
    const float* wq   = (const float*)d_in[1];
    const float* bq   = (const float*)d_in[2];
    const float* wk   = (const float*)d_in[3];
    const float* bk   = (const float*)d_in[4];
    const float* wv   = (const float*)d_in[5];
    const float* bv   = (const float*)d_in[6];
    const float* ln1g = (const float*)d_in[7];
    const float* ln1b = (const float*)d_in[8];
    const float* w1   = (const float*)d_in[9];
    const float* b1   = (const float*)d_in[10];
    const float* w2   = (const float*)d_in[11];
    const float* b2   = (const float*)d_in[12];
    const float* ln2g = (const float*)d_in[13];
    const float* ln2b = (const float*)d_in[14];
    float* out = (float*)d_out;

    float *q, *k, *v, *ctx, *h, *ff, *part, *stats;
    float *xr, *hr, *wqr, *wkr, *wvr, *w1r, *w2r;
    cudaGetSymbolAddress((void**)&q,     g_q);
    cudaGetSymbolAddress((void**)&k,     g_k);
    cudaGetSymbolAddress((void**)&v,     g_v);
    cudaGetSymbolAddress((void**)&ctx,   g_ctx);
    cudaGetSymbolAddress((void**)&h,     g_h);
    cudaGetSymbolAddress((void**)&ff,    g_ff);
    cudaGetSymbolAddress((void**)&part,  g_part);
    cudaGetSymbolAddress((void**)&stats, g_stats);
    cudaGetSymbolAddress((void**)&xr,    g_xr);
    cudaGetSymbolAddress((void**)&hr,    g_hr);
    cudaGetSymbolAddress((void**)&wqr,   g_wqr);
    cudaGetSymbolAddress((void**)&wkr,   g_wkr);
    cudaGetSymbolAddress((void**)&wvr,   g_wvr);
    cudaGetSymbolAddress((void**)&w1r,   g_w1r);
    cudaGetSymbolAddress((void**)&w2r,   g_w2r);

    static bool attr_done = false;
    if (!attr_done) {
        cudaFuncSetAttribute(flash_attn,
                             cudaFuncAttributeMaxDynamicSharedMemorySize, ATTN_SMEM);
        cudaFuncSetAttribute(gemm_qkv,
                             cudaFuncAttributeMaxDynamicSharedMemorySize, GEMM_SMEM);
        cudaFuncSetAttribute(gemm_pipe<1>,
                             cudaFuncAttributeMaxDynamicSharedMemorySize, GEMM_SMEM);
        cudaFuncSetAttribute(gemm_pipe<2>,
                             cudaFuncAttributeMaxDynamicSharedMemorySize, GEMM_SMEM);
        attr_done = true;
    }

    // tf32 pre-rounding: ONE launch
    round_all<<<(N_ALL + 255) / 256, 256>>>(x, xr, wq, wqr, wk, wkr,
                                            wv, wvr, w1, w1r, w2, w2r);

    // QKV projections (outputs tf32-rounded; q pre-scaled by 1/8)
    gemm_qkv<<<dim3(D / 128, NT / 128, 3), 256, GEMM_SMEM>>>(
        xr, wqr, bq, wkr, bk, wvr, bv, q, k, v);

    // Flash attention (cp.async double-buffered K/V)
    flash_attn<<<dim3(S / 128, H, B), 256, ATTN_SMEM>>>(q, k, v, ctx);

    // LayerNorm 1: h = LN(x + ctx) (+ rounded copy hr)
    ln_partial<<<dim3(256, B), 256>>>(x, ctx, h, part);
    ln_finalize<256><<<B, 256>>>(part, stats);
    ln_apply<<<dim3(1024, B), 256>>>(h, ln1g, ln1b, stats, h, hr);

    // FFN: ff = round(gelu(hr @ w1r + b1)); ctx = ff @ w2r + b2 + h (+LN2 partials)
    gemm_pipe<1><<<dim3(DFF / 128, NT / 128), 256, GEMM_SMEM>>>(
        hr, w1r, b1, nullptr, ff, D, DFF, nullptr);
    gemm_pipe<2><<<dim3(D / 128, NT / 128), 256, GEMM_SMEM>>>(
        ff, w2r, b2, h, ctx, DFF, D, part);

    // LayerNorm 2 -> output (partials already computed by FFN2 epilogue)
    ln_finalize<64><<<B, 256>>>(part, stats);
    ln_apply<<<dim3(1024, B), 256>>>(ctx, ln2g, ln2b, stats, out, nullptr);
}

// round 14
// speedup vs baseline: 1.7575x; 1.0054x over previous
#include <cuda_runtime.h>
#include <math.h>
#include <stdint.h>

// Problem constants
constexpr int B   = 8;
constexpr int S   = 1024;
constexpr int D   = 1024;
constexpr int H   = 16;
constexpr int DK  = 64;
constexpr int DFF = 4096;
constexpr int NT  = B * S;          // 8192 rows
constexpr float EPS = 1e-5f;

// ---------------------------------------------------------------------------
// Scratch (static __device__ arrays — no runtime allocation)
// ---------------------------------------------------------------------------
__device__ float g_q  [NT * D];
__device__ float g_k  [NT * D];
__device__ float g_v  [NT * D];
__device__ float g_ctx[NT * D];
__device__ float g_h  [NT * D];
__device__ float g_ff [(size_t)NT * DFF];
__device__ float g_part[2 * B * 256];
__device__ float g_stats[2 * B];
// tf32-pre-rounded operand copies
__device__ float g_xr [NT * D];
__device__ float g_hr [NT * D];
__device__ float g_wqr[D * D];
__device__ float g_wkr[D * D];
__device__ float g_wvr[D * D];
__device__ float g_w1r[D * DFF];
__device__ float g_w2r[DFF * D];

// ---------------------------------------------------------------------------
// tf32 / async helpers
// ---------------------------------------------------------------------------
__device__ __forceinline__ uint32_t f2tf32(float x) {
    uint32_t r;
    asm("cvt.rna.tf32.f32 %0, %1;" : "=r"(r) : "f"(x));
    return r;
}

__device__ __forceinline__ void mma_tf32(float c[4], const uint32_t a[4], const uint32_t b[2]) {
    asm volatile(
        "mma.sync.aligned.m16n8k8.row.col.f32.tf32.tf32.f32 "
        "{%0,%1,%2,%3}, {%4,%5,%6,%7}, {%8,%9}, {%0,%1,%2,%3};\n"
        : "+f"(c[0]), "+f"(c[1]), "+f"(c[2]), "+f"(c[3])
        : "r"(a[0]), "r"(a[1]), "r"(a[2]), "r"(a[3]), "r"(b[0]), "r"(b[1]));
}

__device__ __forceinline__ void cp_async16(void* smem_ptr, const void* gptr) {
    uint32_t sa = (uint32_t)__cvta_generic_to_shared(smem_ptr);
    asm volatile("cp.async.cg.shared.global [%0], [%1], 16;\n" :: "r"(sa), "l"(gptr));
}
__device__ __forceinline__ void cp_commit() {
    asm volatile("cp.async.commit_group;\n");
}

// ---------------------------------------------------------------------------
// Prepass: all tf32 rounding in ONE kernel (flat segment dispatch)
// ---------------------------------------------------------------------------
constexpr int N_X = NT * D / 4;
constexpr int N_W = D * D / 4;
constexpr int N_F = D * DFF / 4;
constexpr int N_ALL = N_X + 3 * N_W + 2 * N_F;

__global__ void __launch_bounds__(256)
round_all(const float* __restrict__ x,  float* __restrict__ xr,
          const float* __restrict__ wq, float* __restrict__ wqr,
          const float* __restrict__ wk, float* __restrict__ wkr,
          const float* __restrict__ wv, float* __restrict__ wvr,
          const float* __restrict__ w1, float* __restrict__ w1r,
          const float* __restrict__ w2, float* __restrict__ w2r)
{
    int i = blockIdx.x * 256 + threadIdx.x;
    if (i >= N_ALL) return;
    const float* in; float* out; int j;
    if (i < N_X)                    { in = x;  out = xr;  j = i; }
    else if (i < N_X + N_W)         { in = wq; out = wqr; j = i - N_X; }
    else if (i < N_X + 2 * N_W)     { in = wk; out = wkr; j = i - N_X - N_W; }
    else if (i < N_X + 3 * N_W)     { in = wv; out = wvr; j = i - N_X - 2 * N_W; }
    else if (i < N_X + 3 * N_W + N_F) { in = w1; out = w1r; j = i - N_X - 3 * N_W; }
    else                            { in = w2; out = w2r; j = i - N_X - 3 * N_W - N_F; }
    float4 v = ((const float4*)in)[j];
    v.x = __uint_as_float(f2tf32(v.x));
    v.y = __uint_as_float(f2tf32(v.y));
    v.z = __uint_as_float(f2tf32(v.z));
    v.w = __uint_as_float(f2tf32(v.w));
    ((float4*)out)[j] = v;
}

// ---------------------------------------------------------------------------
// Pipelined TF32 GEMM (round-10 best layout).
// EPI: 0 = bias, 1 = bias+GeLU+round, 2 = bias+residual (+LN partial sums),
//      3 = (bias + out)*oscale then tf32-round  (QKV outputs for attention)
// ---------------------------------------------------------------------------
constexpr int ASZ = 128 * 36;
constexpr int BSZ = 32 * 136;
constexpr int GEMM_SMEM = 3 * (ASZ + BSZ) * 4;   // 107,520 B

template <int EPI>
__device__ __forceinline__ void gemm_body(
    const float* __restrict__ A, const float* __restrict__ W,
    const float* __restrict__ bias, const float* __restrict__ res,
    float* __restrict__ C, int K, int N, int bx, int by, float* sm,
    float oscale, float* __restrict__ part2)
{
    float* AsB = sm;
    float* BsB = sm + 3 * ASZ;

    const int tid  = threadIdx.x;
    const int lane = tid & 31;
    const int warp = tid >> 5;
    const int g    = lane >> 2;
    const int t    = lane & 3;
    const int wm   = (warp & 1) * 64;
    const int wn   = (warp >> 1) * 32;

    const float* Ab = A + (size_t)(by * 128) * K;
    const float* Wb = W + bx * 128;

    float acc[4][4][4];
#pragma unroll
    for (int mi = 0; mi < 4; mi++)
#pragma unroll
        for (int nj = 0; nj < 4; nj++)
#pragma unroll
            for (int c = 0; c < 4; c++) acc[mi][nj][c] = 0.f;

    const uint32_t* Ac0 = (const uint32_t*)(AsB);
    const uint32_t* Ac1 = (const uint32_t*)(AsB + ASZ);
    const uint32_t* Ac2 = (const uint32_t*)(AsB + 2 * ASZ);
    const uint32_t* Bc0 = (const uint32_t*)(BsB);
    const uint32_t* Bc1 = (const uint32_t*)(BsB + BSZ);
    const uint32_t* Bc2 = (const uint32_t*)(BsB + 2 * BSZ);

    auto stage_to = [&](float* Ad, float* Bd, int kk) {
#pragma unroll
        for (int u = 0; u < 4; u++) {
            const int i   = tid + u * 256;
            const int row = i >> 3;
            const int c4  = (i & 7) * 4;
            cp_async16(Ad + row * 36 + c4, Ab + (size_t)row * K + kk + c4);
        }
#pragma unroll
        for (int u = 0; u < 4; u++) {
            const int i   = tid + u * 256;
            const int row = i >> 5;
            const int c4  = (i & 31) * 4;
            cp_async16(Bd + row * 136 + c4, Wb + (size_t)(kk + row) * N + c4);
        }
        cp_commit();
    };

    const int nT = K >> 5;
    stage_to((float*)Ac0, (float*)Bc0, 0);
    if (nT > 1) stage_to((float*)Ac1, (float*)Bc1, 32);

    for (int tt = 0; tt < nT; tt++) {
        if (tt + 1 < nT) asm volatile("cp.async.wait_group 1;\n" ::: "memory");
        else             asm volatile("cp.async.wait_group 0;\n" ::: "memory");
        __syncthreads();
        if (tt + 2 < nT) stage_to((float*)Ac2, (float*)Bc2, (tt + 2) * 32);

#pragma unroll
        for (int ks = 0; ks < 4; ks++) {
            const int kb = ks * 8;
            uint32_t a[4][4], b[4][2];
#pragma unroll
            for (int mi = 0; mi < 4; mi++) {
                const int m0 = wm + mi * 16;
                a[mi][0] = Ac0[(m0 + g)     * 36 + kb + t];
                a[mi][1] = Ac0[(m0 + 8 + g) * 36 + kb + t];
                a[mi][2] = Ac0[(m0 + g)     * 36 + kb + 4 + t];
                a[mi][3] = Ac0[(m0 + 8 + g) * 36 + kb + 4 + t];
            }
#pragma unroll
            for (int nj = 0; nj < 4; nj++) {
                const int n0 = wn + nj * 8;
                b[nj][0] = Bc0[(kb + t)     * 136 + n0 + g];
                b[nj][1] = Bc0[(kb + 4 + t) * 136 + n0 + g];
            }
#pragma unroll
            for (int mi = 0; mi < 4; mi++)
#pragma unroll
                for (int nj = 0; nj < 4; nj++)
                    mma_tf32(acc[mi][nj], a[mi], b[nj]);
        }

        const uint32_t* ta = Ac0; Ac0 = Ac1; Ac1 = Ac2; Ac2 = ta;
        const uint32_t* tb = Bc0; Bc0 = Bc1; Bc1 = Bc2; Bc2 = tb;
    }

    float lsum = 0.f, lsq = 0.f;
#pragma unroll
    for (int mi = 0; mi < 4; mi++) {
#pragma unroll
        for (int nj = 0; nj < 4; nj++) {
            const int row = by * 128 + wm + mi * 16 + g;
            const int col = bx * 128 + wn + nj * 8 + t * 2;
#pragma unroll
            for (int half = 0; half < 2; half++) {
                const int r = row + half * 8;
                float v0 = acc[mi][nj][half * 2 + 0] + bias[col];
                float v1 = acc[mi][nj][half * 2 + 1] + bias[col + 1];
                if (EPI == 1) {
                    v0 = 0.5f * v0 * (1.0f + erff(v0 * 0.70710678118654752f));
                    v1 = 0.5f * v1 * (1.0f + erff(v1 * 0.70710678118654752f));
                    v0 = __uint_as_float(f2tf32(v0));
                    v1 = __uint_as_float(f2tf32(v1));
                } else if (EPI == 2) {
                    v0 += res[(size_t)r * N + col];
                    v1 += res[(size_t)r * N + col + 1];
                    lsum += v0 + v1;
                    lsq  += v0 * v0 + v1 * v1;
                } else if (EPI == 3) {
                    v0 = __uint_as_float(f2tf32(v0 * oscale));
                    v1 = __uint_as_float(f2tf32(v1 * oscale));
                }
                float2 out = make_float2(v0, v1);
                *(float2*)(C + (size_t)r * N + col) = out;
            }
        }
    }

    if (EPI == 2) {
        __syncthreads();
        float* r1 = sm;
        float* r2 = sm + 256;
        r1[tid] = lsum; r2[tid] = lsq;
        __syncthreads();
        for (int st = 128; st > 0; st >>= 1) {
            if (tid < st) { r1[tid] += r1[tid + st]; r2[tid] += r2[tid + st]; }
            __syncthreads();
        }
        if (tid == 0) {
            const int b    = by >> 3;
            const int slot = (by & 7) * 8 + bx;
            part2[b * 64 + slot]          = r1[0];
            part2[B * 64 + b * 64 + slot] = r2[0];
        }
    }
}

__global__ void __launch_bounds__(256, 2)
gemm_qkv(const float* __restrict__ x,
         const float* __restrict__ wq, const float* __restrict__ bq,
         const float* __restrict__ wk, const float* __restrict__ bk,
         const float* __restrict__ wv, const float* __restrict__ bv,
         float* __restrict__ q, float* __restrict__ k, float* __restrict__ v)
{
    extern __shared__ float sm[];
    const float* W; const float* bias; float* C; float osc;
    if (blockIdx.z == 0)      { W = wq; bias = bq; C = q; osc = 0.125f; }
    else if (blockIdx.z == 1) { W = wk; bias = bk; C = k; osc = 1.0f; }
    else                      { W = wv; bias = bv; C = v; osc = 1.0f; }
    gemm_body<3>(x, W, bias, nullptr, C, D, D, blockIdx.x, blockIdx.y, sm, osc, nullptr);
}

template <int EPI>
__global__ void __launch_bounds__(256, 2)
gemm_pipe(const float* __restrict__ A, const float* __restrict__ W,
          const float* __restrict__ bias, const float* __restrict__ res,
          float* __restrict__ C, int K, int N, float* __restrict__ part2)
{
    extern __shared__ float sm[];
    gemm_body<EPI>(A, W, bias, res, C, K, N, blockIdx.x, blockIdx.y, sm, 1.0f, part2);
}

// ---------------------------------------------------------------------------
// Flash attention: K-tile 64, cp.async double-buffered K/V.
// Epilogue fuses LN1 stage-1: hres = x + ctx stored directly, plus per-block
// partial (sum, sumsq) to slot [qtile*16 + head] (128 slots / batch).
// ---------------------------------------------------------------------------
constexpr int PS_STRIDE = 68;
constexpr int KS_STRIDE = 68;
constexpr int VS_STRIDE = 72;
constexpr int ATTN_SMEM =
    (128 * PS_STRIDE + 2 * 64 * KS_STRIDE + 2 * 64 * VS_STRIDE) * 4;  // 106,496 B

__global__ void __launch_bounds__(256, 2)
flash_attn(const float* __restrict__ Q, const float* __restrict__ Kg,
           const float* __restrict__ Vg, const float* __restrict__ X,
           float* __restrict__ hres, float* __restrict__ part)
{
    extern __shared__ uint32_t smem[];
    uint32_t* Ps = smem;
    uint32_t* Kb = Ps + 128 * PS_STRIDE;
    uint32_t* Vb = Kb + 2 * 64 * KS_STRIDE;

    const int tid  = threadIdx.x;
    const int lane = tid & 31;
    const int warp = tid >> 5;
    const int g    = lane >> 2;
    const int t    = lane & 3;
    const int m0   = warp * 16;

    const int q0 = blockIdx.x * 128;
    const int hh = blockIdx.y;
    const int b  = blockIdx.z;

    const float* Qb  = Q  + (size_t)b * S * D + hh * DK;
    const float* Kgb = Kg + (size_t)b * S * D + hh * DK;
    const float* Vgb = Vg + (size_t)b * S * D + hh * DK;

#pragma unroll
    for (int u = 0; u < 8; u++) {
        const int idx = u * 256 + tid;
        const int row = idx >> 4;
        const int c4  = (idx & 15) * 4;
        cp_async16(Ps + row * PS_STRIDE + c4, Qb + (size_t)(q0 + row) * D + c4);
    }
    cp_commit();

    auto stageKV = [&](int buf, int k0) {
        uint32_t* Kd = Kb + buf * 64 * KS_STRIDE;
        uint32_t* Vd = Vb + buf * 64 * VS_STRIDE;
#pragma unroll
        for (int u = 0; u < 4; u++) {
            const int idx = u * 256 + tid;
            const int row = idx >> 4;
            const int c4  = (idx & 15) * 4;
            cp_async16(Kd + row * KS_STRIDE + c4, Kgb + (size_t)(k0 + row) * D + c4);
            cp_async16(Vd + row * VS_STRIDE + c4, Vgb + (size_t)(k0 + row) * D + c4);
        }
        cp_commit();
    };

    stageKV(0, 0);

    asm volatile("cp.async.wait_group 1;\n" ::: "memory");
    __syncthreads();
    uint32_t qf[8][4];
#pragma unroll
    for (int kc = 0; kc < 8; kc++) {
        const int kb = kc * 8;
        qf[kc][0] = Ps[(m0 + g)     * PS_STRIDE + kb + t];
        qf[kc][1] = Ps[(m0 + 8 + g) * PS_STRIDE + kb + t];
        qf[kc][2] = Ps[(m0 + g)     * PS_STRIDE + kb + 4 + t];
        qf[kc][3] = Ps[(m0 + 8 + g) * PS_STRIDE + kb + 4 + t];
    }

    float o[8][4];
#pragma unroll
    for (int j = 0; j < 8; j++)
#pragma unroll
        for (int c = 0; c < 4; c++) o[j][c] = 0.f;
    float mrun0 = -1e30f, mrun1 = -1e30f, lrun0 = 0.f, lrun1 = 0.f;

    constexpr int NIT = S / 64;
    for (int it = 0; it < NIT; it++) {
        const int buf = it & 1;
        __syncthreads();
        if (it + 1 < NIT) stageKV(buf ^ 1, (it + 1) * 64);
        if (it + 1 < NIT) asm volatile("cp.async.wait_group 1;\n" ::: "memory");
        else              asm volatile("cp.async.wait_group 0;\n" ::: "memory");
        __syncthreads();

        const uint32_t* Ks = Kb + buf * 64 * KS_STRIDE;
        const uint32_t* Vs = Vb + buf * 64 * VS_STRIDE;

        float sc[8][4];
#pragma unroll
        for (int j = 0; j < 8; j++) {
            sc[j][0] = 0.f; sc[j][1] = 0.f; sc[j][2] = 0.f; sc[j][3] = 0.f;
            const int n0 = j * 8;
#pragma unroll
            for (int kc = 0; kc < 8; kc++) {
                const int kb = kc * 8;
                uint32_t bf[2];
                bf[0] = Ks[(n0 + g) * KS_STRIDE + kb + t];
                bf[1] = Ks[(n0 + g) * KS_STRIDE + kb + 4 + t];
                mma_tf32(sc[j], qf[kc], bf);
            }
        }

        float nm0 = -1e30f, nm1 = -1e30f;
#pragma unroll
        for (int j = 0; j < 8; j++) {
            nm0 = fmaxf(nm0, fmaxf(sc[j][0], sc[j][1]));
            nm1 = fmaxf(nm1, fmaxf(sc[j][2], sc[j][3]));
        }
        nm0 = fmaxf(nm0, __shfl_xor_sync(0xffffffffu, nm0, 1));
        nm0 = fmaxf(nm0, __shfl_xor_sync(0xffffffffu, nm0, 2));
        nm1 = fmaxf(nm1, __shfl_xor_sync(0xffffffffu, nm1, 1));
        nm1 = fmaxf(nm1, __shfl_xor_sync(0xffffffffu, nm1, 2));
        const float newm0 = fmaxf(mrun0, nm0);
        const float newm1 = fmaxf(mrun1, nm1);
        const float f0 = __expf(mrun0 - newm0);
        const float f1 = __expf(mrun1 - newm1);

        float s0 = 0.f, s1 = 0.f;
#pragma unroll
        for (int j = 0; j < 8; j++) {
            const float p00 = __expf(sc[j][0] - newm0);
            const float p01 = __expf(sc[j][1] - newm0);
            const float p10 = __expf(sc[j][2] - newm1);
            const float p11 = __expf(sc[j][3] - newm1);
            s0 += p00 + p01;
            s1 += p10 + p11;
            uint2 w0 = make_uint2(f2tf32(p00), f2tf32(p01));
            uint2 w1 = make_uint2(f2tf32(p10), f2tf32(p11));
            *(uint2*)&Ps[(m0 + g)     * PS_STRIDE + j * 8 + 2 * t] = w0;
            *(uint2*)&Ps[(m0 + 8 + g) * PS_STRIDE + j * 8 + 2 * t] = w1;
        }
        s0 += __shfl_xor_sync(0xffffffffu, s0, 1);
        s0 += __shfl_xor_sync(0xffffffffu, s0, 2);
        s1 += __shfl_xor_sync(0xffffffffu, s1, 1);
        s1 += __shfl_xor_sync(0xffffffffu, s1, 2);
        lrun0 = lrun0 * f0 + s0;
        lrun1 = lrun1 * f1 + s1;
        mrun0 = newm0;
        mrun1 = newm1;
#pragma unroll
        for (int j = 0; j < 8; j++) {
            o[j][0] *= f0; o[j][1] *= f0;
            o[j][2] *= f1; o[j][3] *= f1;
        }
        __syncwarp();

#pragma unroll
        for (int kc = 0; kc < 8; kc++) {
            const int kb = kc * 8;
            uint32_t a[4];
            a[0] = Ps[(m0 + g)     * PS_STRIDE + kb + t];
            a[1] = Ps[(m0 + 8 + g) * PS_STRIDE + kb + t];
            a[2] = Ps[(m0 + g)     * PS_STRIDE + kb + 4 + t];
            a[3] = Ps[(m0 + 8 + g) * PS_STRIDE + kb + 4 + t];
#pragma unroll
            for (int j = 0; j < 8; j++) {
                uint32_t bf[2];
                bf[0] = Vs[(kb + t)     * VS_STRIDE + j * 8 + g];
                bf[1] = Vs[(kb + 4 + t) * VS_STRIDE + j * 8 + g];
                mma_tf32(o[j], a, bf);
            }
        }
    }

    // ---- epilogue: hres = x + ctx, plus LN1 partial sums
    const float inv0 = 1.0f / lrun0;
    const float inv1 = 1.0f / lrun1;
    const int row0 = q0 + m0 + g;
    const int row1 = row0 + 8;
    float lsum = 0.f, lsq = 0.f;
#pragma unroll
    for (int j = 0; j < 8; j++) {
        const int col = hh * DK + j * 8 + 2 * t;
        float2 xv0 = *(const float2*)(X + (size_t)(b * S + row0) * D + col);
        float2 xv1 = *(const float2*)(X + (size_t)(b * S + row1) * D + col);
        float h00 = xv0.x + o[j][0] * inv0;
        float h01 = xv0.y + o[j][1] * inv0;
        float h10 = xv1.x + o[j][2] * inv1;
        float h11 = xv1.y + o[j][3] * inv1;
        lsum += h00 + h01 + h10 + h11;
        lsq  += h00 * h00 + h01 * h01 + h10 * h10 + h11 * h11;
        *(float2*)(hres + (size_t)(b * S + row0) * D + col) = make_float2(h00, h01);
        *(float2*)(hres + (size_t)(b * S + row1) * D + col) = make_float2(h10, h11);
    }

    __syncthreads();   // Ps free
    float* r1 = (float*)Ps;
    float* r2 = r1 + 256;
    r1[tid] = lsum; r2[tid] = lsq;
    __syncthreads();
    for (int st = 128; st > 0; st >>= 1) {
        if (tid < st) { r1[tid] += r1[tid + st]; r2[tid] += r2[tid + st]; }
        __syncthreads();
    }
    if (tid == 0) {
        const int slot = blockIdx.x * 16 + hh;        // 128 slots per batch
        part[b * 128 + slot]           = r1[0];
        part[B * 128 + b * 128 + slot] = r2[0];
    }
}

// ---------------------------------------------------------------------------
// LayerNorm finalize/apply
// ---------------------------------------------------------------------------
template <int NCHUNK>
__global__ void __launch_bounds__(256)
ln_finalize(const float* __restrict__ part, float* __restrict__ stats)
{
    const int b = blockIdx.x, tid = threadIdx.x;
    __shared__ float r1[256], r2[256];
    r1[tid] = tid < NCHUNK ? part[b * NCHUNK + tid] : 0.f;
    r2[tid] = tid < NCHUNK ? part[B * NCHUNK + b * NCHUNK + tid] : 0.f;
    __syncthreads();
    for (int st = 128; st > 0; st >>= 1) {
        if (tid < st) { r1[tid] += r1[tid + st]; r2[tid] += r2[tid + st]; }
        __syncthreads();
    }
    if (tid == 0) {
        const float n = (float)S * (float)D;
        float mean = r1[0] / n;
        float var  = r2[0] / n - mean * mean;
        stats[2 * b]     = mean;
        stats[2 * b + 1] = rsqrtf(var + EPS);
    }
}

__global__ void __launch_bounds__(256)
ln_apply(const float* __restrict__ y, const float* __restrict__ g,
         const float* __restrict__ beta, const float* __restrict__ stats,
         float* __restrict__ out, float* __restrict__ out_r)
{
    const int b = blockIdx.y;
    const int idx = (blockIdx.x * 256 + threadIdx.x) * 4;
    const float mean = stats[2 * b];
    const float rstd = stats[2 * b + 1];
    const size_t off = (size_t)b * S * D + idx;
    float4 v  = *(const float4*)(y + off);
    float4 gg = *(const float4*)(g + idx);
    float4 bb = *(const float4*)(beta + idx);
    v.x = (v.x - mean) * rstd * gg.x + bb.x;
    v.y = (v.y - mean) * rstd * gg.y + bb.y;
    v.z = (v.z - mean) * rstd * gg.z + bb.z;
    v.w = (v.w - mean) * rstd * gg.w + bb.w;
    *(float4*)(out + off) = v;
    if (out_r) {
        float4 r;
        r.x = __uint_as_float(f2tf32(v.x));
        r.y = __uint_as_float(f2tf32(v.y));
        r.z = __uint_as_float(f2tf32(v.z));
        r.w = __uint_as_float(f2tf32(v.w));
        *(float4*)(out_r + off) = r;
    }
}

// ---------------------------------------------------------------------------
// kernel_launch
// ---------------------------------------------------------------------------
extern "C" void kernel_launch(void* const* d_in, const int* in_sizes, int n_in,
                              void* d_out, int out_size)
{
    const float* x    = (const float*)d_in[0];
    const float* wq   = (const float*)d_in[1];
    const float* bq   = (const float*)d_in[2];
    const float* wk   = (const float*)d_in[3];
    const float* bk   = (const float*)d_in[4];
    const float* wv   = (const float*)d_in[5];
    const float* bv   = (const float*)d_in[6];
    const float* ln1g = (const float*)d_in[7];
    const float* ln1b = (const float*)d_in[8];
    const float* w1   = (const float*)d_in[9];
    const float* b1   = (const float*)d_in[10];
    const float* w2   = (const float*)d_in[11];
    const float* b2   = (const float*)d_in[12];
    const float* ln2g = (const float*)d_in[13];
    const float* ln2b = (const float*)d_in[14];
    float* out = (float*)d_out;

    float *q, *k, *v, *ctx, *h, *ff, *part, *stats;
    float *xr, *hr, *wqr, *wkr, *wvr, *w1r, *w2r;
    cudaGetSymbolAddress((void**)&q,     g_q);
    cudaGetSymbolAddress((void**)&k,     g_k);
    cudaGetSymbolAddress((void**)&v,     g_v);
    cudaGetSymbolAddress((void**)&ctx,   g_ctx);
    cudaGetSymbolAddress((void**)&h,     g_h);
    cudaGetSymbolAddress((void**)&ff,    g_ff);
    cudaGetSymbolAddress((void**)&part,  g_part);
    cudaGetSymbolAddress((void**)&stats, g_stats);
    cudaGetSymbolAddress((void**)&xr,    g_xr);
    cudaGetSymbolAddress((void**)&hr,    g_hr);
    cudaGetSymbolAddress((void**)&wqr,   g_wqr);
    cudaGetSymbolAddress((void**)&wkr,   g_wkr);
    cudaGetSymbolAddress((void**)&wvr,   g_wvr);
    cudaGetSymbolAddress((void**)&w1r,   g_w1r);
    cudaGetSymbolAddress((void**)&w2r,   g_w2r);

    static bool attr_done = false;
    if (!attr_done) {
        cudaFuncSetAttribute(flash_attn,
                             cudaFuncAttributeMaxDynamicSharedMemorySize, ATTN_SMEM);
        cudaFuncSetAttribute(gemm_qkv,
                             cudaFuncAttributeMaxDynamicSharedMemorySize, GEMM_SMEM);
        cudaFuncSetAttribute(gemm_pipe<1>,
                             cudaFuncAttributeMaxDynamicSharedMemorySize, GEMM_SMEM);
        cudaFuncSetAttribute(gemm_pipe<2>,
                             cudaFuncAttributeMaxDynamicSharedMemorySize, GEMM_SMEM);
        attr_done = true;
    }

    // tf32 pre-rounding: ONE launch
    round_all<<<(N_ALL + 255) / 256, 256>>>(x, xr, wq, wqr, wk, wkr,
                                            wv, wvr, w1, w1r, w2, w2r);

    // QKV projections (outputs tf32-rounded; q pre-scaled by 1/8)
    gemm_qkv<<<dim3(D / 128, NT / 128, 3), 256, GEMM_SMEM>>>(
        xr, wqr, bq, wkr, bk, wvr, bv, q, k, v);

    // Flash attention (+fused h = x + ctx and LN1 partial sums)
    flash_attn<<<dim3(S / 128, H, B), 256, ATTN_SMEM>>>(q, k, v, x, h, part);

    // LayerNorm 1 finalize + apply (h in-place, + rounded copy hr)
    ln_finalize<128><<<B, 256>>>(part, stats);
    ln_apply<<<dim3(1024, B), 256>>>(h, ln1g, ln1b, stats, h, hr);

    // FFN: ff = round(gelu(hr @ w1r + b1)); ctx = ff @ w2r + b2 + h (+LN2 partials)
    gemm_pipe<1><<<dim3(DFF / 128, NT / 128), 256, GEMM_SMEM>>>(
        hr, w1r, b1, nullptr, ff, D, DFF, nullptr);
    gemm_pipe<2><<<dim3(D / 128, NT / 128), 256, GEMM_SMEM>>>(
        ff, w2r, b2, h, ctx, DFF, D, part);

    // LayerNorm 2 -> output (partials from FFN2 epilogue)
    ln_finalize<64><<<B, 256>>>(part, stats);
    ln_apply<<<dim3(1024, B), 256>>>(ctx, ln2g, ln2b, stats, out, nullptr);
}

// round 15
// speedup vs baseline: 2.5090x; 1.4276x over previous
#include <cuda_runtime.h>
#include <cuda_fp16.h>
#include <math.h>
#include <stdint.h>

// Problem constants
constexpr int B   = 8;
constexpr int S   = 1024;
constexpr int D   = 1024;
constexpr int H   = 16;
constexpr int DK  = 64;
constexpr int DFF = 4096;
constexpr int NT  = B * S;          // 8192 rows
constexpr float EPS = 1e-5f;

// ---------------------------------------------------------------------------
// Scratch (static __device__ arrays — no runtime allocation)
// ---------------------------------------------------------------------------
__device__ float g_q  [NT * D];
__device__ float g_k  [NT * D];
__device__ float g_v  [NT * D];
__device__ float g_ctx[NT * D];
__device__ float g_h  [NT * D];
__device__ float g_part[2 * B * 256];
__device__ float g_stats[2 * B];
// fp16 operands
__device__ __half g_xh [NT * D];
__device__ __half g_hh [NT * D];
__device__ __half g_ffh[(size_t)NT * DFF];
__device__ __half g_wqt[D * D];            // Wt[n][k]
__device__ __half g_wkt[D * D];
__device__ __half g_wvt[D * D];
__device__ __half g_w1t[(size_t)DFF * D];  // [DFF][D]
__device__ __half g_w2t[(size_t)D * DFF];  // [D][DFF]

// ---------------------------------------------------------------------------
// helpers
// ---------------------------------------------------------------------------
__device__ __forceinline__ uint32_t f2tf32(float x) {
    uint32_t r;
    asm("cvt.rna.tf32.f32 %0, %1;" : "=r"(r) : "f"(x));
    return r;
}
__device__ __forceinline__ void mma_tf32(float c[4], const uint32_t a[4], const uint32_t b[2]) {
    asm volatile(
        "mma.sync.aligned.m16n8k8.row.col.f32.tf32.tf32.f32 "
        "{%0,%1,%2,%3}, {%4,%5,%6,%7}, {%8,%9}, {%0,%1,%2,%3};\n"
        : "+f"(c[0]), "+f"(c[1]), "+f"(c[2]), "+f"(c[3])
        : "r"(a[0]), "r"(a[1]), "r"(a[2]), "r"(a[3]), "r"(b[0]), "r"(b[1]));
}
__device__ __forceinline__ void mma_f16(float c[4], const uint32_t a[4], const uint32_t b[2]) {
    asm volatile(
        "mma.sync.aligned.m16n8k16.row.col.f32.f16.f16.f32 "
        "{%0,%1,%2,%3}, {%4,%5,%6,%7}, {%8,%9}, {%0,%1,%2,%3};\n"
        : "+f"(c[0]), "+f"(c[1]), "+f"(c[2]), "+f"(c[3])
        : "r"(a[0]), "r"(a[1]), "r"(a[2]), "r"(a[3]), "r"(b[0]), "r"(b[1]));
}
__device__ __forceinline__ void cp_async16(void* smem_ptr, const void* gptr) {
    uint32_t sa = (uint32_t)__cvta_generic_to_shared(smem_ptr);
    asm volatile("cp.async.cg.shared.global [%0], [%1], 16;\n" :: "r"(sa), "l"(gptr));
}
__device__ __forceinline__ void cp_commit() {
    asm volatile("cp.async.commit_group;\n");
}

// ---------------------------------------------------------------------------
// Prepass: x -> fp16 ; weights -> transposed fp16
// ---------------------------------------------------------------------------
__global__ void __launch_bounds__(256)
conv_x_f16(const float* __restrict__ in, __half* __restrict__ out, int n4)
{
    const int i = blockIdx.x * 256 + threadIdx.x;
    if (i < n4) {
        float4 v = ((const float4*)in)[i];
        __half2 h0 = __floats2half2_rn(v.x, v.y);
        __half2 h1 = __floats2half2_rn(v.z, v.w);
        uint2 o = make_uint2(*(uint32_t*)&h0, *(uint32_t*)&h1);
        ((uint2*)out)[i] = o;
    }
}

// out[c][r] = half(in[r][c]); in: [R][C] fp32. grid: (C/32, R/32 [,Z])
__global__ void __launch_bounds__(256)
transpose_f16(const float* __restrict__ in0, __half* __restrict__ out0,
              const float* __restrict__ in1, __half* __restrict__ out1,
              const float* __restrict__ in2, __half* __restrict__ out2,
              int R, int C)
{
    const float* in  = blockIdx.z == 0 ? in0  : (blockIdx.z == 1 ? in1  : in2);
    __half*      out = blockIdx.z == 0 ? out0 : (blockIdx.z == 1 ? out1 : out2);
    __shared__ float tile[32][33];
    const int c0 = blockIdx.x * 32, r0 = blockIdx.y * 32;
    const int tx = threadIdx.x, ty = threadIdx.y;   // 32 x 8
#pragma unroll
    for (int i = 0; i < 32; i += 8)
        tile[ty + i][tx] = in[(size_t)(r0 + ty + i) * C + c0 + tx];
    __syncthreads();
#pragma unroll
    for (int i = 0; i < 32; i += 8)
        out[(size_t)(c0 + ty + i) * R + r0 + tx] = __float2half_rn(tile[tx][ty + i]);
}

// ---------------------------------------------------------------------------
// FP16 tensor-core GEMM: C(128x128 tile) = A[M,K](f16) * Wt[n][k](f16)^T + bias
// 256 thr = 8 warps, warp tile 64x32 via m16n8k16, BK=32, 3-stage cp.async.
// Both smem tiles [128][40] halfs (stride 20 words -> banks 20g+t all distinct).
// EPI: 1 = bias+GeLU -> half out, 2 = bias+residual -> float out (+LN partials),
//      3 = (bias+acc)*oscale -> tf32-rounded float out (QKV)
// ---------------------------------------------------------------------------
constexpr int TSZH = 128 * 40;                       // halfs per tile
constexpr int GEMM_SMEM = 3 * 2 * TSZH * 2;          // 61,440 B

template <int EPI>
__device__ __forceinline__ void gemm_body(
    const __half* __restrict__ A, const __half* __restrict__ Wt,
    const float* __restrict__ bias, const float* __restrict__ res,
    void* __restrict__ Cv, int K, int N, int bx, int by, __half* sm,
    float oscale, float* __restrict__ part2)
{
    __half* AsB = sm;                 // 3 x [128][40]
    __half* BsB = sm + 3 * TSZH;      // 3 x [128][40]

    const int tid  = threadIdx.x;
    const int lane = tid & 31;
    const int warp = tid >> 5;
    const int g    = lane >> 2;
    const int t    = lane & 3;
    const int wm   = (warp & 1) * 64;
    const int wn   = (warp >> 1) * 32;

    const __half* Ab = A  + (size_t)(by * 128) * K;
    const __half* Wb = Wt + (size_t)(bx * 128) * K;

    float acc[4][4][4];
#pragma unroll
    for (int mi = 0; mi < 4; mi++)
#pragma unroll
        for (int nj = 0; nj < 4; nj++)
#pragma unroll
            for (int c = 0; c < 4; c++) acc[mi][nj][c] = 0.f;

    __half* A0 = AsB;              __half* A1 = AsB + TSZH; __half* A2 = AsB + 2 * TSZH;
    __half* B0 = BsB;              __half* B1 = BsB + TSZH; __half* B2 = BsB + 2 * TSZH;

    auto stage_to = [&](__half* Ad, __half* Bd, int kk) {
#pragma unroll
        for (int u = 0; u < 2; u++) {
            const int i   = tid + u * 256;
            const int row = i >> 2;
            const int c8  = (i & 3) * 8;
            cp_async16(Ad + row * 40 + c8, Ab + (size_t)row * K + kk + c8);
        }
#pragma unroll
        for (int u = 0; u < 2; u++) {
            const int i   = tid + u * 256;
            const int row = i >> 2;
            const int c8  = (i & 3) * 8;
            cp_async16(Bd + row * 40 + c8, Wb + (size_t)row * K + kk + c8);
        }
        cp_commit();
    };

    const int nT = K >> 5;
    stage_to(A0, B0, 0);
    if (nT > 1) stage_to(A1, B1, 32);

    for (int tt = 0; tt < nT; tt++) {
        if (tt + 1 < nT) asm volatile("cp.async.wait_group 1;\n" ::: "memory");
        else             asm volatile("cp.async.wait_group 0;\n" ::: "memory");
        __syncthreads();
        if (tt + 2 < nT) stage_to(A2, B2, (tt + 2) * 32);

        const uint32_t* Ac = (const uint32_t*)A0;
        const uint32_t* Bc = (const uint32_t*)B0;
#pragma unroll
        for (int ks = 0; ks < 2; ks++) {
            const int kb = ks * 8;              // word offset (16 halfs)
            uint32_t a[4][4], b[4][2];
#pragma unroll
            for (int mi = 0; mi < 4; mi++) {
                const int m0 = wm + mi * 16;
                a[mi][0] = Ac[(m0 + g)     * 20 + kb + t];
                a[mi][1] = Ac[(m0 + 8 + g) * 20 + kb + t];
                a[mi][2] = Ac[(m0 + g)     * 20 + kb + 4 + t];
                a[mi][3] = Ac[(m0 + 8 + g) * 20 + kb + 4 + t];
            }
#pragma unroll
            for (int nj = 0; nj < 4; nj++) {
                const int n0 = wn + nj * 8;
                b[nj][0] = Bc[(n0 + g) * 20 + kb + t];
                b[nj][1] = Bc[(n0 + g) * 20 + kb + 4 + t];
            }
#pragma unroll
            for (int mi = 0; mi < 4; mi++)
#pragma unroll
                for (int nj = 0; nj < 4; nj++)
                    mma_f16(acc[mi][nj], a[mi], b[nj]);
        }

        __half* ta = A0; A0 = A1; A1 = A2; A2 = ta;
        __half* tb = B0; B0 = B1; B1 = B2; B2 = tb;
    }

    float lsum = 0.f, lsq = 0.f;
#pragma unroll
    for (int mi = 0; mi < 4; mi++) {
#pragma unroll
        for (int nj = 0; nj < 4; nj++) {
            const int row = by * 128 + wm + mi * 16 + g;
            const int col = bx * 128 + wn + nj * 8 + t * 2;
#pragma unroll
            for (int half_i = 0; half_i < 2; half_i++) {
                const int r = row + half_i * 8;
                float v0 = acc[mi][nj][half_i * 2 + 0] + bias[col];
                float v1 = acc[mi][nj][half_i * 2 + 1] + bias[col + 1];
                if (EPI == 1) {
                    v0 = 0.5f * v0 * (1.0f + erff(v0 * 0.70710678118654752f));
                    v1 = 0.5f * v1 * (1.0f + erff(v1 * 0.70710678118654752f));
                    __half2 hv = __floats2half2_rn(v0, v1);
                    *(__half2*)((__half*)Cv + (size_t)r * N + col) = hv;
                } else {
                    if (EPI == 2) {
                        v0 += res[(size_t)r * N + col];
                        v1 += res[(size_t)r * N + col + 1];
                        lsum += v0 + v1;
                        lsq  += v0 * v0 + v1 * v1;
                    } else if (EPI == 3) {
                        v0 = __uint_as_float(f2tf32(v0 * oscale));
                        v1 = __uint_as_float(f2tf32(v1 * oscale));
                    }
                    *(float2*)((float*)Cv + (size_t)r * N + col) = make_float2(v0, v1);
                }
            }
        }
    }

    if (EPI == 2) {
        __syncthreads();
        float* r1 = (float*)sm;
        float* r2 = r1 + 256;
        r1[tid] = lsum; r2[tid] = lsq;
        __syncthreads();
        for (int st = 128; st > 0; st >>= 1) {
            if (tid < st) { r1[tid] += r1[tid + st]; r2[tid] += r2[tid + st]; }
            __syncthreads();
        }
        if (tid == 0) {
            const int b    = by >> 3;
            const int slot = (by & 7) * 8 + bx;
            part2[b * 64 + slot]          = r1[0];
            part2[B * 64 + b * 64 + slot] = r2[0];
        }
    }
}

__global__ void __launch_bounds__(256, 2)
gemm_qkv(const __half* __restrict__ x,
         const __half* __restrict__ wqt, const float* __restrict__ bq,
         const __half* __restrict__ wkt, const float* __restrict__ bk,
         const __half* __restrict__ wvt, const float* __restrict__ bv,
         float* __restrict__ q, float* __restrict__ k, float* __restrict__ v)
{
    extern __shared__ __half smh[];
    const __half* W; const float* bias; float* C; float osc;
    if (blockIdx.z == 0)      { W = wqt; bias = bq; C = q; osc = 0.125f; }
    else if (blockIdx.z == 1) { W = wkt; bias = bk; C = k; osc = 1.0f; }
    else                      { W = wvt; bias = bv; C = v; osc = 1.0f; }
    gemm_body<3>(x, W, bias, nullptr, C, D, D, blockIdx.x, blockIdx.y, smh, osc, nullptr);
}

template <int EPI>
__global__ void __launch_bounds__(256, 2)
gemm_pipe(const __half* __restrict__ A, const __half* __restrict__ Wt,
          const float* __restrict__ bias, const float* __restrict__ res,
          void* __restrict__ C, int K, int N, float* __restrict__ part2)
{
    extern __shared__ __half smh[];
    gemm_body<EPI>(A, Wt, bias, res, C, K, N, blockIdx.x, blockIdx.y, smh, 1.0f, part2);
}

// ---------------------------------------------------------------------------
// Flash attention (round-14 verified: K-tile 64, cp.async double-buffer,
// fused h = x + ctx + LN1 partials). Unchanged.
// ---------------------------------------------------------------------------
constexpr int PS_STRIDE = 68;
constexpr int KS_STRIDE = 68;
constexpr int VS_STRIDE = 72;
constexpr int ATTN_SMEM =
    (128 * PS_STRIDE + 2 * 64 * KS_STRIDE + 2 * 64 * VS_STRIDE) * 4;  // 106,496 B

__global__ void __launch_bounds__(256, 2)
flash_attn(const float* __restrict__ Q, const float* __restrict__ Kg,
           const float* __restrict__ Vg, const float* __restrict__ X,
           float* __restrict__ hres, float* __restrict__ part)
{
    extern __shared__ uint32_t smem[];
    uint32_t* Ps = smem;
    uint32_t* Kb = Ps + 128 * PS_STRIDE;
    uint32_t* Vb = Kb + 2 * 64 * KS_STRIDE;

    const int tid  = threadIdx.x;
    const int lane = tid & 31;
    const int warp = tid >> 5;
    const int g    = lane >> 2;
    const int t    = lane & 3;
    const int m0   = warp * 16;

    const int q0 = blockIdx.x * 128;
    const int hh = blockIdx.y;
    const int b  = blockIdx.z;

    const float* Qb  = Q  + (size_t)b * S * D + hh * DK;
    const float* Kgb = Kg + (size_t)b * S * D + hh * DK;
    const float* Vgb = Vg + (size_t)b * S * D + hh * DK;

#pragma unroll
    for (int u = 0; u < 8; u++) {
        const int idx = u * 256 + tid;
        const int row = idx >> 4;
        const int c4  = (idx & 15) * 4;
        cp_async16(Ps + row * PS_STRIDE + c4, Qb + (size_t)(q0 + row) * D + c4);
    }
    cp_commit();

    auto stageKV = [&](int buf, int k0) {
        uint32_t* Kd = Kb + buf * 64 * KS_STRIDE;
        uint32_t* Vd = Vb + buf * 64 * VS_STRIDE;
#pragma unroll
        for (int u = 0; u < 4; u++) {
            const int idx = u * 256 + tid;
            const int row = idx >> 4;
            const int c4  = (idx & 15) * 4;
            cp_async16(Kd + row * KS_STRIDE + c4, Kgb + (size_t)(k0 + row) * D + c4);
            cp_async16(Vd + row * VS_STRIDE + c4, Vgb + (size_t)(k0 + row) * D + c4);
        }
        cp_commit();
    };

    stageKV(0, 0);

    asm volatile("cp.async.wait_group 1;\n" ::: "memory");
    __syncthreads();
    uint32_t qf[8][4];
#pragma unroll
    for (int kc = 0; kc < 8; kc++) {
        const int kb = kc * 8;
        qf[kc][0] = Ps[(m0 + g)     * PS_STRIDE + kb + t];
        qf[kc][1] = Ps[(m0 + 8 + g) * PS_STRIDE + kb + t];
        qf[kc][2] = Ps[(m0 + g)     * PS_STRIDE + kb + 4 + t];
        qf[kc][3] = Ps[(m0 + 8 + g) * PS_STRIDE + kb + 4 + t];
    }

    float o[8][4];
#pragma unroll
    for (int j = 0; j < 8; j++)
#pragma unroll
        for (int c = 0; c < 4; c++) o[j][c] = 0.f;
    float mrun0 = -1e30f, mrun1 = -1e30f, lrun0 = 0.f, lrun1 = 0.f;

    constexpr int NIT = S / 64;
    for (int it = 0; it < NIT; it++) {
        const int buf = it & 1;
        __syncthreads();
        if (it + 1 < NIT) stageKV(buf ^ 1, (it + 1) * 64);
        if (it + 1 < NIT) asm volatile("cp.async.wait_group 1;\n" ::: "memory");
        else              asm volatile("cp.async.wait_group 0;\n" ::: "memory");
        __syncthreads();

        const uint32_t* Ks = Kb + buf * 64 * KS_STRIDE;
        const uint32_t* Vs = Vb + buf * 64 * VS_STRIDE;

        float sc[8][4];
#pragma unroll
        for (int j = 0; j < 8; j++) {
            sc[j][0] = 0.f; sc[j][1] = 0.f; sc[j][2] = 0.f; sc[j][3] = 0.f;
            const int n0 = j * 8;
#pragma unroll
            for (int kc = 0; kc < 8; kc++) {
                const int kb = kc * 8;
                uint32_t bf[2];
                bf[0] = Ks[(n0 + g) * KS_STRIDE + kb + t];
                bf[1] = Ks[(n0 + g) * KS_STRIDE + kb + 4 + t];
                mma_tf32(sc[j], qf[kc], bf);
            }
        }

        float nm0 = -1e30f, nm1 = -1e30f;
#pragma unroll
        for (int j = 0; j < 8; j++) {
            nm0 = fmaxf(nm0, fmaxf(sc[j][0], sc[j][1]));
            nm1 = fmaxf(nm1, fmaxf(sc[j][2], sc[j][3]));
        }
        nm0 = fmaxf(nm0, __shfl_xor_sync(0xffffffffu, nm0, 1));
        nm0 = fmaxf(nm0, __shfl_xor_sync(0xffffffffu, nm0, 2));
        nm1 = fmaxf(nm1, __shfl_xor_sync(0xffffffffu, nm1, 1));
        nm1 = fmaxf(nm1, __shfl_xor_sync(0xffffffffu, nm1, 2));
        const float newm0 = fmaxf(mrun0, nm0);
        const float newm1 = fmaxf(mrun1, nm1);
        const float f0 = __expf(mrun0 - newm0);
        const float f1 = __expf(mrun1 - newm1);

        float s0 = 0.f, s1 = 0.f;
#pragma unroll
        for (int j = 0; j < 8; j++) {
            const float p00 = __expf(sc[j][0] - newm0);
            const float p01 = __expf(sc[j][1] - newm0);
            const float p10 = __expf(sc[j][2] - newm1);
            const float p11 = __expf(sc[j][3] - newm1);
            s0 += p00 + p01;
            s1 += p10 + p11;
            uint2 w0 = make_uint2(f2tf32(p00), f2tf32(p01));
            uint2 w1 = make_uint2(f2tf32(p10), f2tf32(p11));
            *(uint2*)&Ps[(m0 + g)     * PS_STRIDE + j * 8 + 2 * t] = w0;
            *(uint2*)&Ps[(m0 + 8 + g) * PS_STRIDE + j * 8 + 2 * t] = w1;
        }
        s0 += __shfl_xor_sync(0xffffffffu, s0, 1);
        s0 += __shfl_xor_sync(0xffffffffu, s0, 2);
        s1 += __shfl_xor_sync(0xffffffffu, s1, 1);
        s1 += __shfl_xor_sync(0xffffffffu, s1, 2);
        lrun0 = lrun0 * f0 + s0;
        lrun1 = lrun1 * f1 + s1;
        mrun0 = newm0;
        mrun1 = newm1;
#pragma unroll
        for (int j = 0; j < 8; j++) {
            o[j][0] *= f0; o[j][1] *= f0;
            o[j][2] *= f1; o[j][3] *= f1;
        }
        __syncwarp();

#pragma unroll
        for (int kc = 0; kc < 8; kc++) {
            const int kb = kc * 8;
            uint32_t a[4];
            a[0] = Ps[(m0 + g)     * PS_STRIDE + kb + t];
            a[1] = Ps[(m0 + 8 + g) * PS_STRIDE + kb + t];
            a[2] = Ps[(m0 + g)     * PS_STRIDE + kb + 4 + t];
            a[3] = Ps[(m0 + 8 + g) * PS_STRIDE + kb + 4 + t];
#pragma unroll
            for (int j = 0; j < 8; j++) {
                uint32_t bf[2];
                bf[0] = Vs[(kb + t)     * VS_STRIDE + j * 8 + g];
                bf[1] = Vs[(kb + 4 + t) * VS_STRIDE + j * 8 + g];
                mma_tf32(o[j], a, bf);
            }
        }
    }

    const float inv0 = 1.0f / lrun0;
    const float inv1 = 1.0f / lrun1;
    const int row0 = q0 + m0 + g;
    const int row1 = row0 + 8;
    float lsum = 0.f, lsq = 0.f;
#pragma unroll
    for (int j = 0; j < 8; j++) {
        const int col = hh * DK + j * 8 + 2 * t;
        float2 xv0 = *(const float2*)(X + (size_t)(b * S + row0) * D + col);
        float2 xv1 = *(const float2*)(X + (size_t)(b * S + row1) * D + col);
        float h00 = xv0.x + o[j][0] * inv0;
        float h01 = xv0.y + o[j][1] * inv0;
        float h10 = xv1.x + o[j][2] * inv1;
        float h11 = xv1.y + o[j][3] * inv1;
        lsum += h00 + h01 + h10 + h11;
        lsq  += h00 * h00 + h01 * h01 + h10 * h10 + h11 * h11;
        *(float2*)(hres + (size_t)(b * S + row0) * D + col) = make_float2(h00, h01);
        *(float2*)(hres + (size_t)(b * S + row1) * D + col) = make_float2(h10, h11);
    }

    __syncthreads();
    float* r1 = (float*)Ps;
    float* r2 = r1 + 256;
    r1[tid] = lsum; r2[tid] = lsq;
    __syncthreads();
    for (int st = 128; st > 0; st >>= 1) {
        if (tid < st) { r1[tid] += r1[tid + st]; r2[tid] += r2[tid + st]; }
        __syncthreads();
    }
    if (tid == 0) {
        const int slot = blockIdx.x * 16 + hh;
        part[b * 128 + slot]           = r1[0];
        part[B * 128 + b * 128 + slot] = r2[0];
    }
}

// ---------------------------------------------------------------------------
// LayerNorm finalize/apply
// ---------------------------------------------------------------------------
template <int NCHUNK>
__global__ void __launch_bounds__(256)
ln_finalize(const float* __restrict__ part, float* __restrict__ stats)
{
    const int b = blockIdx.x, tid = threadIdx.x;
    __shared__ float r1[256], r2[256];
    r1[tid] = tid < NCHUNK ? part[b * NCHUNK + tid] : 0.f;
    r2[tid] = tid < NCHUNK ? part[B * NCHUNK + b * NCHUNK + tid] : 0.f;
    __syncthreads();
    for (int st = 128; st > 0; st >>= 1) {
        if (tid < st) { r1[tid] += r1[tid + st]; r2[tid] += r2[tid + st]; }
        __syncthreads();
    }
    if (tid == 0) {
        const float n = (float)S * (float)D;
        float mean = r1[0] / n;
        float var  = r2[0] / n - mean * mean;
        stats[2 * b]     = mean;
        stats[2 * b + 1] = rsqrtf(var + EPS);
    }
}

// normalize + affine; optionally emit fp16 copy for GEMM A operand
__global__ void __launch_bounds__(256)
ln_apply(const float* __restrict__ y, const float* __restrict__ g,
         const float* __restrict__ beta, const float* __restrict__ stats,
         float* __restrict__ out, __half* __restrict__ out_h)
{
    const int b = blockIdx.y;
    const int idx = (blockIdx.x * 256 + threadIdx.x) * 4;
    const float mean = stats[2 * b];
    const float rstd = stats[2 * b + 1];
    const size_t off = (size_t)b * S * D + idx;
    float4 v  = *(const float4*)(y + off);
    float4 gg = *(const float4*)(g + idx);
    float4 bb = *(const float4*)(beta + idx);
    v.x = (v.x - mean) * rstd * gg.x + bb.x;
    v.y = (v.y - mean) * rstd * gg.y + bb.y;
    v.z = (v.z - mean) * rstd * gg.z + bb.z;
    v.w = (v.w - mean) * rstd * gg.w + bb.w;
    *(float4*)(out + off) = v;
    if (out_h) {
        __half2 h0 = __floats2half2_rn(v.x, v.y);
        __half2 h1 = __floats2half2_rn(v.z, v.w);
        uint2 o = make_uint2(*(uint32_t*)&h0, *(uint32_t*)&h1);
        *(uint2*)(out_h + off) = o;
    }
}

// ---------------------------------------------------------------------------
// kernel_launch
// ---------------------------------------------------------------------------
extern "C" void kernel_launch(void* const* d_in, const int* in_sizes, int n_in,
                              void* d_out, int out_size)
{
    const float* x    = (const float*)d_in[0];
    const float* wq   = (const float*)d_in[1];
    const float* bq   = (const float*)d_in[2];
    const float* wk   = (const float*)d_in[3];
    const float* bk   = (const float*)d_in[4];
    const float* wv   = (const float*)d_in[5];
    const float* bv   = (const float*)d_in[6];
    const float* ln1g = (const float*)d_in[7];
    const float* ln1b = (const float*)d_in[8];
    const float* w1   = (const float*)d_in[9];
    const float* b1   = (const float*)d_in[10];
    const float* w2   = (const float*)d_in[11];
    const float* b2   = (const float*)d_in[12];
    const float* ln2g = (const float*)d_in[13];
    const float* ln2b = (const float*)d_in[14];
    float* out = (float*)d_out;

    float *q, *k, *v, *ctx, *h, *part, *stats;
    __half *xh, *hh, *ffh, *wqt, *wkt, *wvt, *w1t, *w2t;
    cudaGetSymbolAddress((void**)&q,     g_q);
    cudaGetSymbolAddress((void**)&k,     g_k);
    cudaGetSymbolAddress((void**)&v,     g_v);
    cudaGetSymbolAddress((void**)&ctx,   g_ctx);
    cudaGetSymbolAddress((void**)&h,     g_h);
    cudaGetSymbolAddress((void**)&part,  g_part);
    cudaGetSymbolAddress((void**)&stats, g_stats);
    cudaGetSymbolAddress((void**)&xh,    g_xh);
    cudaGetSymbolAddress((void**)&hh,    g_hh);
    cudaGetSymbolAddress((void**)&ffh,   g_ffh);
    cudaGetSymbolAddress((void**)&wqt,   g_wqt);
    cudaGetSymbolAddress((void**)&wkt,   g_wkt);
    cudaGetSymbolAddress((void**)&wvt,   g_wvt);
    cudaGetSymbolAddress((void**)&w1t,   g_w1t);
    cudaGetSymbolAddress((void**)&w2t,   g_w2t);

    static bool attr_done = false;
    if (!attr_done) {
        cudaFuncSetAttribute(flash_attn,
                             cudaFuncAttributeMaxDynamicSharedMemorySize, ATTN_SMEM);
        cudaFuncSetAttribute(gemm_qkv,
                             cudaFuncAttributeMaxDynamicSharedMemorySize, GEMM_SMEM);
        cudaFuncSetAttribute(gemm_pipe<1>,
                             cudaFuncAttributeMaxDynamicSharedMemorySize, GEMM_SMEM);
        cudaFuncSetAttribute(gemm_pipe<2>,
                             cudaFuncAttributeMaxDynamicSharedMemorySize, GEMM_SMEM);
        attr_done = true;
    }

    // Prepass: x -> fp16; weights -> transposed fp16
    conv_x_f16<<<(NT * D / 4 + 255) / 256, 256>>>(x, xh, NT * D / 4);
    transpose_f16<<<dim3(D / 32, D / 32, 3), dim3(32, 8)>>>(
        wq, wqt, wk, wkt, wv, wvt, D, D);
    transpose_f16<<<dim3(DFF / 32, D / 32, 1), dim3(32, 8)>>>(
        w1, w1t, nullptr, nullptr, nullptr, nullptr, D, DFF);
    transpose_f16<<<dim3(D / 32, DFF / 32, 1), dim3(32, 8)>>>(
        w2, w2t, nullptr, nullptr, nullptr, nullptr, DFF, D);

    // QKV projections (fp16 MMA; outputs fp32 tf32-rounded, q pre-scaled 1/8)
    gemm_qkv<<<dim3(D / 128, NT / 128, 3), 256, GEMM_SMEM>>>(
        xh, wqt, bq, wkt, bk, wvt, bv, q, k, v);

    // Flash attention (+fused h = x + ctx and LN1 partial sums)
    flash_attn<<<dim3(S / 128, H, B), 256, ATTN_SMEM>>>(q, k, v, x, h, part);

    // LayerNorm 1 finalize + apply (h float in-place, + fp16 copy hh)
    ln_finalize<128><<<B, 256>>>(part, stats);
    ln_apply<<<dim3(1024, B), 256>>>(h, ln1g, ln1b, stats, h, hh);

    // FFN: ffh = half(gelu(hh @ w1 + b1)); ctx = ffh @ w2 + b2 + h (+LN2 partials)
    gemm_pipe<1><<<dim3(DFF / 128, NT / 128), 256, GEMM_SMEM>>>(
        hh, w1t, b1, nullptr, ffh, D, DFF, nullptr);
    gemm_pipe<2><<<dim3(D / 128, NT / 128), 256, GEMM_SMEM>>>(
        ffh, w2t, b2, h, ctx, DFF, D, part);

    // LayerNorm 2 -> output (partials from FFN2 epilogue)
    ln_finalize<64><<<B, 256>>>(part, stats);
    ln_apply<<<dim3(1024, B), 256>>>(ctx, ln2g, ln2b, stats, out, nullptr);
}

// round 16
// speedup vs baseline: 2.7968x; 1.1147x over previous
#include <cuda_runtime.h>
#include <cuda_fp16.h>
#include <math.h>
#include <stdint.h>

// Problem constants
constexpr int B   = 8;
constexpr int S   = 1024;
constexpr int D   = 1024;
constexpr int H   = 16;
constexpr int DK  = 64;
constexpr int DFF = 4096;
constexpr int NT  = B * S;          // 8192 rows
constexpr float EPS = 1e-5f;

// ---------------------------------------------------------------------------
// Scratch (static __device__ arrays — no runtime allocation)
// ---------------------------------------------------------------------------
__device__ float g_ctx[NT * D];
__device__ float g_h  [NT * D];
__device__ float g_part[2 * B * 256];
__device__ float g_stats[2 * B];
// fp16 operands
__device__ __half g_qh [NT * D];
__device__ __half g_kh [NT * D];
__device__ __half g_vh [NT * D];
__device__ __half g_xh [NT * D];
__device__ __half g_hh [NT * D];
__device__ __half g_ffh[(size_t)NT * DFF];
__device__ __half g_wqt[D * D];            // Wt[n][k]
__device__ __half g_wkt[D * D];
__device__ __half g_wvt[D * D];
__device__ __half g_w1t[(size_t)DFF * D];
__device__ __half g_w2t[(size_t)D * DFF];

// ---------------------------------------------------------------------------
// helpers
// ---------------------------------------------------------------------------
__device__ __forceinline__ void mma_f16(float c[4], const uint32_t a[4], const uint32_t b[2]) {
    asm volatile(
        "mma.sync.aligned.m16n8k16.row.col.f32.f16.f16.f32 "
        "{%0,%1,%2,%3}, {%4,%5,%6,%7}, {%8,%9}, {%0,%1,%2,%3};\n"
        : "+f"(c[0]), "+f"(c[1]), "+f"(c[2]), "+f"(c[3])
        : "r"(a[0]), "r"(a[1]), "r"(a[2]), "r"(a[3]), "r"(b[0]), "r"(b[1]));
}
__device__ __forceinline__ void cp_async16(void* smem_ptr, const void* gptr) {
    uint32_t sa = (uint32_t)__cvta_generic_to_shared(smem_ptr);
    asm volatile("cp.async.cg.shared.global [%0], [%1], 16;\n" :: "r"(sa), "l"(gptr));
}
__device__ __forceinline__ void cp_commit() {
    asm volatile("cp.async.commit_group;\n");
}
__device__ __forceinline__ void ldsm_x4_trans(uint32_t& r0, uint32_t& r1,
                                              uint32_t& r2, uint32_t& r3, uint32_t addr) {
    asm volatile("ldmatrix.sync.aligned.m8n8.x4.trans.shared.b16 {%0,%1,%2,%3}, [%4];"
                 : "=r"(r0), "=r"(r1), "=r"(r2), "=r"(r3) : "r"(addr));
}

// ---------------------------------------------------------------------------
// Prepass: x -> fp16 ; weights -> transposed fp16
// ---------------------------------------------------------------------------
__global__ void __launch_bounds__(256)
conv_x_f16(const float* __restrict__ in, __half* __restrict__ out, int n4)
{
    const int i = blockIdx.x * 256 + threadIdx.x;
    if (i < n4) {
        float4 v = ((const float4*)in)[i];
        __half2 h0 = __floats2half2_rn(v.x, v.y);
        __half2 h1 = __floats2half2_rn(v.z, v.w);
        uint2 o = make_uint2(*(uint32_t*)&h0, *(uint32_t*)&h1);
        ((uint2*)out)[i] = o;
    }
}

__global__ void __launch_bounds__(256)
transpose_f16(const float* __restrict__ in0, __half* __restrict__ out0,
              const float* __restrict__ in1, __half* __restrict__ out1,
              const float* __restrict__ in2, __half* __restrict__ out2,
              int R, int C)
{
    const float* in  = blockIdx.z == 0 ? in0  : (blockIdx.z == 1 ? in1  : in2);
    __half*      out = blockIdx.z == 0 ? out0 : (blockIdx.z == 1 ? out1 : out2);
    __shared__ float tile[32][33];
    const int c0 = blockIdx.x * 32, r0 = blockIdx.y * 32;
    const int tx = threadIdx.x, ty = threadIdx.y;
#pragma unroll
    for (int i = 0; i < 32; i += 8)
        tile[ty + i][tx] = in[(size_t)(r0 + ty + i) * C + c0 + tx];
    __syncthreads();
#pragma unroll
    for (int i = 0; i < 32; i += 8)
        out[(size_t)(c0 + ty + i) * R + r0 + tx] = __float2half_rn(tile[tx][ty + i]);
}

// ---------------------------------------------------------------------------
// FP16 tensor-core GEMM (round-15 verified layout).
// EPI: 1 = bias+GeLU -> half out, 2 = bias+residual -> float out (+LN partials),
//      3 = (bias+acc)*oscale -> HALF out (QKV)
// ---------------------------------------------------------------------------
constexpr int TSZH = 128 * 40;
constexpr int GEMM_SMEM = 3 * 2 * TSZH * 2;          // 61,440 B

template <int EPI>
__device__ __forceinline__ void gemm_body(
    const __half* __restrict__ A, const __half* __restrict__ Wt,
    const float* __restrict__ bias, const float* __restrict__ res,
    void* __restrict__ Cv, int K, int N, int bx, int by, __half* sm,
    float oscale, float* __restrict__ part2)
{
    __half* AsB = sm;
    __half* BsB = sm + 3 * TSZH;

    const int tid  = threadIdx.x;
    const int lane = tid & 31;
    const int warp = tid >> 5;
    const int g    = lane >> 2;
    const int t    = lane & 3;
    const int wm   = (warp & 1) * 64;
    const int wn   = (warp >> 1) * 32;

    const __half* Ab = A  + (size_t)(by * 128) * K;
    const __half* Wb = Wt + (size_t)(bx * 128) * K;

    float acc[4][4][4];
#pragma unroll
    for (int mi = 0; mi < 4; mi++)
#pragma unroll
        for (int nj = 0; nj < 4; nj++)
#pragma unroll
            for (int c = 0; c < 4; c++) acc[mi][nj][c] = 0.f;

    __half* A0 = AsB; __half* A1 = AsB + TSZH; __half* A2 = AsB + 2 * TSZH;
    __half* B0 = BsB; __half* B1 = BsB + TSZH; __half* B2 = BsB + 2 * TSZH;

    auto stage_to = [&](__half* Ad, __half* Bd, int kk) {
#pragma unroll
        for (int u = 0; u < 2; u++) {
            const int i   = tid + u * 256;
            const int row = i >> 2;
            const int c8  = (i & 3) * 8;
            cp_async16(Ad + row * 40 + c8, Ab + (size_t)row * K + kk + c8);
        }
#pragma unroll
        for (int u = 0; u < 2; u++) {
            const int i   = tid + u * 256;
            const int row = i >> 2;
            const int c8  = (i & 3) * 8;
            cp_async16(Bd + row * 40 + c8, Wb + (size_t)row * K + kk + c8);
        }
        cp_commit();
    };

    const int nT = K >> 5;
    stage_to(A0, B0, 0);
    if (nT > 1) stage_to(A1, B1, 32);

    for (int tt = 0; tt < nT; tt++) {
        if (tt + 1 < nT) asm volatile("cp.async.wait_group 1;\n" ::: "memory");
        else             asm volatile("cp.async.wait_group 0;\n" ::: "memory");
        __syncthreads();
        if (tt + 2 < nT) stage_to(A2, B2, (tt + 2) * 32);

        const uint32_t* Ac = (const uint32_t*)A0;
        const uint32_t* Bc = (const uint32_t*)B0;
#pragma unroll
        for (int ks = 0; ks < 2; ks++) {
            const int kb = ks * 8;
            uint32_t a[4][4], b[4][2];
#pragma unroll
            for (int mi = 0; mi < 4; mi++) {
                const int m0 = wm + mi * 16;
                a[mi][0] = Ac[(m0 + g)     * 20 + kb + t];
                a[mi][1] = Ac[(m0 + 8 + g) * 20 + kb + t];
                a[mi][2] = Ac[(m0 + g)     * 20 + kb + 4 + t];
                a[mi][3] = Ac[(m0 + 8 + g) * 20 + kb + 4 + t];
            }
#pragma unroll
            for (int nj = 0; nj < 4; nj++) {
                const int n0 = wn + nj * 8;
                b[nj][0] = Bc[(n0 + g) * 20 + kb + t];
                b[nj][1] = Bc[(n0 + g) * 20 + kb + 4 + t];
            }
#pragma unroll
            for (int mi = 0; mi < 4; mi++)
#pragma unroll
                for (int nj = 0; nj < 4; nj++)
                    mma_f16(acc[mi][nj], a[mi], b[nj]);
        }

        __half* ta = A0; A0 = A1; A1 = A2; A2 = ta;
        __half* tb = B0; B0 = B1; B1 = B2; B2 = tb;
    }

    float lsum = 0.f, lsq = 0.f;
#pragma unroll
    for (int mi = 0; mi < 4; mi++) {
#pragma unroll
        for (int nj = 0; nj < 4; nj++) {
            const int row = by * 128 + wm + mi * 16 + g;
            const int col = bx * 128 + wn + nj * 8 + t * 2;
#pragma unroll
            for (int half_i = 0; half_i < 2; half_i++) {
                const int r = row + half_i * 8;
                float v0 = acc[mi][nj][half_i * 2 + 0] + bias[col];
                float v1 = acc[mi][nj][half_i * 2 + 1] + bias[col + 1];
                if (EPI == 1) {
                    v0 = 0.5f * v0 * (1.0f + erff(v0 * 0.70710678118654752f));
                    v1 = 0.5f * v1 * (1.0f + erff(v1 * 0.70710678118654752f));
                    __half2 hv = __floats2half2_rn(v0, v1);
                    *(__half2*)((__half*)Cv + (size_t)r * N + col) = hv;
                } else if (EPI == 3) {
                    __half2 hv = __floats2half2_rn(v0 * oscale, v1 * oscale);
                    *(__half2*)((__half*)Cv + (size_t)r * N + col) = hv;
                } else {
                    v0 += res[(size_t)r * N + col];
                    v1 += res[(size_t)r * N + col + 1];
                    lsum += v0 + v1;
                    lsq  += v0 * v0 + v1 * v1;
                    *(float2*)((float*)Cv + (size_t)r * N + col) = make_float2(v0, v1);
                }
            }
        }
    }

    if (EPI == 2) {
        __syncthreads();
        float* r1 = (float*)sm;
        float* r2 = r1 + 256;
        r1[tid] = lsum; r2[tid] = lsq;
        __syncthreads();
        for (int st = 128; st > 0; st >>= 1) {
            if (tid < st) { r1[tid] += r1[tid + st]; r2[tid] += r2[tid + st]; }
            __syncthreads();
        }
        if (tid == 0) {
            const int b    = by >> 3;
            const int slot = (by & 7) * 8 + bx;
            part2[b * 64 + slot]          = r1[0];
            part2[B * 64 + b * 64 + slot] = r2[0];
        }
    }
}

__global__ void __launch_bounds__(256, 2)
gemm_qkv(const __half* __restrict__ x,
         const __half* __restrict__ wqt, const float* __restrict__ bq,
         const __half* __restrict__ wkt, const float* __restrict__ bk,
         const __half* __restrict__ wvt, const float* __restrict__ bv,
         __half* __restrict__ q, __half* __restrict__ k, __half* __restrict__ v)
{
    extern __shared__ __half smh[];
    const __half* W; const float* bias; __half* C; float osc;
    if (blockIdx.z == 0)      { W = wqt; bias = bq; C = q; osc = 0.125f; }
    else if (blockIdx.z == 1) { W = wkt; bias = bk; C = k; osc = 1.0f; }
    else                      { W = wvt; bias = bv; C = v; osc = 1.0f; }
    gemm_body<3>(x, W, bias, nullptr, C, D, D, blockIdx.x, blockIdx.y, smh, osc, nullptr);
}

template <int EPI>
__global__ void __launch_bounds__(256, 2)
gemm_pipe(const __half* __restrict__ A, const __half* __restrict__ Wt,
          const float* __restrict__ bias, const float* __restrict__ res,
          void* __restrict__ C, int K, int N, float* __restrict__ part2)
{
    extern __shared__ __half smh[];
    gemm_body<EPI>(A, Wt, bias, res, C, K, N, blockIdx.x, blockIdx.y, smh, 1.0f, part2);
}

// ---------------------------------------------------------------------------
// FP16 flash attention: K-tile 64, cp.async double-buffered K/V,
// S=QK^T and P·V via m16n8k16 (V B-frags via ldmatrix.trans).
// Epilogue: h = x + ctx, LN1 partial sums. Tiles: [row][72 halfs] (36 words).
// ---------------------------------------------------------------------------
constexpr int FW = 36;   // words per row (72 halfs)
constexpr int ATTN_SMEM = (128 * FW + 2 * 64 * FW + 2 * 64 * FW) * 4;  // 55,296 B

__global__ void __launch_bounds__(256, 2)
flash_attn(const __half* __restrict__ Q, const __half* __restrict__ Kg,
           const __half* __restrict__ Vg, const float* __restrict__ X,
           float* __restrict__ hres, float* __restrict__ part)
{
    extern __shared__ __half smh[];
    __half* Ph = smh;                    // Q then P: [128][72]
    __half* Kh = Ph + 128 * 72;          // 2 x [64][72]
    __half* Vh = Kh + 2 * 64 * 72;       // 2 x [64][72]
    uint32_t* Pw = (uint32_t*)Ph;

    const int tid  = threadIdx.x;
    const int lane = tid & 31;
    const int warp = tid >> 5;
    const int g    = lane >> 2;
    const int t    = lane & 3;
    const int m0   = warp * 16;
    // ldmatrix.trans lane mapping for V tiles
    const int lkey = ((lane >> 3) & 1) * 8 + (lane & 7);
    const int ldk  = (lane >> 4) * 8;

    const int q0 = blockIdx.x * 128;
    const int hh = blockIdx.y;
    const int b  = blockIdx.z;

    const __half* Qb  = Q  + (size_t)b * S * D + hh * DK;
    const __half* Kgb = Kg + (size_t)b * S * D + hh * DK;
    const __half* Vgb = Vg + (size_t)b * S * D + hh * DK;

    // ---- stage Q tile (128 rows x 128 B) - group A
#pragma unroll
    for (int u = 0; u < 4; u++) {
        const int idx = u * 256 + tid;
        const int row = idx >> 3;
        const int c8  = (idx & 7) * 8;
        cp_async16(Ph + row * 72 + c8, Qb + (size_t)(q0 + row) * D + c8);
    }
    cp_commit();

    auto stageKV = [&](int buf, int k0) {
        __half* Kd = Kh + buf * 64 * 72;
        __half* Vd = Vh + buf * 64 * 72;
#pragma unroll
        for (int u = 0; u < 2; u++) {
            const int idx = u * 256 + tid;
            const int row = idx >> 3;
            const int c8  = (idx & 7) * 8;
            cp_async16(Kd + row * 72 + c8, Kgb + (size_t)(k0 + row) * D + c8);
            cp_async16(Vd + row * 72 + c8, Vgb + (size_t)(k0 + row) * D + c8);
        }
        cp_commit();
    };

    stageKV(0, 0);

    asm volatile("cp.async.wait_group 1;\n" ::: "memory");
    __syncthreads();
    // Q fragments: 4 k-chunks of 16 dk
    uint32_t qf[4][4];
#pragma unroll
    for (int kc = 0; kc < 4; kc++) {
        qf[kc][0] = Pw[(m0 + g)     * FW + kc * 8 + t];
        qf[kc][1] = Pw[(m0 + 8 + g) * FW + kc * 8 + t];
        qf[kc][2] = Pw[(m0 + g)     * FW + kc * 8 + 4 + t];
        qf[kc][3] = Pw[(m0 + 8 + g) * FW + kc * 8 + 4 + t];
    }

    float o[8][4];
#pragma unroll
    for (int j = 0; j < 8; j++)
#pragma unroll
        for (int c = 0; c < 4; c++) o[j][c] = 0.f;
    float mrun0 = -1e30f, mrun1 = -1e30f, lrun0 = 0.f, lrun1 = 0.f;

    constexpr int NIT = S / 64;
    for (int it = 0; it < NIT; it++) {
        const int buf = it & 1;
        __syncthreads();
        if (it + 1 < NIT) stageKV(buf ^ 1, (it + 1) * 64);
        if (it + 1 < NIT) asm volatile("cp.async.wait_group 1;\n" ::: "memory");
        else              asm volatile("cp.async.wait_group 0;\n" ::: "memory");
        __syncthreads();

        const uint32_t* Kw = (const uint32_t*)(Kh + buf * 64 * 72);
        const __half*   Vs = Vh + buf * 64 * 72;
        const uint32_t  vbase = (uint32_t)__cvta_generic_to_shared(Vs);

        // ---- S = Q K^T : 8 n-frags (64 keys), 4 k-chunks (dk)
        float sc[8][4];
#pragma unroll
        for (int j = 0; j < 8; j++) {
            sc[j][0] = 0.f; sc[j][1] = 0.f; sc[j][2] = 0.f; sc[j][3] = 0.f;
            const int n0 = j * 8;
#pragma unroll
            for (int kc = 0; kc < 4; kc++) {
                uint32_t bf[2];
                bf[0] = Kw[(n0 + g) * FW + kc * 8 + t];
                bf[1] = Kw[(n0 + g) * FW + kc * 8 + 4 + t];
                mma_f16(sc[j], qf[kc], bf);
            }
        }

        // ---- online softmax
        float nm0 = -1e30f, nm1 = -1e30f;
#pragma unroll
        for (int j = 0; j < 8; j++) {
            nm0 = fmaxf(nm0, fmaxf(sc[j][0], sc[j][1]));
            nm1 = fmaxf(nm1, fmaxf(sc[j][2], sc[j][3]));
        }
        nm0 = fmaxf(nm0, __shfl_xor_sync(0xffffffffu, nm0, 1));
        nm0 = fmaxf(nm0, __shfl_xor_sync(0xffffffffu, nm0, 2));
        nm1 = fmaxf(nm1, __shfl_xor_sync(0xffffffffu, nm1, 1));
        nm1 = fmaxf(nm1, __shfl_xor_sync(0xffffffffu, nm1, 2));
        const float newm0 = fmaxf(mrun0, nm0);
        const float newm1 = fmaxf(mrun1, nm1);
        const float f0 = __expf(mrun0 - newm0);
        const float f1 = __expf(mrun1 - newm1);

        float s0 = 0.f, s1 = 0.f;
#pragma unroll
        for (int j = 0; j < 8; j++) {
            const float p00 = __expf(sc[j][0] - newm0);
            const float p01 = __expf(sc[j][1] - newm0);
            const float p10 = __expf(sc[j][2] - newm1);
            const float p11 = __expf(sc[j][3] - newm1);
            s0 += p00 + p01;
            s1 += p10 + p11;
            __half2 hp0 = __floats2half2_rn(p00, p01);
            __half2 hp1 = __floats2half2_rn(p10, p11);
            Pw[(m0 + g)     * FW + j * 4 + t] = *(uint32_t*)&hp0;
            Pw[(m0 + 8 + g) * FW + j * 4 + t] = *(uint32_t*)&hp1;
        }
        s0 += __shfl_xor_sync(0xffffffffu, s0, 1);
        s0 += __shfl_xor_sync(0xffffffffu, s0, 2);
        s1 += __shfl_xor_sync(0xffffffffu, s1, 1);
        s1 += __shfl_xor_sync(0xffffffffu, s1, 2);
        lrun0 = lrun0 * f0 + s0;
        lrun1 = lrun1 * f1 + s1;
        mrun0 = newm0;
        mrun1 = newm1;
#pragma unroll
        for (int j = 0; j < 8; j++) {
            o[j][0] *= f0; o[j][1] *= f0;
            o[j][2] *= f1; o[j][3] *= f1;
        }
        __syncwarp();

        // ---- O += P V : 4 key-chunks x 4 dk-chunks (ldmatrix.trans B frags)
#pragma unroll
        for (int kc = 0; kc < 4; kc++) {
            uint32_t a[4];
            a[0] = Pw[(m0 + g)     * FW + kc * 8 + t];
            a[1] = Pw[(m0 + 8 + g) * FW + kc * 8 + t];
            a[2] = Pw[(m0 + g)     * FW + kc * 8 + 4 + t];
            a[3] = Pw[(m0 + 8 + g) * FW + kc * 8 + 4 + t];
#pragma unroll
            for (int nd = 0; nd < 4; nd++) {
                uint32_t r0, r1, r2, r3;
                const uint32_t addr = vbase +
                    (uint32_t)(((kc * 16 + lkey) * 72 + nd * 16 + ldk) * 2);
                ldsm_x4_trans(r0, r1, r2, r3, addr);
                uint32_t bA[2] = {r0, r1};
                uint32_t bB[2] = {r2, r3};
                mma_f16(o[nd * 2 + 0], a, bA);
                mma_f16(o[nd * 2 + 1], a, bB);
            }
        }
    }

    // ---- epilogue: h = x + ctx, LN1 partials
    const float inv0 = 1.0f / lrun0;
    const float inv1 = 1.0f / lrun1;
    const int row0 = q0 + m0 + g;
    const int row1 = row0 + 8;
    float lsum = 0.f, lsq = 0.f;
#pragma unroll
    for (int j = 0; j < 8; j++) {
        const int col = hh * DK + j * 8 + 2 * t;
        float2 xv0 = *(const float2*)(X + (size_t)(b * S + row0) * D + col);
        float2 xv1 = *(const float2*)(X + (size_t)(b * S + row1) * D + col);
        float h00 = xv0.x + o[j][0] * inv0;
        float h01 = xv0.y + o[j][1] * inv0;
        float h10 = xv1.x + o[j][2] * inv1;
        float h11 = xv1.y + o[j][3] * inv1;
        lsum += h00 + h01 + h10 + h11;
        lsq  += h00 * h00 + h01 * h01 + h10 * h10 + h11 * h11;
        *(float2*)(hres + (size_t)(b * S + row0) * D + col) = make_float2(h00, h01);
        *(float2*)(hres + (size_t)(b * S + row1) * D + col) = make_float2(h10, h11);
    }

    __syncthreads();
    float* r1 = (float*)Ph;
    float* r2 = r1 + 256;
    r1[tid] = lsum; r2[tid] = lsq;
    __syncthreads();
    for (int st = 128; st > 0; st >>= 1) {
        if (tid < st) { r1[tid] += r1[tid + st]; r2[tid] += r2[tid + st]; }
        __syncthreads();
    }
    if (tid == 0) {
        const int slot = blockIdx.x * 16 + hh;
        part[b * 128 + slot]           = r1[0];
        part[B * 128 + b * 128 + slot] = r2[0];
    }
}

// ---------------------------------------------------------------------------
// LayerNorm finalize/apply
// ---------------------------------------------------------------------------
template <int NCHUNK>
__global__ void __launch_bounds__(256)
ln_finalize(const float* __restrict__ part, float* __restrict__ stats)
{
    const int b = blockIdx.x, tid = threadIdx.x;
    __shared__ float r1[256], r2[256];
    r1[tid] = tid < NCHUNK ? part[b * NCHUNK + tid] : 0.f;
    r2[tid] = tid < NCHUNK ? part[B * NCHUNK + b * NCHUNK + tid] : 0.f;
    __syncthreads();
    for (int st = 128; st > 0; st >>= 1) {
        if (tid < st) { r1[tid] += r1[tid + st]; r2[tid] += r2[tid + st]; }
        __syncthreads();
    }
    if (tid == 0) {
        const float n = (float)S * (float)D;
        float mean = r1[0] / n;
        float var  = r2[0] / n - mean * mean;
        stats[2 * b]     = mean;
        stats[2 * b + 1] = rsqrtf(var + EPS);
    }
}

__global__ void __launch_bounds__(256)
ln_apply(const float* __restrict__ y, const float* __restrict__ g,
         const float* __restrict__ beta, const float* __restrict__ stats,
         float* __restrict__ out, __half* __restrict__ out_h)
{
    const int b = blockIdx.y;
    const int idx = (blockIdx.x * 256 + threadIdx.x) * 4;
    const float mean = stats[2 * b];
    const float rstd = stats[2 * b + 1];
    const size_t off = (size_t)b * S * D + idx;
    float4 v  = *(const float4*)(y + off);
    float4 gg = *(const float4*)(g + idx);
    float4 bb = *(const float4*)(beta + idx);
    v.x = (v.x - mean) * rstd * gg.x + bb.x;
    v.y = (v.y - mean) * rstd * gg.y + bb.y;
    v.z = (v.z - mean) * rstd * gg.z + bb.z;
    v.w = (v.w - mean) * rstd * gg.w + bb.w;
    *(float4*)(out + off) = v;
    if (out_h) {
        __half2 h0 = __floats2half2_rn(v.x, v.y);
        __half2 h1 = __floats2half2_rn(v.z, v.w);
        uint2 o = make_uint2(*(uint32_t*)&h0, *(uint32_t*)&h1);
        *(uint2*)(out_h + off) = o;
    }
}

// ---------------------------------------------------------------------------
// kernel_launch
// ---------------------------------------------------------------------------
extern "C" void kernel_launch(void* const* d_in, const int* in_sizes, int n_in,
                              void* d_out, int out_size)
{
    const float* x    = (const float*)d_in[0];
    const float* wq   = (const float*)d_in[1];
    const float* bq   = (const float*)d_in[2];
    const float* wk   = (const float*)d_in[3];
    const float* bk   = (const float*)d_in[4];
    const float* wv   = (const float*)d_in[5];
    const float* bv   = (const float*)d_in[6];
    const float* ln1g = (const float*)d_in[7];
    const float* ln1b = (const float*)d_in[8];
    const float* w1   = (const float*)d_in[9];
    const float* b1   = (const float*)d_in[10];
    const float* w2   = (const float*)d_in[11];
    const float* b2   = (const float*)d_in[12];
    const float* ln2g = (const float*)d_in[13];
    const float* ln2b = (const float*)d_in[14];
    float* out = (float*)d_out;

    float *ctx, *h, *part, *stats;
    __half *qh, *kh, *vh, *xh, *hh, *ffh, *wqt, *wkt, *wvt, *w1t, *w2t;
    cudaGetSymbolAddress((void**)&ctx,   g_ctx);
    cudaGetSymbolAddress((void**)&h,     g_h);
    cudaGetSymbolAddress((void**)&part,  g_part);
    cudaGetSymbolAddress((void**)&stats, g_stats);
    cudaGetSymbolAddress((void**)&qh,    g_qh);
    cudaGetSymbolAddress((void**)&kh,    g_kh);
    cudaGetSymbolAddress((void**)&vh,    g_vh);
    cudaGetSymbolAddress((void**)&xh,    g_xh);
    cudaGetSymbolAddress((void**)&hh,    g_hh);
    cudaGetSymbolAddress((void**)&ffh,   g_ffh);
    cudaGetSymbolAddress((void**)&wqt,   g_wqt);
    cudaGetSymbolAddress((void**)&wkt,   g_wkt);
    cudaGetSymbolAddress((void**)&wvt,   g_wvt);
    cudaGetSymbolAddress((void**)&w1t,   g_w1t);
    cudaGetSymbolAddress((void**)&w2t,   g_w2t);

    static bool attr_done = false;
    if (!attr_done) {
        cudaFuncSetAttribute(flash_attn,
                             cudaFuncAttributeMaxDynamicSharedMemorySize, ATTN_SMEM);
        cudaFuncSetAttribute(gemm_qkv,
                             cudaFuncAttributeMaxDynamicSharedMemorySize, GEMM_SMEM);
        cudaFuncSetAttribute(gemm_pipe<1>,
                             cudaFuncAttributeMaxDynamicSharedMemorySize, GEMM_SMEM);
        cudaFuncSetAttribute(gemm_pipe<2>,
                             cudaFuncAttributeMaxDynamicSharedMemorySize, GEMM_SMEM);
        attr_done = true;
    }

    // Prepass: x -> fp16; weights -> transposed fp16
    conv_x_f16<<<(NT * D / 4 + 255) / 256, 256>>>(x, xh, NT * D / 4);
    transpose_f16<<<dim3(D / 32, D / 32, 3), dim3(32, 8)>>>(
        wq, wqt, wk, wkt, wv, wvt, D, D);
    transpose_f16<<<dim3(DFF / 32, D / 32, 1), dim3(32, 8)>>>(
        w1, w1t, nullptr, nullptr, nullptr, nullptr, D, DFF);
    transpose_f16<<<dim3(D / 32, DFF / 32, 1), dim3(32, 8)>>>(
        w2, w2t, nullptr, nullptr, nullptr, nullptr, DFF, D);

    // QKV projections (fp16 MMA, fp16 outputs; q pre-scaled 1/8)
    gemm_qkv<<<dim3(D / 128, NT / 128, 3), 256, GEMM_SMEM>>>(
        xh, wqt, bq, wkt, bk, wvt, bv, qh, kh, vh);

    // FP16 flash attention (+fused h = x + ctx and LN1 partial sums)
    flash_attn<<<dim3(S / 128, H, B), 256, ATTN_SMEM>>>(qh, kh, vh, x, h, part);

    // LayerNorm 1 finalize + apply (h float in-place, + fp16 copy hh)
    ln_finalize<128><<<B, 256>>>(part, stats);
    ln_apply<<<dim3(1024, B), 256>>>(h, ln1g, ln1b, stats, h, hh);

    // FFN: ffh = half(gelu(hh @ w1 + b1)); ctx = ffh @ w2 + b2 + h (+LN2 partials)
    gemm_pipe<1><<<dim3(DFF / 128, NT / 128), 256, GEMM_SMEM>>>(
        hh, w1t, b1, nullptr, ffh, D, DFF, nullptr);
    gemm_pipe<2><<<dim3(D / 128, NT / 128), 256, GEMM_SMEM>>>(
        ffh, w2t, b2, h, ctx, DFF, D, part);

    // LayerNorm 2 -> output (partials from FFN2 epilogue)
    ln_finalize<64><<<B, 256>>>(part, stats);
    ln_apply<<<dim3(1024, B), 256>>>(ctx, ln2g, ln2b, stats, out, nullptr);
}

// round 17
// speedup vs baseline: 3.1718x; 1.1341x over previous
#include <cuda_runtime.h>
#include <cuda_fp16.h>
#include <math.h>
#include <stdint.h>

// Problem constants
constexpr int B   = 8;
constexpr int S   = 1024;
constexpr int D   = 1024;
constexpr int H   = 16;
constexpr int DK  = 64;
constexpr int DFF = 4096;
constexpr int NT  = B * S;          // 8192 rows
constexpr float EPS = 1e-5f;

// ---------------------------------------------------------------------------
// Scratch (static __device__ arrays — no runtime allocation)
// ---------------------------------------------------------------------------
__device__ float g_ctx[NT * D];
__device__ float g_h  [NT * D];
__device__ float g_part[2 * B * 256];
__device__ float g_stats[2 * B];
// fp16 operands
__device__ __half g_qh [NT * D];
__device__ __half g_kh [NT * D];
__device__ __half g_vh [NT * D];
__device__ __half g_xh [NT * D];
__device__ __half g_hh [NT * D];
__device__ __half g_ffh[(size_t)NT * DFF];
__device__ __half g_wqt[D * D];            // Wt[n][k]
__device__ __half g_wkt[D * D];
__device__ __half g_wvt[D * D];
__device__ __half g_w1t[(size_t)DFF * D];
__device__ __half g_w2t[(size_t)D * DFF];

// ---------------------------------------------------------------------------
// helpers
// ---------------------------------------------------------------------------
__device__ __forceinline__ void mma_f16(float c[4], const uint32_t a[4], const uint32_t b[2]) {
    asm volatile(
        "mma.sync.aligned.m16n8k16.row.col.f32.f16.f16.f32 "
        "{%0,%1,%2,%3}, {%4,%5,%6,%7}, {%8,%9}, {%0,%1,%2,%3};\n"
        : "+f"(c[0]), "+f"(c[1]), "+f"(c[2]), "+f"(c[3])
        : "r"(a[0]), "r"(a[1]), "r"(a[2]), "r"(a[3]), "r"(b[0]), "r"(b[1]));
}
__device__ __forceinline__ void cp_async16(void* smem_ptr, const void* gptr) {
    uint32_t sa = (uint32_t)__cvta_generic_to_shared(smem_ptr);
    asm volatile("cp.async.cg.shared.global [%0], [%1], 16;\n" :: "r"(sa), "l"(gptr));
}
__device__ __forceinline__ void cp_commit() {
    asm volatile("cp.async.commit_group;\n");
}
__device__ __forceinline__ void ldsm_x4(uint32_t& r0, uint32_t& r1,
                                        uint32_t& r2, uint32_t& r3, uint32_t addr) {
    asm volatile("ldmatrix.sync.aligned.m8n8.x4.shared.b16 {%0,%1,%2,%3}, [%4];"
                 : "=r"(r0), "=r"(r1), "=r"(r2), "=r"(r3) : "r"(addr));
}
__device__ __forceinline__ void ldsm_x4_trans(uint32_t& r0, uint32_t& r1,
                                              uint32_t& r2, uint32_t& r3, uint32_t addr) {
    asm volatile("ldmatrix.sync.aligned.m8n8.x4.trans.shared.b16 {%0,%1,%2,%3}, [%4];"
                 : "=r"(r0), "=r"(r1), "=r"(r2), "=r"(r3) : "r"(addr));
}

// ---------------------------------------------------------------------------
// Prepass: x -> fp16 ; weights -> transposed fp16
// ---------------------------------------------------------------------------
__global__ void __launch_bounds__(256)
conv_x_f16(const float* __restrict__ in, __half* __restrict__ out, int n4)
{
    const int i = blockIdx.x * 256 + threadIdx.x;
    if (i < n4) {
        float4 v = ((const float4*)in)[i];
        __half2 h0 = __floats2half2_rn(v.x, v.y);
        __half2 h1 = __floats2half2_rn(v.z, v.w);
        uint2 o = make_uint2(*(uint32_t*)&h0, *(uint32_t*)&h1);
        ((uint2*)out)[i] = o;
    }
}

__global__ void __launch_bounds__(256)
transpose_f16(const float* __restrict__ in0, __half* __restrict__ out0,
              const float* __restrict__ in1, __half* __restrict__ out1,
              const float* __restrict__ in2, __half* __restrict__ out2,
              int R, int C)
{
    const float* in  = blockIdx.z == 0 ? in0  : (blockIdx.z == 1 ? in1  : in2);
    __half*      out = blockIdx.z == 0 ? out0 : (blockIdx.z == 1 ? out1 : out2);
    __shared__ float tile[32][33];
    const int c0 = blockIdx.x * 32, r0 = blockIdx.y * 32;
    const int tx = threadIdx.x, ty = threadIdx.y;
#pragma unroll
    for (int i = 0; i < 32; i += 8)
        tile[ty + i][tx] = in[(size_t)(r0 + ty + i) * C + c0 + tx];
    __syncthreads();
#pragma unroll
    for (int i = 0; i < 32; i += 8)
        out[(size_t)(c0 + ty + i) * R + r0 + tx] = __float2half_rn(tile[tx][ty + i]);
}

// ---------------------------------------------------------------------------
// FP16 tensor-core GEMM with ldmatrix fragment loads.
// 256 thr = 8 warps, warp tile 64x32 via m16n8k16, BK=32, 3-stage cp.async.
// Tiles [128][40] halfs (word stride 20; LDSM phases conflict-free).
// EPI: 1 = bias+GeLU -> half out, 2 = bias+residual -> float out (+LN partials),
//      3 = (bias+acc)*oscale -> HALF out (QKV)
// ---------------------------------------------------------------------------
constexpr int TSZH = 128 * 40;
constexpr int GEMM_SMEM = 3 * 2 * TSZH * 2;          // 61,440 B

template <int EPI>
__device__ __forceinline__ void gemm_body(
    const __half* __restrict__ A, const __half* __restrict__ Wt,
    const float* __restrict__ bias, const float* __restrict__ res,
    void* __restrict__ Cv, int K, int N, int bx, int by, __half* sm,
    float oscale, float* __restrict__ part2)
{
    __half* AsB = sm;
    __half* BsB = sm + 3 * TSZH;

    const int tid  = threadIdx.x;
    const int lane = tid & 31;
    const int warp = tid >> 5;
    const int g    = lane >> 2;
    const int t    = lane & 3;
    const int wm   = (warp & 1) * 64;
    const int wn   = (warp >> 1) * 32;

    // ldmatrix lane address components (halfs)
    const int arow = (lane & 7) + ((lane >> 3) & 1) * 8;
    const int akh  = (lane >> 4) * 8;
    const int brow = (lane & 7) + (lane >> 4) * 8;
    const int bkh  = ((lane >> 3) & 1) * 8;

    const __half* Ab = A  + (size_t)(by * 128) * K;
    const __half* Wb = Wt + (size_t)(bx * 128) * K;

    float acc[4][4][4];
#pragma unroll
    for (int mi = 0; mi < 4; mi++)
#pragma unroll
        for (int nj = 0; nj < 4; nj++)
#pragma unroll
            for (int c = 0; c < 4; c++) acc[mi][nj][c] = 0.f;

    __half* A0 = AsB; __half* A1 = AsB + TSZH; __half* A2 = AsB + 2 * TSZH;
    __half* B0 = BsB; __half* B1 = BsB + TSZH; __half* B2 = BsB + 2 * TSZH;

    auto stage_to = [&](__half* Ad, __half* Bd, int kk) {
#pragma unroll
        for (int u = 0; u < 2; u++) {
            const int i   = tid + u * 256;
            const int row = i >> 2;
            const int c8  = (i & 3) * 8;
            cp_async16(Ad + row * 40 + c8, Ab + (size_t)row * K + kk + c8);
        }
#pragma unroll
        for (int u = 0; u < 2; u++) {
            const int i   = tid + u * 256;
            const int row = i >> 2;
            const int c8  = (i & 3) * 8;
            cp_async16(Bd + row * 40 + c8, Wb + (size_t)row * K + kk + c8);
        }
        cp_commit();
    };

    const int nT = K >> 5;
    stage_to(A0, B0, 0);
    if (nT > 1) stage_to(A1, B1, 32);

    for (int tt = 0; tt < nT; tt++) {
        if (tt + 1 < nT) asm volatile("cp.async.wait_group 1;\n" ::: "memory");
        else             asm volatile("cp.async.wait_group 0;\n" ::: "memory");
        __syncthreads();
        if (tt + 2 < nT) stage_to(A2, B2, (tt + 2) * 32);

        const uint32_t Aaddr = (uint32_t)__cvta_generic_to_shared(A0)
                               + (uint32_t)(((wm + arow) * 40 + akh) * 2);
        const uint32_t Baddr = (uint32_t)__cvta_generic_to_shared(B0)
                               + (uint32_t)(((wn + brow) * 40 + bkh) * 2);
#pragma unroll
        for (int ks = 0; ks < 2; ks++) {
            const uint32_t kof = ks * 32;   // 16 halfs = 32 bytes
            uint32_t a[4][4], b[4][2];
#pragma unroll
            for (int mi = 0; mi < 4; mi++)
                ldsm_x4(a[mi][0], a[mi][1], a[mi][2], a[mi][3],
                        Aaddr + (uint32_t)(mi * 16 * 80) + kof);
#pragma unroll
            for (int nj2 = 0; nj2 < 2; nj2++) {
                uint32_t r0, r1, r2, r3;
                ldsm_x4(r0, r1, r2, r3, Baddr + (uint32_t)(nj2 * 16 * 80) + kof);
                b[nj2 * 2 + 0][0] = r0; b[nj2 * 2 + 0][1] = r1;
                b[nj2 * 2 + 1][0] = r2; b[nj2 * 2 + 1][1] = r3;
            }
#pragma unroll
            for (int mi = 0; mi < 4; mi++)
#pragma unroll
                for (int nj = 0; nj < 4; nj++)
                    mma_f16(acc[mi][nj], a[mi], b[nj]);
        }

        __half* ta = A0; A0 = A1; A1 = A2; A2 = ta;
        __half* tb = B0; B0 = B1; B1 = B2; B2 = tb;
    }

    float lsum = 0.f, lsq = 0.f;
#pragma unroll
    for (int mi = 0; mi < 4; mi++) {
#pragma unroll
        for (int nj = 0; nj < 4; nj++) {
            const int row = by * 128 + wm + mi * 16 + g;
            const int col = bx * 128 + wn + nj * 8 + t * 2;
#pragma unroll
            for (int half_i = 0; half_i < 2; half_i++) {
                const int r = row + half_i * 8;
                float v0 = acc[mi][nj][half_i * 2 + 0] + bias[col];
                float v1 = acc[mi][nj][half_i * 2 + 1] + bias[col + 1];
                if (EPI == 1) {
                    v0 = 0.5f * v0 * (1.0f + erff(v0 * 0.70710678118654752f));
                    v1 = 0.5f * v1 * (1.0f + erff(v1 * 0.70710678118654752f));
                    __half2 hv = __floats2half2_rn(v0, v1);
                    *(__half2*)((__half*)Cv + (size_t)r * N + col) = hv;
                } else if (EPI == 3) {
                    __half2 hv = __floats2half2_rn(v0 * oscale, v1 * oscale);
                    *(__half2*)((__half*)Cv + (size_t)r * N + col) = hv;
                } else {
                    v0 += res[(size_t)r * N + col];
                    v1 += res[(size_t)r * N + col + 1];
                    lsum += v0 + v1;
                    lsq  += v0 * v0 + v1 * v1;
                    *(float2*)((float*)Cv + (size_t)r * N + col) = make_float2(v0, v1);
                }
            }
        }
    }

    if (EPI == 2) {
        __syncthreads();
        float* r1 = (float*)sm;
        float* r2 = r1 + 256;
        r1[tid] = lsum; r2[tid] = lsq;
        __syncthreads();
        for (int st = 128; st > 0; st >>= 1) {
            if (tid < st) { r1[tid] += r1[tid + st]; r2[tid] += r2[tid + st]; }
            __syncthreads();
        }
        if (tid == 0) {
            const int b    = by >> 3;
            const int slot = (by & 7) * 8 + bx;
            part2[b * 64 + slot]          = r1[0];
            part2[B * 64 + b * 64 + slot] = r2[0];
        }
    }
}

__global__ void __launch_bounds__(256, 2)
gemm_qkv(const __half* __restrict__ x,
         const __half* __restrict__ wqt, const float* __restrict__ bq,
         const __half* __restrict__ wkt, const float* __restrict__ bk,
         const __half* __restrict__ wvt, const float* __restrict__ bv,
         __half* __restrict__ q, __half* __restrict__ k, __half* __restrict__ v)
{
    extern __shared__ __half smh[];
    const __half* W; const float* bias; __half* C; float osc;
    if (blockIdx.z == 0)      { W = wqt; bias = bq; C = q; osc = 0.125f; }
    else if (blockIdx.z == 1) { W = wkt; bias = bk; C = k; osc = 1.0f; }
    else                      { W = wvt; bias = bv; C = v; osc = 1.0f; }
    gemm_body<3>(x, W, bias, nullptr, C, D, D, blockIdx.x, blockIdx.y, smh, osc, nullptr);
}

template <int EPI>
__global__ void __launch_bounds__(256, 2)
gemm_pipe(const __half* __restrict__ A, const __half* __restrict__ Wt,
          const float* __restrict__ bias, const float* __restrict__ res,
          void* __restrict__ C, int K, int N, float* __restrict__ part2)
{
    extern __shared__ __half smh[];
    gemm_body<EPI>(A, Wt, bias, res, C, K, N, blockIdx.x, blockIdx.y, smh, 1.0f, part2);
}

// ---------------------------------------------------------------------------
// FP16 flash attention (round-16 verified, unchanged)
// ---------------------------------------------------------------------------
constexpr int FW = 36;   // words per row (72 halfs)
constexpr int ATTN_SMEM = (128 * FW + 2 * 64 * FW + 2 * 64 * FW) * 4;  // 55,296 B

__global__ void __launch_bounds__(256, 2)
flash_attn(const __half* __restrict__ Q, const __half* __restrict__ Kg,
           const __half* __restrict__ Vg, const float* __restrict__ X,
           float* __restrict__ hres, float* __restrict__ part)
{
    extern __shared__ __half smh[];
    __half* Ph = smh;
    __half* Kh = Ph + 128 * 72;
    __half* Vh = Kh + 2 * 64 * 72;
    uint32_t* Pw = (uint32_t*)Ph;

    const int tid  = threadIdx.x;
    const int lane = tid & 31;
    const int warp = tid >> 5;
    const int g    = lane >> 2;
    const int t    = lane & 3;
    const int m0   = warp * 16;
    const int lkey = ((lane >> 3) & 1) * 8 + (lane & 7);
    const int ldk  = (lane >> 4) * 8;

    const int q0 = blockIdx.x * 128;
    const int hh = blockIdx.y;
    const int b  = blockIdx.z;

    const __half* Qb  = Q  + (size_t)b * S * D + hh * DK;
    const __half* Kgb = Kg + (size_t)b * S * D + hh * DK;
    const __half* Vgb = Vg + (size_t)b * S * D + hh * DK;

#pragma unroll
    for (int u = 0; u < 4; u++) {
        const int idx = u * 256 + tid;
        const int row = idx >> 3;
        const int c8  = (idx & 7) * 8;
        cp_async16(Ph + row * 72 + c8, Qb + (size_t)(q0 + row) * D + c8);
    }
    cp_commit();

    auto stageKV = [&](int buf, int k0) {
        __half* Kd = Kh + buf * 64 * 72;
        __half* Vd = Vh + buf * 64 * 72;
#pragma unroll
        for (int u = 0; u < 2; u++) {
            const int idx = u * 256 + tid;
            const int row = idx >> 3;
            const int c8  = (idx & 7) * 8;
            cp_async16(Kd + row * 72 + c8, Kgb + (size_t)(k0 + row) * D + c8);
            cp_async16(Vd + row * 72 + c8, Vgb + (size_t)(k0 + row) * D + c8);
        }
        cp_commit();
    };

    stageKV(0, 0);

    asm volatile("cp.async.wait_group 1;\n" ::: "memory");
    __syncthreads();
    uint32_t qf[4][4];
#pragma unroll
    for (int kc = 0; kc < 4; kc++) {
        qf[kc][0] = Pw[(m0 + g)     * FW + kc * 8 + t];
        qf[kc][1] = Pw[(m0 + 8 + g) * FW + kc * 8 + t];
        qf[kc][2] = Pw[(m0 + g)     * FW + kc * 8 + 4 + t];
        qf[kc][3] = Pw[(m0 + 8 + g) * FW + kc * 8 + 4 + t];
    }

    float o[8][4];
#pragma unroll
    for (int j = 0; j < 8; j++)
#pragma unroll
        for (int c = 0; c < 4; c++) o[j][c] = 0.f;
    float mrun0 = -1e30f, mrun1 = -1e30f, lrun0 = 0.f, lrun1 = 0.f;

    constexpr int NIT = S / 64;
    for (int it = 0; it < NIT; it++) {
        const int buf = it & 1;
        __syncthreads();
        if (it + 1 < NIT) stageKV(buf ^ 1, (it + 1) * 64);
        if (it + 1 < NIT) asm volatile("cp.async.wait_group 1;\n" ::: "memory");
        else              asm volatile("cp.async.wait_group 0;\n" ::: "memory");
        __syncthreads();

        const uint32_t* Kw = (const uint32_t*)(Kh + buf * 64 * 72);
        const __half*   Vs = Vh + buf * 64 * 72;
        const uint32_t  vbase = (uint32_t)__cvta_generic_to_shared(Vs);

        float sc[8][4];
#pragma unroll
        for (int j = 0; j < 8; j++) {
            sc[j][0] = 0.f; sc[j][1] = 0.f; sc[j][2] = 0.f; sc[j][3] = 0.f;
            const int n0 = j * 8;
#pragma unroll
            for (int kc = 0; kc < 4; kc++) {
                uint32_t bf[2];
                bf[0] = Kw[(n0 + g) * FW + kc * 8 + t];
                bf[1] = Kw[(n0 + g) * FW + kc * 8 + 4 + t];
                mma_f16(sc[j], qf[kc], bf);
            }
        }

        float nm0 = -1e30f, nm1 = -1e30f;
#pragma unroll
        for (int j = 0; j < 8; j++) {
            nm0 = fmaxf(nm0, fmaxf(sc[j][0], sc[j][1]));
            nm1 = fmaxf(nm1, fmaxf(sc[j][2], sc[j][3]));
        }
        nm0 = fmaxf(nm0, __shfl_xor_sync(0xffffffffu, nm0, 1));
        nm0 = fmaxf(nm0, __shfl_xor_sync(0xffffffffu, nm0, 2));
        nm1 = fmaxf(nm1, __shfl_xor_sync(0xffffffffu, nm1, 1));
        nm1 = fmaxf(nm1, __shfl_xor_sync(0xffffffffu, nm1, 2));
        const float newm0 = fmaxf(mrun0, nm0);
        const float newm1 = fmaxf(mrun1, nm1);
        const float f0 = __expf(mrun0 - newm0);
        const float f1 = __expf(mrun1 - newm1);

        float s0 = 0.f, s1 = 0.f;
#pragma unroll
        for (int j = 0; j < 8; j++) {
            const float p00 = __expf(sc[j][0] - newm0);
            const float p01 = __expf(sc[j][1] - newm0);
            const float p10 = __expf(sc[j][2] - newm1);
            const float p11 = __expf(sc[j][3] - newm1);
            s0 += p00 + p01;
            s1 += p10 + p11;
            __half2 hp0 = __floats2half2_rn(p00, p01);
            __half2 hp1 = __floats2half2_rn(p10, p11);
            Pw[(m0 + g)     * FW + j * 4 + t] = *(uint32_t*)&hp0;
            Pw[(m0 + 8 + g) * FW + j * 4 + t] = *(uint32_t*)&hp1;
        }
        s0 += __shfl_xor_sync(0xffffffffu, s0, 1);
        s0 += __shfl_xor_sync(0xffffffffu, s0, 2);
        s1 += __shfl_xor_sync(0xffffffffu, s1, 1);
        s1 += __shfl_xor_sync(0xffffffffu, s1, 2);
        lrun0 = lrun0 * f0 + s0;
        lrun1 = lrun1 * f1 + s1;
        mrun0 = newm0;
        mrun1 = newm1;
#pragma unroll
        for (int j = 0; j < 8; j++) {
            o[j][0] *= f0; o[j][1] *= f0;
            o[j][2] *= f1; o[j][3] *= f1;
        }
        __syncwarp();

#pragma unroll
        for (int kc = 0; kc < 4; kc++) {
            uint32_t a[4];
            a[0] = Pw[(m0 + g)     * FW + kc * 8 + t];
            a[1] = Pw[(m0 + 8 + g) * FW + kc * 8 + t];
            a[2] = Pw[(m0 + g)     * FW + kc * 8 + 4 + t];
            a[3] = Pw[(m0 + 8 + g) * FW + kc * 8 + 4 + t];
#pragma unroll
            for (int nd = 0; nd < 4; nd++) {
                uint32_t r0, r1, r2, r3;
                const uint32_t addr = vbase +
                    (uint32_t)(((kc * 16 + lkey) * 72 + nd * 16 + ldk) * 2);
                ldsm_x4_trans(r0, r1, r2, r3, addr);
                uint32_t bA[2] = {r0, r1};
                uint32_t bB[2] = {r2, r3};
                mma_f16(o[nd * 2 + 0], a, bA);
                mma_f16(o[nd * 2 + 1], a, bB);
            }
        }
    }

    const float inv0 = 1.0f / lrun0;
    const float inv1 = 1.0f / lrun1;
    const int row0 = q0 + m0 + g;
    const int row1 = row0 + 8;
    float lsum = 0.f, lsq = 0.f;
#pragma unroll
    for (int j = 0; j < 8; j++) {
        const int col = hh * DK + j * 8 + 2 * t;
        float2 xv0 = *(const float2*)(X + (size_t)(b * S + row0) * D + col);
        float2 xv1 = *(const float2*)(X + (size_t)(b * S + row1) * D + col);
        float h00 = xv0.x + o[j][0] * inv0;
        float h01 = xv0.y + o[j][1] * inv0;
        float h10 = xv1.x + o[j][2] * inv1;
        float h11 = xv1.y + o[j][3] * inv1;
        lsum += h00 + h01 + h10 + h11;
        lsq  += h00 * h00 + h01 * h01 + h10 * h10 + h11 * h11;
        *(float2*)(hres + (size_t)(b * S + row0) * D + col) = make_float2(h00, h01);
        *(float2*)(hres + (size_t)(b * S + row1) * D + col) = make_float2(h10, h11);
    }

    __syncthreads();
    float* r1 = (float*)Ph;
    float* r2 = r1 + 256;
    r1[tid] = lsum; r2[tid] = lsq;
    __syncthreads();
    for (int st = 128; st > 0; st >>= 1) {
        if (tid < st) { r1[tid] += r1[tid + st]; r2[tid] += r2[tid + st]; }
        __syncthreads();
    }
    if (tid == 0) {
        const int slot = blockIdx.x * 16 + hh;
        part[b * 128 + slot]           = r1[0];
        part[B * 128 + b * 128 + slot] = r2[0];
    }
}

// ---------------------------------------------------------------------------
// LayerNorm finalize/apply
// ---------------------------------------------------------------------------
template <int NCHUNK>
__global__ void __launch_bounds__(256)
ln_finalize(const float* __restrict__ part, float* __restrict__ stats)
{
    const int b = blockIdx.x, tid = threadIdx.x;
    __shared__ float r1[256], r2[256];
    r1[tid] = tid < NCHUNK ? part[b * NCHUNK + tid] : 0.f;
    r2[tid] = tid < NCHUNK ? part[B * NCHUNK + b * NCHUNK + tid] : 0.f;
    __syncthreads();
    for (int st = 128; st > 0; st >>= 1) {
        if (tid < st) { r1[tid] += r1[tid + st]; r2[tid] += r2[tid + st]; }
        __syncthreads();
    }
    if (tid == 0) {
        const float n = (float)S * (float)D;
        float mean = r1[0] / n;
        float var  = r2[0] / n - mean * mean;
        stats[2 * b]     = mean;
        stats[2 * b + 1] = rsqrtf(var + EPS);
    }
}

__global__ void __launch_bounds__(256)
ln_apply(const float* __restrict__ y, const float* __restrict__ g,
         const float* __restrict__ beta, const float* __restrict__ stats,
         float* __restrict__ out, __half* __restrict__ out_h)
{
    const int b = blockIdx.y;
    const int idx = (blockIdx.x * 256 + threadIdx.x) * 4;
    const float mean = stats[2 * b];
    const float rstd = stats[2 * b + 1];
    const size_t off = (size_t)b * S * D + idx;
    float4 v  = *(const float4*)(y + off);
    float4 gg = *(const float4*)(g + idx);
    float4 bb = *(const float4*)(beta + idx);
    v.x = (v.x - mean) * rstd * gg.x + bb.x;
    v.y = (v.y - mean) * rstd * gg.y + bb.y;
    v.z = (v.z - mean) * rstd * gg.z + bb.z;
    v.w = (v.w - mean) * rstd * gg.w + bb.w;
    *(float4*)(out + off) = v;
    if (out_h) {
        __half2 h0 = __floats2half2_rn(v.x, v.y);
        __half2 h1 = __floats2half2_rn(v.z, v.w);
        uint2 o = make_uint2(*(uint32_t*)&h0, *(uint32_t*)&h1);
        *(uint2*)(out_h + off) = o;
    }
}

// ---------------------------------------------------------------------------
// kernel_launch
// ---------------------------------------------------------------------------
extern "C" void kernel_launch(void* const* d_in, const int* in_sizes, int n_in,
                              void* d_out, int out_size)
{
    const float* x    = (const float*)d_in[0];
    const float* wq   = (const float*)d_in[1];
    const float* bq   = (const float*)d_in[2];
    const float* wk   = (const float*)d_in[3];
    const float* bk   = (const float*)d_in[4];
    const float* wv   = (const float*)d_in[5];
    const float* bv   = (const float*)d_in[6];
    const float* ln1g = (const float*)d_in[7];
    const float* ln1b = (const float*)d_in[8];
    const float* w1   = (const float*)d_in[9];
    const float* b1   = (const float*)d_in[10];
    const float* w2   = (const float*)d_in[11];
    const float* b2   = (const float*)d_in[12];
    const float* ln2g = (const float*)d_in[13];
    const float* ln2b = (const float*)d_in[14];
    float* out = (float*)d_out;

    float *ctx, *h, *part, *stats;
    __half *qh, *kh, *vh, *xh, *hh, *ffh, *wqt, *wkt, *wvt, *w1t, *w2t;
    cudaGetSymbolAddress((void**)&ctx,   g_ctx);
    cudaGetSymbolAddress((void**)&h,     g_h);
    cudaGetSymbolAddress((void**)&part,  g_part);
    cudaGetSymbolAddress((void**)&stats, g_stats);
    cudaGetSymbolAddress((void**)&qh,    g_qh);
    cudaGetSymbolAddress((void**)&kh,    g_kh);
    cudaGetSymbolAddress((void**)&vh,    g_vh);
    cudaGetSymbolAddress((void**)&xh,    g_xh);
    cudaGetSymbolAddress((void**)&hh,    g_hh);
    cudaGetSymbolAddress((void**)&ffh,   g_ffh);
    cudaGetSymbolAddress((void**)&wqt,   g_wqt);
    cudaGetSymbolAddress((void**)&wkt,   g_wkt);
    cudaGetSymbolAddress((void**)&wvt,   g_wvt);
    cudaGetSymbolAddress((void**)&w1t,   g_w1t);
    cudaGetSymbolAddress((void**)&w2t,   g_w2t);

    static bool attr_done = false;
    if (!attr_done) {
        cudaFuncSetAttribute(flash_attn,
                             cudaFuncAttributeMaxDynamicSharedMemorySize, ATTN_SMEM);
        cudaFuncSetAttribute(gemm_qkv,
                             cudaFuncAttributeMaxDynamicSharedMemorySize, GEMM_SMEM);
        cudaFuncSetAttribute(gemm_pipe<1>,
                             cudaFuncAttributeMaxDynamicSharedMemorySize, GEMM_SMEM);
        cudaFuncSetAttribute(gemm_pipe<2>,
                             cudaFuncAttributeMaxDynamicSharedMemorySize, GEMM_SMEM);
        attr_done = true;
    }

    // Prepass: x -> fp16; weights -> transposed fp16
    conv_x_f16<<<(NT * D / 4 + 255) / 256, 256>>>(x, xh, NT * D / 4);
    transpose_f16<<<dim3(D / 32, D / 32, 3), dim3(32, 8)>>>(
        wq, wqt, wk, wkt, wv, wvt, D, D);
    transpose_f16<<<dim3(DFF / 32, D / 32, 1), dim3(32, 8)>>>(
        w1, w1t, nullptr, nullptr, nullptr, nullptr, D, DFF);
    transpose_f16<<<dim3(D / 32, DFF / 32, 1), dim3(32, 8)>>>(
        w2, w2t, nullptr, nullptr, nullptr, nullptr, DFF, D);

    // QKV projections (fp16 MMA, fp16 outputs; q pre-scaled 1/8)
    gemm_qkv<<<dim3(D / 128, NT / 128, 3), 256, GEMM_SMEM>>>(
        xh, wqt, bq, wkt, bk, wvt, bv, qh, kh, vh);

    // FP16 flash attention (+fused h = x + ctx and LN1 partial sums)
    flash_attn<<<dim3(S / 128, H, B), 256, ATTN_SMEM>>>(qh, kh, vh, x, h, part);

    // LayerNorm 1 finalize + apply (h float in-place, + fp16 copy hh)
    ln_finalize<128><<<B, 256>>>(part, stats);
    ln_apply<<<dim3(1024, B), 256>>>(h, ln1g, ln1b, stats, h, hh);

    // FFN: ffh = half(gelu(hh @ w1 + b1)); ctx = ffh @ w2 + b2 + h (+LN2 partials)
    gemm_pipe<1><<<dim3(DFF / 128, NT / 128), 256, GEMM_SMEM>>>(
        hh, w1t, b1, nullptr, ffh, D, DFF, nullptr);
    gemm_pipe<2><<<dim3(D / 128, NT / 128), 256, GEMM_SMEM>>>(
        ffh, w2t, b2, h, ctx, DFF, D, part);

    // LayerNorm 2 -> output (partials from FFN2 epilogue)
    ln_finalize<64><<<B, 256>>>(part, stats);
    ln_apply<<<dim3(1024, B), 256>>>(ctx, ln2g, ln2b, stats, out, nullptr);
}